// round 1
// baseline (speedup 1.0000x reference)
#include <cuda_runtime.h>
#include <math.h>

#define BB 4
#define TT 8192
#define DD 1024
#define HH 8
#define DKV 128
#define II 2816
#define CHUNK 64
#define NC (TT/CHUNK)
#define BT (BB*TT)

#define RMS_EPS 1e-6f
#define GATE_EPS 1e-5f

// ---------------- scratch (device globals; no runtime allocation) ----------------
__device__ float g_xn[(size_t)BT*DD];
__device__ float g_t0[(size_t)BT*DD];
__device__ float g_t1[(size_t)BT*DD];
__device__ float g_t2[(size_t)BT*DD];
__device__ float g_q [(size_t)BT*DD];
__device__ float g_k [(size_t)BT*DD];
__device__ float g_v [(size_t)BT*DD];
__device__ float g_o [(size_t)BT*DD];
__device__ float g_h [(size_t)BT*DD];
__device__ float g_S [(size_t)BB*HH*NC*DKV*DKV];
__device__ float g_m1[(size_t)BT*II];
__device__ float g_m2[(size_t)BT*II];
__device__ float g_cos[TT*64];
__device__ float g_sin[TT*64];

// ---------------- rmsnorm over D=1024, one block per row ----------------
__global__ void rmsnorm_kernel(const float* __restrict__ x, const float* __restrict__ w,
                               float* __restrict__ out, float eps) {
    int row = blockIdx.x;
    const float* xr = x + (size_t)row * DD;
    float s = 0.f;
    for (int i = threadIdx.x; i < DD; i += 256) { float v = xr[i]; s += v * v; }
    __shared__ float red[8];
    #pragma unroll
    for (int o = 16; o > 0; o >>= 1) s += __shfl_down_sync(0xffffffffu, s, o);
    if ((threadIdx.x & 31) == 0) red[threadIdx.x >> 5] = s;
    __syncthreads();
    if (threadIdx.x < 8) {
        s = red[threadIdx.x];
        #pragma unroll
        for (int o = 4; o > 0; o >>= 1) s += __shfl_down_sync(0xffu, s, o);
        if (threadIdx.x == 0) red[0] = s;
    }
    __syncthreads();
    float inv = rsqrtf(red[0] / (float)DD + eps);
    float* orow = out + (size_t)row * DD;
    for (int i = threadIdx.x; i < DD; i += 256) orow[i] = xr[i] * inv * w[i];
}

// ---------------- classic 128x128x8 fp32 SGEMM, optional residual add ----------------
// A: MxK row-major, Bm: KxN row-major, C = A@Bm (+R). M%128==0, N%128==0, K%8==0.
__global__ __launch_bounds__(256, 2)
void sgemm_kernel(const float* __restrict__ A, const float* __restrict__ Bm,
                  const float* __restrict__ R, float* __restrict__ C,
                  int M, int N, int K) {
    __shared__ float As[8][128];
    __shared__ float Bs[8][128];
    const int tid = threadIdx.x;
    const int tx = tid & 15, ty = tid >> 4;
    const int bm = blockIdx.y * 128, bn = blockIdx.x * 128;
    const int arow = tid >> 1, acol = (tid & 1) << 2;
    const int brow = tid >> 5, bcol = (tid & 31) << 2;
    const float* Aptr = A + (size_t)(bm + arow) * K + acol;
    const float* Bptr = Bm + (size_t)brow * N + bn + bcol;

    float acc[8][8];
    #pragma unroll
    for (int i = 0; i < 8; ++i)
        #pragma unroll
        for (int j = 0; j < 8; ++j) acc[i][j] = 0.f;

    for (int k0 = 0; k0 < K; k0 += 8) {
        float4 a = *(const float4*)(Aptr + k0);
        As[acol + 0][arow] = a.x; As[acol + 1][arow] = a.y;
        As[acol + 2][arow] = a.z; As[acol + 3][arow] = a.w;
        float4 b = *(const float4*)(Bptr + (size_t)k0 * N);
        *(float4*)&Bs[brow][bcol] = b;
        __syncthreads();
        #pragma unroll
        for (int k = 0; k < 8; ++k) {
            float4 a0 = *(const float4*)&As[k][ty * 8];
            float4 a1 = *(const float4*)&As[k][ty * 8 + 4];
            float4 b0 = *(const float4*)&Bs[k][tx * 8];
            float4 b1 = *(const float4*)&Bs[k][tx * 8 + 4];
            float ar[8] = {a0.x, a0.y, a0.z, a0.w, a1.x, a1.y, a1.z, a1.w};
            float br[8] = {b0.x, b0.y, b0.z, b0.w, b1.x, b1.y, b1.z, b1.w};
            #pragma unroll
            for (int i = 0; i < 8; ++i)
                #pragma unroll
                for (int j = 0; j < 8; ++j) acc[i][j] += ar[i] * br[j];
        }
        __syncthreads();
    }
    #pragma unroll
    for (int i = 0; i < 8; ++i) {
        size_t roff = (size_t)(bm + ty * 8 + i) * N + bn + tx * 8;
        #pragma unroll
        for (int j = 0; j < 8; ++j) {
            float vv = acc[i][j];
            if (R) vv += R[roff + j];
            C[roff + j] = vv;
        }
    }
}

// ---------------- causal short conv (K=4) + silu ----------------
__global__ void conv_silu_kernel(const float* __restrict__ x, const float* __restrict__ w,
                                 float* __restrict__ y) {
    size_t idx = (size_t)blockIdx.x * 256 + threadIdx.x;
    if (idx >= (size_t)BT * DD) return;
    int d = (int)(idx % DD);
    int t = (int)((idx / DD) % TT);
    size_t bbase = idx - (size_t)t * DD - d;
    float acc = 0.f;
    #pragma unroll
    for (int k = 0; k < 4; ++k) {
        int tt = t - 3 + k;
        if (tt >= 0) acc += x[bbase + (size_t)tt * DD + d] * w[d * 4 + k];
    }
    y[idx] = acc / (1.f + expf(-acc));
}

// ---------------- RoPE table (double-precision sin/cos of the fp32 phase) ----------------
__global__ void rope_table_kernel() {
    int idx = blockIdx.x * 256 + threadIdx.x;
    if (idx >= TT * 64) return;
    int t = idx >> 6, j = idx & 63;
    float invf = (float)(1.0 / pow(10000.0, (double)j / 64.0));
    float f = (float)t * invf;
    g_cos[idx] = (float)cos((double)f);
    g_sin[idx] = (float)sin((double)f);
}

// ---------------- RoPE apply, in place on [B,T,H,128] ----------------
__global__ void rope_kernel(float* __restrict__ x) {
    size_t idx = (size_t)blockIdx.x * 256 + threadIdx.x;
    if (idx >= (size_t)BB * TT * HH * 64) return;
    int j = (int)(idx & 63);
    int h = (int)((idx >> 6) & 7);
    size_t bt = idx >> 9;
    int t = (int)(bt % TT);
    float c = g_cos[t * 64 + j], s = g_sin[t * 64 + j];
    size_t base = bt * DD + h * 128;
    float x1 = x[base + j], x2 = x[base + 64 + j];
    x[base + j]      = x1 * c - x2 * s;
    x[base + 64 + j] = x1 * s + x2 * c;
}

// ---------------- retention phase 1: per-chunk local state S_loc = sum_i kdec[i] k_i (x) v_i ----------------
__global__ void ret_phase1(const float* __restrict__ k, const float* __restrict__ v,
                           float* __restrict__ S) {
    extern __shared__ float sm[];
    float* ks = sm;               // 64 x 129 (padded)
    float* vs = sm + 64 * 129;
    int c = blockIdx.x, h = blockIdx.y, b = blockIdx.z;
    float gamma = 1.f - exp2f(-5.f - (float)h);
    float lg = logf(gamma);
    int tid = threadIdx.x;
    for (int x = tid; x < 8192; x += 256) {
        int i = x >> 7, d = x & 127;
        size_t g = ((size_t)b * TT + c * 64 + i) * DD + h * 128 + d;
        ks[i * 129 + d] = k[g] * expf(lg * (float)(63 - i));
        vs[i * 129 + d] = v[g];
    }
    __syncthreads();
    size_t sb = (((size_t)(b * HH + h)) * NC + c) * 16384;
    for (int x = tid; x < 16384; x += 256) {
        int d = x >> 7, e = x & 127;
        float a = 0.f;
        #pragma unroll
        for (int j = 0; j < 64; ++j) a += ks[j * 129 + d] * vs[j * 129 + e];
        S[sb + x] = a;
    }
}

// ---------------- retention phase 2: exclusive prefix scan of states over chunks ----------------
__global__ void ret_scan(float* __restrict__ S) {
    int bh = blockIdx.x;
    int h = bh & 7;
    float gamma = 1.f - exp2f(-5.f - (float)h);
    float cdec = expf(logf(gamma) * 64.f);
    float carry[64];
    #pragma unroll
    for (int r = 0; r < 64; ++r) carry[r] = 0.f;
    size_t base = (size_t)bh * NC * 16384;
    for (int c = 0; c < NC; ++c) {
        size_t cb = base + (size_t)c * 16384;
        #pragma unroll
        for (int r = 0; r < 64; ++r) {
            size_t idx = cb + threadIdx.x + (r << 8);
            float loc = S[idx];
            S[idx] = carry[r];
            carry[r] = carry[r] * cdec + loc;
        }
    }
}

// ---------------- retention phase 3: o = (mask * qk^T) v + cross * q @ S_prefix ----------------
__global__ void ret_phase3(const float* __restrict__ q, const float* __restrict__ k,
                           const float* __restrict__ v, const float* __restrict__ S,
                           float* __restrict__ o) {
    extern __shared__ float sm[];
    float* qs  = sm;                  // 64 x 129
    float* ks  = qs + 64 * 129;       // 64 x 129
    float* vs  = ks + 64 * 129;       // 64 x 129
    float* Ps  = vs + 64 * 129;       // 128 x 129
    float* att = Ps + 128 * 129;      // 64 x 65
    int c = blockIdx.x, h = blockIdx.y, b = blockIdx.z;
    float gamma = 1.f - exp2f(-5.f - (float)h);
    float lg = logf(gamma);
    const float scale = 0.08838834764831845f;  // 128^-0.5
    int tid = threadIdx.x;
    for (int x = tid; x < 8192; x += 256) {
        int i = x >> 7, d = x & 127;
        size_t g = ((size_t)b * TT + c * 64 + i) * DD + h * 128 + d;
        qs[i * 129 + d] = q[g] * scale;
        ks[i * 129 + d] = k[g];
        vs[i * 129 + d] = v[g];
    }
    size_t sb = (((size_t)(b * HH + h)) * NC + c) * 16384;
    for (int x = tid; x < 16384; x += 256) {
        int d = x >> 7, e = x & 127;
        Ps[d * 129 + e] = S[sb + x];
    }
    __syncthreads();
    for (int x = tid; x < 4096; x += 256) {
        int i = x >> 6, j = x & 63;
        float a = 0.f;
        if (i >= j) {
            #pragma unroll
            for (int d = 0; d < 128; ++d) a += qs[i * 129 + d] * ks[j * 129 + d];
            a *= expf(lg * (float)(i - j));
        }
        att[i * 65 + j] = a;
    }
    __syncthreads();
    for (int x = tid; x < 8192; x += 256) {
        int i = x >> 7, e = x & 127;
        float acc = 0.f;
        #pragma unroll
        for (int j = 0; j < 64; ++j) acc += att[i * 65 + j] * vs[j * 129 + e];
        float acc2 = 0.f;
        #pragma unroll
        for (int d = 0; d < 128; ++d) acc2 += qs[i * 129 + d] * Ps[d * 129 + e];
        acc += expf(lg * (float)(i + 1)) * acc2;
        o[((size_t)b * TT + c * 64 + i) * DD + h * 128 + e] = acc;
    }
}

// ---------------- gating: o = rmsnorm_128(o) * gnorm_w * silu(g), one warp per (b,t,h) row ----------------
__global__ void gate_kernel(float* __restrict__ o, const float* __restrict__ g,
                            const float* __restrict__ w) {
    int row = blockIdx.x * 8 + (threadIdx.x >> 5);
    int lane = threadIdx.x & 31;
    float* orow = o + (size_t)row * 128;
    const float* grow = g + (size_t)row * 128;
    float v[4]; float s = 0.f;
    #pragma unroll
    for (int r = 0; r < 4; ++r) { v[r] = orow[lane + 32 * r]; s += v[r] * v[r]; }
    #pragma unroll
    for (int off = 16; off > 0; off >>= 1) s += __shfl_xor_sync(0xffffffffu, s, off);
    float inv = rsqrtf(s / 128.f + GATE_EPS);
    #pragma unroll
    for (int r = 0; r < 4; ++r) {
        int i = lane + 32 * r;
        float gg = grow[i];
        orow[i] = v[r] * inv * w[i] * (gg / (1.f + expf(-gg)));
    }
}

// ---------------- swiglu combine: m1 = silu(m1) * m2 ----------------
__global__ void swiglu_kernel(float* __restrict__ a, const float* __restrict__ b2, size_t n) {
    size_t idx = (size_t)blockIdx.x * 256 + threadIdx.x;
    if (idx < n) { float x = a[idx]; a[idx] = (x / (1.f + expf(-x))) * b2[idx]; }
}

// ---------------- launch ----------------
extern "C" void kernel_launch(void* const* d_in, const int* in_sizes, int n_in,
                              void* d_out, int out_size) {
    const float* hs    = (const float*)d_in[0];
    const float* ln1   = (const float*)d_in[1];
    const float* ln2   = (const float*)d_in[2];
    const float* wq    = (const float*)d_in[3];
    const float* wk    = (const float*)d_in[4];
    const float* wv    = (const float*)d_in[5];
    const float* wg    = (const float*)d_in[6];
    const float* wo    = (const float*)d_in[7];
    const float* cq    = (const float*)d_in[8];
    const float* ck    = (const float*)d_in[9];
    const float* cv    = (const float*)d_in[10];
    const float* gn    = (const float*)d_in[11];
    const float* wgate = (const float*)d_in[12];
    const float* wup   = (const float*)d_in[13];
    const float* wdown = (const float*)d_in[14];
    float* out = (float*)d_out;

    cudaFuncSetAttribute(ret_phase1, cudaFuncAttributeMaxDynamicSharedMemorySize, 2 * 64 * 129 * 4);
    cudaFuncSetAttribute(ret_phase3, cudaFuncAttributeMaxDynamicSharedMemorySize,
                         (3 * 64 * 129 + 128 * 129 + 64 * 65) * 4);

    float *xn, *t0, *t1, *t2, *q, *k, *v, *o, *hbuf, *S, *m1, *m2;
    cudaGetSymbolAddress((void**)&xn, g_xn);
    cudaGetSymbolAddress((void**)&t0, g_t0);
    cudaGetSymbolAddress((void**)&t1, g_t1);
    cudaGetSymbolAddress((void**)&t2, g_t2);
    cudaGetSymbolAddress((void**)&q,  g_q);
    cudaGetSymbolAddress((void**)&k,  g_k);
    cudaGetSymbolAddress((void**)&v,  g_v);
    cudaGetSymbolAddress((void**)&o,  g_o);
    cudaGetSymbolAddress((void**)&hbuf, g_h);
    cudaGetSymbolAddress((void**)&S,  g_S);
    cudaGetSymbolAddress((void**)&m1, g_m1);
    cudaGetSymbolAddress((void**)&m2, g_m2);

    const int ew = (int)(((size_t)BT * DD + 255) / 256);
    rope_table_kernel<<<(TT * 64 + 255) / 256, 256>>>();
    rmsnorm_kernel<<<BT, 256>>>(hs, ln1, xn, RMS_EPS);

    dim3 g8(DD / 128, BT / 128);
    sgemm_kernel<<<g8, 256>>>(xn, wq, nullptr, t0, BT, DD, DD);
    conv_silu_kernel<<<ew, 256>>>(t0, cq, q);
    sgemm_kernel<<<g8, 256>>>(xn, wk, nullptr, t1, BT, DD, DD);
    conv_silu_kernel<<<ew, 256>>>(t1, ck, k);
    sgemm_kernel<<<g8, 256>>>(xn, wv, nullptr, t2, BT, DD, DD);
    conv_silu_kernel<<<ew, 256>>>(t2, cv, v);

    const int rw = (int)(((size_t)BB * TT * HH * 64 + 255) / 256);
    rope_kernel<<<rw, 256>>>(q);
    rope_kernel<<<rw, 256>>>(k);

    dim3 gc(NC, HH, BB);
    ret_phase1<<<gc, 256, 2 * 64 * 129 * 4>>>(k, v, S);
    ret_scan<<<BB * HH, 256>>>(S);
    ret_phase3<<<gc, 256, (3 * 64 * 129 + 128 * 129 + 64 * 65) * 4>>>(q, k, v, S, o);

    sgemm_kernel<<<g8, 256>>>(xn, wg, nullptr, t0, BT, DD, DD);
    gate_kernel<<<(BT * HH) / 8, 256>>>(o, t0, gn);
    sgemm_kernel<<<g8, 256>>>(o, wo, hs, hbuf, BT, DD, DD);

    rmsnorm_kernel<<<BT, 256>>>(hbuf, ln2, xn, RMS_EPS);
    dim3 gi(II / 128, BT / 128);
    sgemm_kernel<<<gi, 256>>>(xn, wgate, nullptr, m1, BT, II, DD);
    sgemm_kernel<<<gi, 256>>>(xn, wup,   nullptr, m2, BT, II, DD);
    size_t nmid = (size_t)BT * II;
    swiglu_kernel<<<(int)((nmid + 255) / 256), 256>>>(m1, m2, nmid);
    sgemm_kernel<<<g8, 256>>>(m1, wdown, hbuf, out, BT, DD, II);
}

// round 2
// speedup vs baseline: 2.0468x; 2.0468x over previous
#include <cuda_runtime.h>
#include <math.h>
#include <stdint.h>

#define BB 4
#define TT 8192
#define DD 1024
#define HH 8
#define DKV 128
#define II 2816
#define CHUNK 64
#define NC (TT/CHUNK)
#define BT (BB*TT)

#define RMS_EPS 1e-6f
#define GATE_EPS 1e-5f

// ---------------- scratch (device globals; no runtime allocation) ----------------
__device__ float g_xn[(size_t)BT*DD];
__device__ float g_t0[(size_t)BT*DD];
__device__ float g_t1[(size_t)BT*DD];
__device__ float g_t2[(size_t)BT*DD];
__device__ float g_q [(size_t)BT*DD];
__device__ float g_k [(size_t)BT*DD];
__device__ float g_v [(size_t)BT*DD];
__device__ float g_o [(size_t)BT*DD];
__device__ float g_h [(size_t)BT*DD];
__device__ float g_S [(size_t)BB*HH*NC*DKV*DKV];
__device__ float g_m1[(size_t)BT*II];
__device__ float g_m2[(size_t)BT*II];
__device__ float g_cos[TT*64];
__device__ float g_sin[TT*64];

// ---------------- rmsnorm over D=1024, one block per row ----------------
__global__ void rmsnorm_kernel(const float* __restrict__ x, const float* __restrict__ w,
                               float* __restrict__ out, float eps) {
    int row = blockIdx.x;
    const float* xr = x + (size_t)row * DD;
    float s = 0.f;
    for (int i = threadIdx.x; i < DD; i += 256) { float v = xr[i]; s += v * v; }
    __shared__ float red[8];
    #pragma unroll
    for (int o = 16; o > 0; o >>= 1) s += __shfl_down_sync(0xffffffffu, s, o);
    if ((threadIdx.x & 31) == 0) red[threadIdx.x >> 5] = s;
    __syncthreads();
    if (threadIdx.x < 8) {
        s = red[threadIdx.x];
        #pragma unroll
        for (int o = 4; o > 0; o >>= 1) s += __shfl_down_sync(0xffu, s, o);
        if (threadIdx.x == 0) red[0] = s;
    }
    __syncthreads();
    float inv = rsqrtf(red[0] / (float)DD + eps);
    float* orow = out + (size_t)row * DD;
    for (int i = threadIdx.x; i < DD; i += 256) orow[i] = xr[i] * inv * w[i];
}

// ================= tf32 tensor-core GEMM =================
// C = A @ B (+R). A: MxK row-major, B: KxN row-major. M%128==0, N%128==0, K%16==0.
// 128x128 CTA tile, BK=16, cp.async double-buffered, 8 warps (2 M x 4 N),
// each warp 64x32 via mma.sync.m16n8k8.tf32.

#define BKT 16
#define ASTR (BKT + 4)     // 20 floats  -> conflict-free A frag loads
#define BSTR (128 + 8)     // 136 floats -> conflict-free B frag loads

__device__ __forceinline__ uint32_t f2tf(float x) {
    uint32_t r;
    asm("cvt.rna.tf32.f32 %0, %1;" : "=r"(r) : "f"(x));
    return r;
}
__device__ __forceinline__ void mma_tf32(float* c, const uint32_t* a, const uint32_t* b) {
    asm volatile("mma.sync.aligned.m16n8k8.row.col.f32.tf32.tf32.f32 "
        "{%0,%1,%2,%3}, {%4,%5,%6,%7}, {%8,%9}, {%0,%1,%2,%3};"
        : "+f"(c[0]), "+f"(c[1]), "+f"(c[2]), "+f"(c[3])
        : "r"(a[0]), "r"(a[1]), "r"(a[2]), "r"(a[3]), "r"(b[0]), "r"(b[1]));
}
__device__ __forceinline__ void cpasync16(uint32_t s, const void* g) {
    asm volatile("cp.async.cg.shared.global [%0], [%1], 16;" :: "r"(s), "l"(g));
}

__global__ __launch_bounds__(256, 2)
void tgemm_kernel(const float* __restrict__ A, const float* __restrict__ B,
                  const float* __restrict__ R, float* __restrict__ C,
                  int M, int N, int K) {
    __shared__ float As[2][128][ASTR];
    __shared__ float Bs[2][BKT][BSTR];

    const int tid = threadIdx.x;
    const int lane = tid & 31;
    const int warpId = tid >> 5;
    const int g = lane >> 2, q = lane & 3;
    const int wm = (warpId & 1) * 64;
    const int wn = (warpId >> 1) * 32;
    const int bm = blockIdx.y * 128, bn = blockIdx.x * 128;

    uint32_t sA = (uint32_t)__cvta_generic_to_shared(&As[0][0][0]);
    uint32_t sB = (uint32_t)__cvta_generic_to_shared(&Bs[0][0][0]);
    const uint32_t sAsz = 128 * ASTR * 4;
    const uint32_t sBsz = BKT * BSTR * 4;

    float acc[4][4][4];
    #pragma unroll
    for (int i = 0; i < 4; ++i)
        #pragma unroll
        for (int j = 0; j < 4; ++j)
            #pragma unroll
            for (int r = 0; r < 4; ++r) acc[i][j][r] = 0.f;

    const int ar0 = tid >> 1, ac0 = (tid & 1) * 8;          // A: 2 chunks of 4, same row
    const int br0 = tid >> 5, bc0 = (tid & 31) * 4;         // B: rows 0-7 / 8-15

    const int ntile = K / BKT;

    // prologue: tile 0 -> buf 0
    {
        const float* Ab = A + (size_t)(bm + ar0) * K + ac0;
        cpasync16(sA + (ar0 * ASTR + ac0) * 4, Ab);
        cpasync16(sA + (ar0 * ASTR + ac0 + 4) * 4, Ab + 4);
        const float* Bb = B + (size_t)br0 * N + bn + bc0;
        cpasync16(sB + (br0 * BSTR + bc0) * 4, Bb);
        cpasync16(sB + ((br0 + 8) * BSTR + bc0) * 4, Bb + (size_t)8 * N);
        asm volatile("cp.async.commit_group;");
    }

    int buf = 0;
    for (int t = 0; t < ntile; ++t) {
        asm volatile("cp.async.wait_group 0;");
        __syncthreads();
        if (t + 1 < ntile) {
            int nb = buf ^ 1;
            const float* Ab = A + (size_t)(bm + ar0) * K + (t + 1) * BKT + ac0;
            cpasync16(sA + nb * sAsz + (ar0 * ASTR + ac0) * 4, Ab);
            cpasync16(sA + nb * sAsz + (ar0 * ASTR + ac0 + 4) * 4, Ab + 4);
            const float* Bb = B + (size_t)((t + 1) * BKT + br0) * N + bn + bc0;
            cpasync16(sB + nb * sBsz + (br0 * BSTR + bc0) * 4, Bb);
            cpasync16(sB + nb * sBsz + ((br0 + 8) * BSTR + bc0) * 4, Bb + (size_t)8 * N);
            asm volatile("cp.async.commit_group;");
        }
        #pragma unroll
        for (int ks = 0; ks < BKT; ks += 8) {
            uint32_t a[4][4], b[4][2];
            #pragma unroll
            for (int mt = 0; mt < 4; ++mt) {
                int r0 = wm + mt * 16 + g;
                a[mt][0] = f2tf(As[buf][r0][ks + q]);
                a[mt][1] = f2tf(As[buf][r0 + 8][ks + q]);
                a[mt][2] = f2tf(As[buf][r0][ks + q + 4]);
                a[mt][3] = f2tf(As[buf][r0 + 8][ks + q + 4]);
            }
            #pragma unroll
            for (int nt = 0; nt < 4; ++nt) {
                int c0 = wn + nt * 8 + g;
                b[nt][0] = f2tf(Bs[buf][ks + q][c0]);
                b[nt][1] = f2tf(Bs[buf][ks + q + 4][c0]);
            }
            #pragma unroll
            for (int mt = 0; mt < 4; ++mt)
                #pragma unroll
                for (int nt = 0; nt < 4; ++nt)
                    mma_tf32(acc[mt][nt], a[mt], b[nt]);
        }
        buf ^= 1;
    }

    // epilogue
    #pragma unroll
    for (int mt = 0; mt < 4; ++mt) {
        #pragma unroll
        for (int half = 0; half < 2; ++half) {
            int row = bm + wm + mt * 16 + g + half * 8;
            size_t rbase = (size_t)row * N + bn + wn;
            #pragma unroll
            for (int nt = 0; nt < 4; ++nt) {
                int col = nt * 8 + q * 2;
                float2 v;
                v.x = acc[mt][nt][half * 2 + 0];
                v.y = acc[mt][nt][half * 2 + 1];
                if (R) {
                    const float2 rr = *(const float2*)(R + rbase + col);
                    v.x += rr.x; v.y += rr.y;
                }
                *(float2*)(C + rbase + col) = v;
            }
        }
    }
}

// ---------------- causal short conv (K=4) + silu ----------------
__global__ void conv_silu_kernel(const float* __restrict__ x, const float* __restrict__ w,
                                 float* __restrict__ y) {
    size_t idx = (size_t)blockIdx.x * 256 + threadIdx.x;
    if (idx >= (size_t)BT * DD) return;
    int d = (int)(idx % DD);
    int t = (int)((idx / DD) % TT);
    size_t bbase = idx - (size_t)t * DD - d;
    float acc = 0.f;
    #pragma unroll
    for (int k = 0; k < 4; ++k) {
        int tt = t - 3 + k;
        if (tt >= 0) acc += x[bbase + (size_t)tt * DD + d] * w[d * 4 + k];
    }
    y[idx] = acc / (1.f + expf(-acc));
}

// ---------------- RoPE table (double-precision sin/cos of the fp32 phase) ----------------
__global__ void rope_table_kernel() {
    int idx = blockIdx.x * 256 + threadIdx.x;
    if (idx >= TT * 64) return;
    int t = idx >> 6, j = idx & 63;
    float invf = (float)(1.0 / pow(10000.0, (double)j / 64.0));
    float f = (float)t * invf;
    g_cos[idx] = (float)cos((double)f);
    g_sin[idx] = (float)sin((double)f);
}

// ---------------- RoPE apply, in place on [B,T,H,128] ----------------
__global__ void rope_kernel(float* __restrict__ x) {
    size_t idx = (size_t)blockIdx.x * 256 + threadIdx.x;
    if (idx >= (size_t)BB * TT * HH * 64) return;
    int j = (int)(idx & 63);
    int h = (int)((idx >> 6) & 7);
    size_t bt = idx >> 9;
    int t = (int)(bt % TT);
    float c = g_cos[t * 64 + j], s = g_sin[t * 64 + j];
    size_t base = bt * DD + h * 128;
    float x1 = x[base + j], x2 = x[base + 64 + j];
    x[base + j]      = x1 * c - x2 * s;
    x[base + 64 + j] = x1 * s + x2 * c;
}

// ---------------- retention phase 1 ----------------
__global__ void ret_phase1(const float* __restrict__ k, const float* __restrict__ v,
                           float* __restrict__ S) {
    extern __shared__ float sm[];
    float* ks = sm;               // 64 x 129 (padded)
    float* vs = sm + 64 * 129;
    int c = blockIdx.x, h = blockIdx.y, b = blockIdx.z;
    float gamma = 1.f - exp2f(-5.f - (float)h);
    float lg = logf(gamma);
    int tid = threadIdx.x;
    for (int x = tid; x < 8192; x += 256) {
        int i = x >> 7, d = x & 127;
        size_t g = ((size_t)b * TT + c * 64 + i) * DD + h * 128 + d;
        ks[i * 129 + d] = k[g] * expf(lg * (float)(63 - i));
        vs[i * 129 + d] = v[g];
    }
    __syncthreads();
    size_t sb = (((size_t)(b * HH + h)) * NC + c) * 16384;
    for (int x = tid; x < 16384; x += 256) {
        int d = x >> 7, e = x & 127;
        float a = 0.f;
        #pragma unroll
        for (int j = 0; j < 64; ++j) a += ks[j * 129 + d] * vs[j * 129 + e];
        S[sb + x] = a;
    }
}

// ---------------- retention phase 2: exclusive prefix scan over chunks ----------------
__global__ void ret_scan(float* __restrict__ S) {
    int bh = blockIdx.x;
    int h = bh & 7;
    float gamma = 1.f - exp2f(-5.f - (float)h);
    float cdec = expf(logf(gamma) * 64.f);
    float carry[64];
    #pragma unroll
    for (int r = 0; r < 64; ++r) carry[r] = 0.f;
    size_t base = (size_t)bh * NC * 16384;
    for (int c = 0; c < NC; ++c) {
        size_t cb = base + (size_t)c * 16384;
        #pragma unroll
        for (int r = 0; r < 64; ++r) {
            size_t idx = cb + threadIdx.x + (r << 8);
            float loc = S[idx];
            S[idx] = carry[r];
            carry[r] = carry[r] * cdec + loc;
        }
    }
}

// ---------------- retention phase 3 ----------------
__global__ void ret_phase3(const float* __restrict__ q, const float* __restrict__ k,
                           const float* __restrict__ v, const float* __restrict__ S,
                           float* __restrict__ o) {
    extern __shared__ float sm[];
    float* qs  = sm;                  // 64 x 129
    float* ks  = qs + 64 * 129;       // 64 x 129
    float* vs  = ks + 64 * 129;       // 64 x 129
    float* Ps  = vs + 64 * 129;       // 128 x 129
    float* att = Ps + 128 * 129;      // 64 x 65
    int c = blockIdx.x, h = blockIdx.y, b = blockIdx.z;
    float gamma = 1.f - exp2f(-5.f - (float)h);
    float lg = logf(gamma);
    const float scale = 0.08838834764831845f;  // 128^-0.5
    int tid = threadIdx.x;
    for (int x = tid; x < 8192; x += 256) {
        int i = x >> 7, d = x & 127;
        size_t g = ((size_t)b * TT + c * 64 + i) * DD + h * 128 + d;
        qs[i * 129 + d] = q[g] * scale;
        ks[i * 129 + d] = k[g];
        vs[i * 129 + d] = v[g];
    }
    size_t sb = (((size_t)(b * HH + h)) * NC + c) * 16384;
    for (int x = tid; x < 16384; x += 256) {
        int d = x >> 7, e = x & 127;
        Ps[d * 129 + e] = S[sb + x];
    }
    __syncthreads();
    for (int x = tid; x < 4096; x += 256) {
        int i = x >> 6, j = x & 63;
        float a = 0.f;
        if (i >= j) {
            #pragma unroll
            for (int d = 0; d < 128; ++d) a += qs[i * 129 + d] * ks[j * 129 + d];
            a *= expf(lg * (float)(i - j));
        }
        att[i * 65 + j] = a;
    }
    __syncthreads();
    for (int x = tid; x < 8192; x += 256) {
        int i = x >> 7, e = x & 127;
        float acc = 0.f;
        #pragma unroll
        for (int j = 0; j < 64; ++j) acc += att[i * 65 + j] * vs[j * 129 + e];
        float acc2 = 0.f;
        #pragma unroll
        for (int d = 0; d < 128; ++d) acc2 += qs[i * 129 + d] * Ps[d * 129 + e];
        acc += expf(lg * (float)(i + 1)) * acc2;
        o[((size_t)b * TT + c * 64 + i) * DD + h * 128 + e] = acc;
    }
}

// ---------------- gating ----------------
__global__ void gate_kernel(float* __restrict__ o, const float* __restrict__ g,
                            const float* __restrict__ w) {
    int row = blockIdx.x * 8 + (threadIdx.x >> 5);
    int lane = threadIdx.x & 31;
    float* orow = o + (size_t)row * 128;
    const float* grow = g + (size_t)row * 128;
    float v[4]; float s = 0.f;
    #pragma unroll
    for (int r = 0; r < 4; ++r) { v[r] = orow[lane + 32 * r]; s += v[r] * v[r]; }
    #pragma unroll
    for (int off = 16; off > 0; off >>= 1) s += __shfl_xor_sync(0xffffffffu, s, off);
    float inv = rsqrtf(s / 128.f + GATE_EPS);
    #pragma unroll
    for (int r = 0; r < 4; ++r) {
        int i = lane + 32 * r;
        float gg = grow[i];
        orow[i] = v[r] * inv * w[i] * (gg / (1.f + expf(-gg)));
    }
}

// ---------------- swiglu combine ----------------
__global__ void swiglu_kernel(float* __restrict__ a, const float* __restrict__ b2, size_t n) {
    size_t idx = (size_t)blockIdx.x * 256 + threadIdx.x;
    if (idx < n) { float x = a[idx]; a[idx] = (x / (1.f + expf(-x))) * b2[idx]; }
}

// ---------------- launch ----------------
extern "C" void kernel_launch(void* const* d_in, const int* in_sizes, int n_in,
                              void* d_out, int out_size) {
    const float* hs    = (const float*)d_in[0];
    const float* ln1   = (const float*)d_in[1];
    const float* ln2   = (const float*)d_in[2];
    const float* wq    = (const float*)d_in[3];
    const float* wk    = (const float*)d_in[4];
    const float* wv    = (const float*)d_in[5];
    const float* wg    = (const float*)d_in[6];
    const float* wo    = (const float*)d_in[7];
    const float* cq    = (const float*)d_in[8];
    const float* ck    = (const float*)d_in[9];
    const float* cv    = (const float*)d_in[10];
    const float* gn    = (const float*)d_in[11];
    const float* wgate = (const float*)d_in[12];
    const float* wup   = (const float*)d_in[13];
    const float* wdown = (const float*)d_in[14];
    float* out = (float*)d_out;

    cudaFuncSetAttribute(ret_phase1, cudaFuncAttributeMaxDynamicSharedMemorySize, 2 * 64 * 129 * 4);
    cudaFuncSetAttribute(ret_phase3, cudaFuncAttributeMaxDynamicSharedMemorySize,
                         (3 * 64 * 129 + 128 * 129 + 64 * 65) * 4);

    float *xn, *t0, *t1, *t2, *q, *k, *v, *o, *hbuf, *S, *m1, *m2;
    cudaGetSymbolAddress((void**)&xn, g_xn);
    cudaGetSymbolAddress((void**)&t0, g_t0);
    cudaGetSymbolAddress((void**)&t1, g_t1);
    cudaGetSymbolAddress((void**)&t2, g_t2);
    cudaGetSymbolAddress((void**)&q,  g_q);
    cudaGetSymbolAddress((void**)&k,  g_k);
    cudaGetSymbolAddress((void**)&v,  g_v);
    cudaGetSymbolAddress((void**)&o,  g_o);
    cudaGetSymbolAddress((void**)&hbuf, g_h);
    cudaGetSymbolAddress((void**)&S,  g_S);
    cudaGetSymbolAddress((void**)&m1, g_m1);
    cudaGetSymbolAddress((void**)&m2, g_m2);

    const int ew = (int)(((size_t)BT * DD + 255) / 256);
    rope_table_kernel<<<(TT * 64 + 255) / 256, 256>>>();
    rmsnorm_kernel<<<BT, 256>>>(hs, ln1, xn, RMS_EPS);

    dim3 g8(DD / 128, BT / 128);
    tgemm_kernel<<<g8, 256>>>(xn, wq, nullptr, t0, BT, DD, DD);
    conv_silu_kernel<<<ew, 256>>>(t0, cq, q);
    tgemm_kernel<<<g8, 256>>>(xn, wk, nullptr, t1, BT, DD, DD);
    conv_silu_kernel<<<ew, 256>>>(t1, ck, k);
    tgemm_kernel<<<g8, 256>>>(xn, wv, nullptr, t2, BT, DD, DD);
    conv_silu_kernel<<<ew, 256>>>(t2, cv, v);

    const int rw = (int)(((size_t)BB * TT * HH * 64 + 255) / 256);
    rope_kernel<<<rw, 256>>>(q);
    rope_kernel<<<rw, 256>>>(k);

    dim3 gc(NC, HH, BB);
    ret_phase1<<<gc, 256, 2 * 64 * 129 * 4>>>(k, v, S);
    ret_scan<<<BB * HH, 256>>>(S);
    ret_phase3<<<gc, 256, (3 * 64 * 129 + 128 * 129 + 64 * 65) * 4>>>(q, k, v, S, o);

    tgemm_kernel<<<g8, 256>>>(xn, wg, nullptr, t0, BT, DD, DD);
    gate_kernel<<<(BT * HH) / 8, 256>>>(o, t0, gn);
    tgemm_kernel<<<g8, 256>>>(o, wo, hs, hbuf, BT, DD, DD);

    rmsnorm_kernel<<<BT, 256>>>(hbuf, ln2, xn, RMS_EPS);
    dim3 gi(II / 128, BT / 128);
    tgemm_kernel<<<gi, 256>>>(xn, wgate, nullptr, m1, BT, II, DD);
    tgemm_kernel<<<gi, 256>>>(xn, wup,   nullptr, m2, BT, II, DD);
    size_t nmid = (size_t)BT * II;
    swiglu_kernel<<<(int)((nmid + 255) / 256), 256>>>(m1, m2, nmid);
    tgemm_kernel<<<g8, 256>>>(m1, wdown, hbuf, out, BT, DD, II);
}

// round 3
// speedup vs baseline: 2.6946x; 1.3165x over previous
#include <cuda_runtime.h>
#include <math.h>
#include <stdint.h>

#define BB 4
#define TT 8192
#define DD 1024
#define HH 8
#define DKV 128
#define II 2816
#define CHUNK 64
#define NC (TT/CHUNK)
#define BT (BB*TT)

#define RMS_EPS 1e-6f
#define GATE_EPS 1e-5f

// ---------------- scratch ----------------
__device__ float g_xn[(size_t)BT*DD];
__device__ float g_t0[(size_t)BT*DD];
__device__ float g_t1[(size_t)BT*DD];
__device__ float g_t2[(size_t)BT*DD];
__device__ float g_q [(size_t)BT*DD];
__device__ float g_k [(size_t)BT*DD];
__device__ float g_v [(size_t)BT*DD];
__device__ float g_o [(size_t)BT*DD];
__device__ float g_h [(size_t)BT*DD];
__device__ float g_S [(size_t)BB*HH*NC*DKV*DKV];
__device__ float g_m1[(size_t)BT*II];
__device__ float g_m2[(size_t)BT*II];
__device__ float g_cos[TT*64];
__device__ float g_sin[TT*64];

// ---------------- rmsnorm (float4, 256 thr = 1024 elems) ----------------
__global__ void rmsnorm_kernel(const float* __restrict__ x, const float* __restrict__ w,
                               float* __restrict__ out, float eps) {
    int row = blockIdx.x;
    const float4* xr = (const float4*)(x + (size_t)row * DD);
    float4 v = xr[threadIdx.x];
    float s = v.x * v.x + v.y * v.y + v.z * v.z + v.w * v.w;
    __shared__ float red[8];
    #pragma unroll
    for (int o = 16; o > 0; o >>= 1) s += __shfl_down_sync(0xffffffffu, s, o);
    if ((threadIdx.x & 31) == 0) red[threadIdx.x >> 5] = s;
    __syncthreads();
    if (threadIdx.x < 8) {
        s = red[threadIdx.x];
        #pragma unroll
        for (int o = 4; o > 0; o >>= 1) s += __shfl_down_sync(0xffu, s, o);
        if (threadIdx.x == 0) red[0] = s;
    }
    __syncthreads();
    float inv = rsqrtf(red[0] / (float)DD + eps);
    float4 wv = ((const float4*)w)[threadIdx.x];
    float4 o4;
    o4.x = v.x * inv * wv.x; o4.y = v.y * inv * wv.y;
    o4.z = v.z * inv * wv.z; o4.w = v.w * inv * wv.w;
    ((float4*)(out + (size_t)row * DD))[threadIdx.x] = o4;
}

// ================= tf32 tensor-core GEMM, 256x128 CTA, 64x64 warp, 3-stage =================
#define BKT 16
#define AST 20
#define BST 136
#define SMEM_GEMM ((3*256*AST + 3*16*BST) * 4)

__device__ __forceinline__ uint32_t f2tf(float x) {
    uint32_t r;
    asm("cvt.rna.tf32.f32 %0, %1;" : "=r"(r) : "f"(x));
    return r;
}
__device__ __forceinline__ void mma_tf32(float* c, const uint32_t* a, const uint32_t* b) {
    asm volatile("mma.sync.aligned.m16n8k8.row.col.f32.tf32.tf32.f32 "
        "{%0,%1,%2,%3}, {%4,%5,%6,%7}, {%8,%9}, {%0,%1,%2,%3};"
        : "+f"(c[0]), "+f"(c[1]), "+f"(c[2]), "+f"(c[3])
        : "r"(a[0]), "r"(a[1]), "r"(a[2]), "r"(a[3]), "r"(b[0]), "r"(b[1]));
}
__device__ __forceinline__ void cpasync16(uint32_t s, const void* g) {
    asm volatile("cp.async.cg.shared.global [%0], [%1], 16;" :: "r"(s), "l"(g));
}

__global__ __launch_bounds__(256, 1)
void tgemm_kernel(const float* __restrict__ A, const float* __restrict__ B,
                  const float* __restrict__ R, float* __restrict__ C,
                  int M, int N, int K) {
    extern __shared__ float sm[];
    float* As = sm;                     // 3 stages of 256 x AST
    float* Bs = sm + 3 * 256 * AST;     // 3 stages of 16 x BST

    const int tid = threadIdx.x;
    const int lane = tid & 31;
    const int w = tid >> 5;
    const int g = lane >> 2, q = lane & 3;
    const int wm = (w & 3) * 64;
    const int wn = (w >> 2) * 64;
    const int bm = blockIdx.y * 256, bn = blockIdx.x * 128;

    uint32_t sA = (uint32_t)__cvta_generic_to_shared(As);
    uint32_t sB = (uint32_t)__cvta_generic_to_shared(Bs);

    float acc[4][8][4];
    #pragma unroll
    for (int i = 0; i < 4; ++i)
        #pragma unroll
        for (int j = 0; j < 8; ++j)
            #pragma unroll
            for (int r = 0; r < 4; ++r) acc[i][j][r] = 0.f;

    const int ntile = K / BKT;

    // load helper (4 A-float4s + 2 B-float4s per thread)
    auto loadTile = [&](int t, int s) {
        #pragma unroll
        for (int i = 0; i < 4; ++i) {
            int idx = i * 256 + tid;
            int arow = idx >> 2, acol = (idx & 3) * 4;
            cpasync16(sA + (uint32_t)(s * 256 * AST + arow * AST + acol) * 4,
                      A + (size_t)(bm + arow) * K + t * BKT + acol);
        }
        #pragma unroll
        for (int i = 0; i < 2; ++i) {
            int idx = i * 256 + tid;
            int brow = idx >> 5, bcol = (idx & 31) * 4;
            cpasync16(sB + (uint32_t)(s * 16 * BST + brow * BST + bcol) * 4,
                      B + (size_t)(t * BKT + brow) * N + bn + bcol);
        }
        asm volatile("cp.async.commit_group;");
    };

    loadTile(0, 0);
    loadTile(1, 1);

    for (int t = 0; t < ntile; ++t) {
        int s = t % 3;
        if (t + 2 < ntile) asm volatile("cp.async.wait_group 1;");
        else               asm volatile("cp.async.wait_group 0;");
        __syncthreads();
        if (t + 2 < ntile) loadTile(t + 2, (t + 2) % 3);

        const float* Asb = As + s * 256 * AST;
        const float* Bsb = Bs + s * 16 * BST;
        #pragma unroll
        for (int ks = 0; ks < BKT; ks += 8) {
            uint32_t a[4][4], b[8][2];
            #pragma unroll
            for (int mt = 0; mt < 4; ++mt) {
                const float* p = Asb + (wm + mt * 16 + g) * AST + ks + q;
                a[mt][0] = f2tf(p[0]);
                a[mt][1] = f2tf(p[8 * AST]);
                a[mt][2] = f2tf(p[4]);
                a[mt][3] = f2tf(p[8 * AST + 4]);
            }
            #pragma unroll
            for (int nt = 0; nt < 8; ++nt) {
                int c0 = wn + nt * 8 + g;
                b[nt][0] = f2tf(Bsb[(ks + q) * BST + c0]);
                b[nt][1] = f2tf(Bsb[(ks + q + 4) * BST + c0]);
            }
            #pragma unroll
            for (int mt = 0; mt < 4; ++mt)
                #pragma unroll
                for (int nt = 0; nt < 8; ++nt)
                    mma_tf32(acc[mt][nt], a[mt], b[nt]);
        }
    }

    #pragma unroll
    for (int mt = 0; mt < 4; ++mt) {
        #pragma unroll
        for (int half = 0; half < 2; ++half) {
            int row = bm + wm + mt * 16 + g + half * 8;
            size_t rbase = (size_t)row * N + bn + wn;
            #pragma unroll
            for (int nt = 0; nt < 8; ++nt) {
                int col = nt * 8 + q * 2;
                float2 v;
                v.x = acc[mt][nt][half * 2 + 0];
                v.y = acc[mt][nt][half * 2 + 1];
                if (R) {
                    const float2 rr = *(const float2*)(R + rbase + col);
                    v.x += rr.x; v.y += rr.y;
                }
                *(float2*)(C + rbase + col) = v;
            }
        }
    }
}

// ---------------- causal short conv (K=4) + silu, float4 over d ----------------
__global__ void conv_silu_kernel(const float* __restrict__ x, const float* __restrict__ w,
                                 float* __restrict__ y) {
    size_t idx = (size_t)blockIdx.x * 256 + threadIdx.x;   // over BT*DD/4
    if (idx >= (size_t)BT * DD / 4) return;
    int d4 = (int)(idx & 255);
    size_t bt = idx >> 8;
    int t = (int)(bt % TT);
    const float4* x4 = (const float4*)x;
    const float4* w4 = (const float4*)w;
    float4 wr0 = w4[d4 * 4 + 0], wr1 = w4[d4 * 4 + 1];
    float4 wr2 = w4[d4 * 4 + 2], wr3 = w4[d4 * 4 + 3];
    const float* pw0 = (const float*)&wr0;
    const float* pw1 = (const float*)&wr1;
    const float* pw2 = (const float*)&wr2;
    const float* pw3 = (const float*)&wr3;
    float4 acc = make_float4(0.f, 0.f, 0.f, 0.f);
    #pragma unroll
    for (int k = 0; k < 4; ++k) {
        int tt = t - 3 + k;
        if (tt >= 0) {
            float4 xv = x4[idx - (size_t)(3 - k) * 256];
            acc.x = fmaf(xv.x, pw0[k], acc.x);
            acc.y = fmaf(xv.y, pw1[k], acc.y);
            acc.z = fmaf(xv.z, pw2[k], acc.z);
            acc.w = fmaf(xv.w, pw3[k], acc.w);
        }
    }
    acc.x = acc.x / (1.f + expf(-acc.x));
    acc.y = acc.y / (1.f + expf(-acc.y));
    acc.z = acc.z / (1.f + expf(-acc.z));
    acc.w = acc.w / (1.f + expf(-acc.w));
    ((float4*)y)[idx] = acc;
}

// ---------------- RoPE table ----------------
__global__ void rope_table_kernel() {
    int idx = blockIdx.x * 256 + threadIdx.x;
    if (idx >= TT * 64) return;
    int t = idx >> 6, j = idx & 63;
    float invf = (float)(1.0 / pow(10000.0, (double)j / 64.0));
    float f = (float)t * invf;
    g_cos[idx] = (float)cos((double)f);
    g_sin[idx] = (float)sin((double)f);
}

// ---------------- RoPE apply ----------------
__global__ void rope_kernel(float* __restrict__ x) {
    size_t idx = (size_t)blockIdx.x * 256 + threadIdx.x;
    if (idx >= (size_t)BB * TT * HH * 64) return;
    int j = (int)(idx & 63);
    int h = (int)((idx >> 6) & 7);
    size_t bt = idx >> 9;
    int t = (int)(bt % TT);
    float c = g_cos[t * 64 + j], s = g_sin[t * 64 + j];
    size_t base = bt * DD + h * 128;
    float x1 = x[base + j], x2 = x[base + 64 + j];
    x[base + j]      = x1 * c - x2 * s;
    x[base + 64 + j] = x1 * s + x2 * c;
}

// ---------------- retention phase 1: register-tiled 4x16 ----------------
__global__ void ret_phase1(const float* __restrict__ k, const float* __restrict__ v,
                           float* __restrict__ S) {
    extern __shared__ float sm[];
    float* ks = sm;               // 64 x 129
    float* vs = sm + 64 * 129;
    int c = blockIdx.x, h = blockIdx.y, b = blockIdx.z;
    float gamma = 1.f - exp2f(-5.f - (float)h);
    float lg = logf(gamma);
    int tid = threadIdx.x;
    for (int x = tid; x < 8192; x += 256) {
        int i = x >> 7, d = x & 127;
        size_t gg = ((size_t)b * TT + c * 64 + i) * DD + h * 128 + d;
        ks[i * 129 + d] = k[gg] * expf(lg * (float)(63 - i));
        vs[i * 129 + d] = v[gg];
    }
    __syncthreads();
    int w = tid >> 5, lane = tid & 31;
    int d0 = w * 16 + (lane >> 3) * 4;
    int e0 = (lane & 7) * 16;
    float acc[4][16];
    #pragma unroll
    for (int i = 0; i < 4; ++i)
        #pragma unroll
        for (int j = 0; j < 16; ++j) acc[i][j] = 0.f;
    #pragma unroll 4
    for (int j = 0; j < 64; ++j) {
        float kr[4], vr[16];
        #pragma unroll
        for (int i = 0; i < 4; ++i) kr[i] = ks[j * 129 + d0 + i];
        #pragma unroll
        for (int e = 0; e < 16; ++e) vr[e] = vs[j * 129 + e0 + e];
        #pragma unroll
        for (int i = 0; i < 4; ++i)
            #pragma unroll
            for (int e = 0; e < 16; ++e) acc[i][e] = fmaf(kr[i], vr[e], acc[i][e]);
    }
    size_t sb = (((size_t)(b * HH + h)) * NC + c) * 16384;
    #pragma unroll
    for (int i = 0; i < 4; ++i)
        #pragma unroll
        for (int e = 0; e < 16; ++e)
            S[sb + (d0 + i) * 128 + e0 + e] = acc[i][e];
}

// ---------------- retention phase 2: fully-parallel exclusive scan ----------------
__global__ void ret_scan(float* __restrict__ S) {
    int bh = blockIdx.x >> 6;
    int elem = ((blockIdx.x & 63) << 8) + threadIdx.x;   // 0..16383
    int h = bh & 7;
    float gamma = 1.f - exp2f(-5.f - (float)h);
    float cdec = expf(logf(gamma) * 64.f);
    float carry = 0.f;
    size_t base = (size_t)bh * NC * 16384 + elem;
    for (int c = 0; c < NC; ++c) {
        size_t idx = base + (size_t)c * 16384;
        float loc = S[idx];
        S[idx] = carry;
        carry = carry * cdec + loc;
    }
}

// ---------------- retention phase 3: register-tiled ----------------
__global__ void ret_phase3(const float* __restrict__ q, const float* __restrict__ k,
                           const float* __restrict__ v, const float* __restrict__ S,
                           float* __restrict__ o) {
    extern __shared__ float sm[];
    float* qs  = sm;                  // 64 x 129
    float* ks  = qs + 64 * 129;       // 64 x 129
    float* vs  = ks + 64 * 129;       // 64 x 129
    float* Ps  = vs + 64 * 129;       // 128 x 129
    float* att = Ps + 128 * 129;      // 64 x 65
    int c = blockIdx.x, h = blockIdx.y, b = blockIdx.z;
    float gamma = 1.f - exp2f(-5.f - (float)h);
    float lg = logf(gamma);
    const float scale = 0.08838834764831845f;
    int tid = threadIdx.x;
    int lane = tid & 31;
    for (int x = tid; x < 8192; x += 256) {
        int i = x >> 7, d = x & 127;
        size_t gg = ((size_t)b * TT + c * 64 + i) * DD + h * 128 + d;
        qs[i * 129 + d] = q[gg] * scale;
        ks[i * 129 + d] = k[gg];
        vs[i * 129 + d] = v[gg];
    }
    size_t sb = (((size_t)(b * HH + h)) * NC + c) * 16384;
    for (int x = tid; x < 16384; x += 256) {
        int d = x >> 7, e = x & 127;
        Ps[d * 129 + e] = S[sb + x];
    }
    __syncthreads();

    // att = (qs @ ks^T) * mask : each thread 4x4
    {
        int i0 = (tid >> 4) * 4;
        int j0 = (tid & 15) * 4;
        float a4[4][4];
        #pragma unroll
        for (int i = 0; i < 4; ++i)
            #pragma unroll
            for (int j = 0; j < 4; ++j) a4[i][j] = 0.f;
        #pragma unroll 4
        for (int d = 0; d < 128; ++d) {
            float qr[4], kr[4];
            #pragma unroll
            for (int i = 0; i < 4; ++i) qr[i] = qs[(i0 + i) * 129 + d];
            #pragma unroll
            for (int j = 0; j < 4; ++j) kr[j] = ks[(j0 + j) * 129 + d];
            #pragma unroll
            for (int i = 0; i < 4; ++i)
                #pragma unroll
                for (int j = 0; j < 4; ++j) a4[i][j] = fmaf(qr[i], kr[j], a4[i][j]);
        }
        #pragma unroll
        for (int i = 0; i < 4; ++i)
            #pragma unroll
            for (int j = 0; j < 4; ++j) {
                int ia = i0 + i, ja = j0 + j;
                float f = (ia >= ja) ? expf(lg * (float)(ia - ja)) : 0.f;
                att[ia * 65 + ja] = a4[i][j] * f;
            }
    }
    __syncthreads();

    // o = att @ vs + cross * (qs @ Ps) : each thread 4x8
    {
        int i0 = (tid >> 5) * 8 + (lane >> 4) * 4;
        int e0 = (lane & 15) * 8;
        float accA[4][8], accB[4][8];
        #pragma unroll
        for (int i = 0; i < 4; ++i)
            #pragma unroll
            for (int e = 0; e < 8; ++e) { accA[i][e] = 0.f; accB[i][e] = 0.f; }
        #pragma unroll 4
        for (int j = 0; j < 64; ++j) {
            float ar[4], vr[8];
            #pragma unroll
            for (int i = 0; i < 4; ++i) ar[i] = att[(i0 + i) * 65 + j];
            #pragma unroll
            for (int e = 0; e < 8; ++e) vr[e] = vs[j * 129 + e0 + e];
            #pragma unroll
            for (int i = 0; i < 4; ++i)
                #pragma unroll
                for (int e = 0; e < 8; ++e) accA[i][e] = fmaf(ar[i], vr[e], accA[i][e]);
        }
        #pragma unroll 4
        for (int d = 0; d < 128; ++d) {
            float qr[4], pr[8];
            #pragma unroll
            for (int i = 0; i < 4; ++i) qr[i] = qs[(i0 + i) * 129 + d];
            #pragma unroll
            for (int e = 0; e < 8; ++e) pr[e] = Ps[d * 129 + e0 + e];
            #pragma unroll
            for (int i = 0; i < 4; ++i)
                #pragma unroll
                for (int e = 0; e < 8; ++e) accB[i][e] = fmaf(qr[i], pr[e], accB[i][e]);
        }
        #pragma unroll
        for (int i = 0; i < 4; ++i) {
            float crossf = expf(lg * (float)(i0 + i + 1));
            size_t ob = ((size_t)b * TT + c * 64 + i0 + i) * DD + h * 128 + e0;
            #pragma unroll
            for (int e = 0; e < 8; ++e)
                o[ob + e] = accA[i][e] + crossf * accB[i][e];
        }
    }
}

// ---------------- gating (float4) ----------------
__global__ void gate_kernel(float* __restrict__ o, const float* __restrict__ g,
                            const float* __restrict__ w) {
    int row = blockIdx.x * 8 + (threadIdx.x >> 5);
    int lane = threadIdx.x & 31;
    float4* orow = (float4*)(o + (size_t)row * 128);
    const float4* grow = (const float4*)(g + (size_t)row * 128);
    float4 v = orow[lane];
    float s = v.x * v.x + v.y * v.y + v.z * v.z + v.w * v.w;
    #pragma unroll
    for (int off = 16; off > 0; off >>= 1) s += __shfl_xor_sync(0xffffffffu, s, off);
    float inv = rsqrtf(s / 128.f + GATE_EPS);
    float4 gv = grow[lane];
    float4 wv = ((const float4*)w)[lane];
    float4 r;
    r.x = v.x * inv * wv.x * (gv.x / (1.f + expf(-gv.x)));
    r.y = v.y * inv * wv.y * (gv.y / (1.f + expf(-gv.y)));
    r.z = v.z * inv * wv.z * (gv.z / (1.f + expf(-gv.z)));
    r.w = v.w * inv * wv.w * (gv.w / (1.f + expf(-gv.w)));
    orow[lane] = r;
}

// ---------------- swiglu (float4) ----------------
__global__ void swiglu_kernel(float* __restrict__ a, const float* __restrict__ b2, size_t n4) {
    size_t idx = (size_t)blockIdx.x * 256 + threadIdx.x;
    if (idx >= n4) return;
    float4 x = ((float4*)a)[idx];
    float4 y = ((const float4*)b2)[idx];
    x.x = (x.x / (1.f + expf(-x.x))) * y.x;
    x.y = (x.y / (1.f + expf(-x.y))) * y.y;
    x.z = (x.z / (1.f + expf(-x.z))) * y.z;
    x.w = (x.w / (1.f + expf(-x.w))) * y.w;
    ((float4*)a)[idx] = x;
}

// ---------------- launch ----------------
extern "C" void kernel_launch(void* const* d_in, const int* in_sizes, int n_in,
                              void* d_out, int out_size) {
    const float* hs    = (const float*)d_in[0];
    const float* ln1   = (const float*)d_in[1];
    const float* ln2   = (const float*)d_in[2];
    const float* wq    = (const float*)d_in[3];
    const float* wk    = (const float*)d_in[4];
    const float* wv    = (const float*)d_in[5];
    const float* wg    = (const float*)d_in[6];
    const float* wo    = (const float*)d_in[7];
    const float* cq    = (const float*)d_in[8];
    const float* ck    = (const float*)d_in[9];
    const float* cv    = (const float*)d_in[10];
    const float* gn    = (const float*)d_in[11];
    const float* wgate = (const float*)d_in[12];
    const float* wup   = (const float*)d_in[13];
    const float* wdown = (const float*)d_in[14];
    float* out = (float*)d_out;

    cudaFuncSetAttribute(tgemm_kernel, cudaFuncAttributeMaxDynamicSharedMemorySize, SMEM_GEMM);
    cudaFuncSetAttribute(ret_phase1, cudaFuncAttributeMaxDynamicSharedMemorySize, 2 * 64 * 129 * 4);
    cudaFuncSetAttribute(ret_phase3, cudaFuncAttributeMaxDynamicSharedMemorySize,
                         (3 * 64 * 129 + 128 * 129 + 64 * 65) * 4);

    float *xn, *t0, *t1, *t2, *q, *k, *v, *o, *hbuf, *S, *m1, *m2;
    cudaGetSymbolAddress((void**)&xn, g_xn);
    cudaGetSymbolAddress((void**)&t0, g_t0);
    cudaGetSymbolAddress((void**)&t1, g_t1);
    cudaGetSymbolAddress((void**)&t2, g_t2);
    cudaGetSymbolAddress((void**)&q,  g_q);
    cudaGetSymbolAddress((void**)&k,  g_k);
    cudaGetSymbolAddress((void**)&v,  g_v);
    cudaGetSymbolAddress((void**)&o,  g_o);
    cudaGetSymbolAddress((void**)&hbuf, g_h);
    cudaGetSymbolAddress((void**)&S,  g_S);
    cudaGetSymbolAddress((void**)&m1, g_m1);
    cudaGetSymbolAddress((void**)&m2, g_m2);

    const int ew4 = (int)(((size_t)BT * DD / 4 + 255) / 256);
    rope_table_kernel<<<(TT * 64 + 255) / 256, 256>>>();
    rmsnorm_kernel<<<BT, 256>>>(hs, ln1, xn, RMS_EPS);

    dim3 g8(DD / 128, BT / 256);
    tgemm_kernel<<<g8, 256, SMEM_GEMM>>>(xn, wq, nullptr, t0, BT, DD, DD);
    conv_silu_kernel<<<ew4, 256>>>(t0, cq, q);
    tgemm_kernel<<<g8, 256, SMEM_GEMM>>>(xn, wk, nullptr, t1, BT, DD, DD);
    conv_silu_kernel<<<ew4, 256>>>(t1, ck, k);
    tgemm_kernel<<<g8, 256, SMEM_GEMM>>>(xn, wv, nullptr, t2, BT, DD, DD);
    conv_silu_kernel<<<ew4, 256>>>(t2, cv, v);

    const int rw = (int)(((size_t)BB * TT * HH * 64 + 255) / 256);
    rope_kernel<<<rw, 256>>>(q);
    rope_kernel<<<rw, 256>>>(k);

    dim3 gc(NC, HH, BB);
    ret_phase1<<<gc, 256, 2 * 64 * 129 * 4>>>(k, v, S);
    ret_scan<<<BB * HH * 64, 256>>>(S);
    ret_phase3<<<gc, 256, (3 * 64 * 129 + 128 * 129 + 64 * 65) * 4>>>(q, k, v, S, o);

    tgemm_kernel<<<g8, 256, SMEM_GEMM>>>(xn, wg, nullptr, t0, BT, DD, DD);
    gate_kernel<<<(BT * HH) / 8, 256>>>(o, t0, gn);
    tgemm_kernel<<<g8, 256, SMEM_GEMM>>>(o, wo, hs, hbuf, BT, DD, DD);

    rmsnorm_kernel<<<BT, 256>>>(hbuf, ln2, xn, RMS_EPS);
    dim3 gi(II / 128, BT / 256);
    tgemm_kernel<<<gi, 256, SMEM_GEMM>>>(xn, wgate, nullptr, m1, BT, II, DD);
    tgemm_kernel<<<gi, 256, SMEM_GEMM>>>(xn, wup,   nullptr, m2, BT, II, DD);
    size_t nmid4 = (size_t)BT * II / 4;
    swiglu_kernel<<<(int)((nmid4 + 255) / 256), 256>>>(m1, m2, nmid4);
    tgemm_kernel<<<g8, 256, SMEM_GEMM>>>(m1, wdown, hbuf, out, BT, DD, II);
}

// round 4
// speedup vs baseline: 4.2397x; 1.5734x over previous
#include <cuda_runtime.h>
#include <cuda_fp16.h>
#include <math.h>
#include <stdint.h>

#define BB 4
#define TT 8192
#define DD 1024
#define HH 8
#define II 2816
#define NC 128
#define BT (BB*TT)

#define RMS_EPS 1e-6f
#define GATE_EPS 1e-5f

// ---------------- scratch ----------------
__device__ float  g_t0[(size_t)BT*DD];
__device__ float  g_t1[(size_t)BT*DD];
__device__ float  g_t2[(size_t)BT*DD];
__device__ float  g_q [(size_t)BT*DD];
__device__ float  g_k [(size_t)BT*DD];
__device__ float  g_v [(size_t)BT*DD];
__device__ float  g_o [(size_t)BT*DD];
__device__ float  g_h [(size_t)BT*DD];
__device__ float  g_S [(size_t)BB*HH*NC*128*128];
__device__ float  g_m1[(size_t)BT*II];
__device__ float  g_m2[(size_t)BT*II];
__device__ __half g_xh [(size_t)BT*DD];
__device__ __half g_oh [(size_t)BT*DD];
__device__ __half g_m1h[(size_t)BT*II];
__device__ __half g_bt [(size_t)DD*II];
__device__ float  g_cos[TT*64];
__device__ float  g_sin[TT*64];

// ---------------- rmsnorm -> fp16 out ----------------
__global__ void rmsnorm_kernel(const float* __restrict__ x, const float* __restrict__ w,
                               __half* __restrict__ out, float eps) {
    int row = blockIdx.x;
    const float4* xr = (const float4*)(x + (size_t)row * DD);
    float4 v = xr[threadIdx.x];
    float s = v.x * v.x + v.y * v.y + v.z * v.z + v.w * v.w;
    __shared__ float red[8];
    #pragma unroll
    for (int o = 16; o > 0; o >>= 1) s += __shfl_down_sync(0xffffffffu, s, o);
    if ((threadIdx.x & 31) == 0) red[threadIdx.x >> 5] = s;
    __syncthreads();
    if (threadIdx.x < 8) {
        s = red[threadIdx.x];
        #pragma unroll
        for (int o = 4; o > 0; o >>= 1) s += __shfl_down_sync(0xffu, s, o);
        if (threadIdx.x == 0) red[0] = s;
    }
    __syncthreads();
    float inv = rsqrtf(red[0] / (float)DD + eps);
    float4 wv = ((const float4*)w)[threadIdx.x];
    __half2* orow = (__half2*)(out + (size_t)row * DD);
    orow[threadIdx.x * 2]     = __floats2half2_rn(v.x * inv * wv.x, v.y * inv * wv.y);
    orow[threadIdx.x * 2 + 1] = __floats2half2_rn(v.z * inv * wv.z, v.w * inv * wv.w);
}

// ---------------- weight convert + transpose: W[K][N] fp32 -> Wt[N][K] fp16 ----------------
__global__ void convT_kernel(const float* __restrict__ W, __half* __restrict__ Wt,
                             int K, int N) {
    __shared__ float tile[32][33];
    int n0 = blockIdx.x * 32, k0 = blockIdx.y * 32;
    #pragma unroll
    for (int j = threadIdx.y; j < 32; j += 8)
        tile[j][threadIdx.x] = W[(size_t)(k0 + j) * N + n0 + threadIdx.x];
    __syncthreads();
    #pragma unroll
    for (int j = threadIdx.y; j < 32; j += 8)
        Wt[(size_t)(n0 + j) * K + k0 + threadIdx.x] = __float2half_rn(tile[threadIdx.x][j]);
}

// ================= fp16 tensor-core GEMM =================
// C = A @ B (+R), A: MxK fp16 row-major, Bt: NxK fp16 row-major (B transposed).
// 256x128 CTA tile, BK=32, 3-stage cp.async, 8 warps of 64x64, mma.m16n8k16.
#define BKH 32
#define XW 20                      // uint32 words per smem row (40 fp16: conflict-free)
#define AW (256*XW)
#define BW (128*XW)
#define SMEM_GEMM ((3*AW + 3*BW) * 4)

__device__ __forceinline__ void mma_fp16(float* c, const uint32_t* a, const uint32_t* b) {
    asm volatile("mma.sync.aligned.m16n8k16.row.col.f32.f16.f16.f32 "
        "{%0,%1,%2,%3}, {%4,%5,%6,%7}, {%8,%9}, {%0,%1,%2,%3};"
        : "+f"(c[0]), "+f"(c[1]), "+f"(c[2]), "+f"(c[3])
        : "r"(a[0]), "r"(a[1]), "r"(a[2]), "r"(a[3]), "r"(b[0]), "r"(b[1]));
}
__device__ __forceinline__ void cpasync16(uint32_t s, const void* g) {
    asm volatile("cp.async.cg.shared.global [%0], [%1], 16;" :: "r"(s), "l"(g));
}

__global__ __launch_bounds__(256, 1)
void hgemm_kernel(const __half* __restrict__ A, const __half* __restrict__ Bt,
                  const float* __restrict__ R, float* __restrict__ C,
                  int M, int N, int K) {
    extern __shared__ uint32_t smw[];

    const int tid = threadIdx.x;
    const int lane = tid & 31;
    const int w = tid >> 5;
    const int g = lane >> 2, q = lane & 3;
    const int wm = (w & 3) * 64;
    const int wn = (w >> 2) * 64;
    const int bm = blockIdx.y * 256, bn = blockIdx.x * 128;

    uint32_t sBase = (uint32_t)__cvta_generic_to_shared(smw);

    float acc[4][8][4];
    #pragma unroll
    for (int i = 0; i < 4; ++i)
        #pragma unroll
        for (int j = 0; j < 8; ++j)
            #pragma unroll
            for (int r = 0; r < 4; ++r) acc[i][j][r] = 0.f;

    const int ntile = K / BKH;

    auto loadTile = [&](int t, int s) {
        #pragma unroll
        for (int i = 0; i < 4; ++i) {
            int idx = i * 256 + tid;
            int row = idx >> 2, kc = (idx & 3) * 8;
            cpasync16(sBase + (uint32_t)((s * AW + row * XW) * 4 + kc * 2),
                      A + (size_t)(bm + row) * K + t * BKH + kc);
        }
        #pragma unroll
        for (int i = 0; i < 2; ++i) {
            int idx = i * 256 + tid;
            int n = idx >> 2, kc = (idx & 3) * 8;
            cpasync16(sBase + (uint32_t)((3 * AW + s * BW + n * XW) * 4 + kc * 2),
                      Bt + (size_t)(bn + n) * K + t * BKH + kc);
        }
        asm volatile("cp.async.commit_group;");
    };

    loadTile(0, 0);
    loadTile(1, 1);

    for (int t = 0; t < ntile; ++t) {
        int s = t % 3;
        if (t + 2 < ntile) asm volatile("cp.async.wait_group 1;");
        else               asm volatile("cp.async.wait_group 0;");
        __syncthreads();
        if (t + 2 < ntile) loadTile(t + 2, (t + 2) % 3);

        const uint32_t* Asb = smw + s * AW;
        const uint32_t* Bsb = smw + 3 * AW + s * BW;
        #pragma unroll
        for (int ks = 0; ks < 2; ++ks) {
            uint32_t a[4][4], b[8][2];
            #pragma unroll
            for (int mt = 0; mt < 4; ++mt) {
                int base = (wm + mt * 16 + g) * XW + ks * 8 + q;
                a[mt][0] = Asb[base];
                a[mt][1] = Asb[base + 8 * XW];
                a[mt][2] = Asb[base + 4];
                a[mt][3] = Asb[base + 8 * XW + 4];
            }
            #pragma unroll
            for (int nt = 0; nt < 8; ++nt) {
                int bb = (wn + nt * 8 + g) * XW + ks * 8 + q;
                b[nt][0] = Bsb[bb];
                b[nt][1] = Bsb[bb + 4];
            }
            #pragma unroll
            for (int mt = 0; mt < 4; ++mt)
                #pragma unroll
                for (int nt = 0; nt < 8; ++nt)
                    mma_fp16(acc[mt][nt], a[mt], b[nt]);
        }
    }

    #pragma unroll
    for (int mt = 0; mt < 4; ++mt) {
        #pragma unroll
        for (int half = 0; half < 2; ++half) {
            int row = bm + wm + mt * 16 + g + half * 8;
            size_t rbase = (size_t)row * N + bn + wn;
            #pragma unroll
            for (int nt = 0; nt < 8; ++nt) {
                int col = nt * 8 + q * 2;
                float2 v;
                v.x = acc[mt][nt][half * 2 + 0];
                v.y = acc[mt][nt][half * 2 + 1];
                if (R) {
                    const float2 rr = *(const float2*)(R + rbase + col);
                    v.x += rr.x; v.y += rr.y;
                }
                *(float2*)(C + rbase + col) = v;
            }
        }
    }
}

// ---------------- causal short conv (K=4) + silu, 4 timesteps/thread ----------------
__global__ void conv_silu_kernel(const float* __restrict__ x, const float* __restrict__ w,
                                 float* __restrict__ y) {
    int idx = blockIdx.x * 256 + threadIdx.x;          // BB*(TT/4)*256 threads
    int d4 = idx & 255;
    int rest = idx >> 8;
    int t4 = rest & (TT / 4 - 1);
    int b = rest >> 11;
    const float4* x4 = (const float4*)x;
    const float4* w4 = (const float4*)w;
    float4 wr0 = w4[d4 * 4 + 0], wr1 = w4[d4 * 4 + 1];
    float4 wr2 = w4[d4 * 4 + 2], wr3 = w4[d4 * 4 + 3];
    int t0 = t4 * 4;
    size_t rowbase = (size_t)b * TT * 256 + d4;
    float4 xv[7];
    #pragma unroll
    for (int j = 0; j < 7; ++j) {
        int tt = t0 - 3 + j;
        xv[j] = (tt >= 0) ? x4[rowbase + (size_t)tt * 256] : make_float4(0.f, 0.f, 0.f, 0.f);
    }
    #pragma unroll
    for (int i = 0; i < 4; ++i) {
        float4 a;
        a.x = xv[i].x * wr0.x + xv[i+1].x * wr0.y + xv[i+2].x * wr0.z + xv[i+3].x * wr0.w;
        a.y = xv[i].y * wr1.x + xv[i+1].y * wr1.y + xv[i+2].y * wr1.z + xv[i+3].y * wr1.w;
        a.z = xv[i].z * wr2.x + xv[i+1].z * wr2.y + xv[i+2].z * wr2.z + xv[i+3].z * wr2.w;
        a.w = xv[i].w * wr3.x + xv[i+1].w * wr3.y + xv[i+2].w * wr3.z + xv[i+3].w * wr3.w;
        a.x = a.x / (1.f + expf(-a.x));
        a.y = a.y / (1.f + expf(-a.y));
        a.z = a.z / (1.f + expf(-a.z));
        a.w = a.w / (1.f + expf(-a.w));
        ((float4*)y)[rowbase + (size_t)(t0 + i) * 256] = a;
    }
}

// ---------------- RoPE table ----------------
__global__ void rope_table_kernel() {
    int idx = blockIdx.x * 256 + threadIdx.x;
    if (idx >= TT * 64) return;
    int t = idx >> 6, j = idx & 63;
    float invf = (float)(1.0 / pow(10000.0, (double)j / 64.0));
    float f = (float)t * invf;
    g_cos[idx] = (float)cos((double)f);
    g_sin[idx] = (float)sin((double)f);
}

// ---------------- RoPE apply ----------------
__global__ void rope_kernel(float* __restrict__ x) {
    size_t idx = (size_t)blockIdx.x * 256 + threadIdx.x;
    if (idx >= (size_t)BB * TT * HH * 64) return;
    int j = (int)(idx & 63);
    int h = (int)((idx >> 6) & 7);
    size_t bt = idx >> 9;
    int t = (int)(bt % TT);
    float c = g_cos[t * 64 + j], s = g_sin[t * 64 + j];
    size_t base = bt * DD + h * 128;
    float x1 = x[base + j], x2 = x[base + 64 + j];
    x[base + j]      = x1 * c - x2 * s;
    x[base + 64 + j] = x1 * s + x2 * c;
}

// ---------------- retention phase 1 ----------------
__global__ void ret_phase1(const float* __restrict__ k, const float* __restrict__ v,
                           float* __restrict__ S) {
    extern __shared__ float sm[];
    float* ks = sm;
    float* vs = sm + 64 * 129;
    int c = blockIdx.x, h = blockIdx.y, b = blockIdx.z;
    float gamma = 1.f - exp2f(-5.f - (float)h);
    float lg = logf(gamma);
    int tid = threadIdx.x;
    for (int x = tid; x < 8192; x += 256) {
        int i = x >> 7, d = x & 127;
        size_t gg = ((size_t)b * TT + c * 64 + i) * DD + h * 128 + d;
        ks[i * 129 + d] = k[gg] * expf(lg * (float)(63 - i));
        vs[i * 129 + d] = v[gg];
    }
    __syncthreads();
    int w = tid >> 5, lane = tid & 31;
    int d0 = w * 16 + (lane >> 3) * 4;
    int e0 = (lane & 7) * 16;
    float acc[4][16];
    #pragma unroll
    for (int i = 0; i < 4; ++i)
        #pragma unroll
        for (int j = 0; j < 16; ++j) acc[i][j] = 0.f;
    #pragma unroll 4
    for (int j = 0; j < 64; ++j) {
        float kr[4], vr[16];
        #pragma unroll
        for (int i = 0; i < 4; ++i) kr[i] = ks[j * 129 + d0 + i];
        #pragma unroll
        for (int e = 0; e < 16; ++e) vr[e] = vs[j * 129 + e0 + e];
        #pragma unroll
        for (int i = 0; i < 4; ++i)
            #pragma unroll
            for (int e = 0; e < 16; ++e) acc[i][e] = fmaf(kr[i], vr[e], acc[i][e]);
    }
    size_t sb = (((size_t)(b * HH + h)) * NC + c) * 16384;
    #pragma unroll
    for (int i = 0; i < 4; ++i)
        #pragma unroll
        for (int e = 0; e < 16; ++e)
            S[sb + (d0 + i) * 128 + e0 + e] = acc[i][e];
}

// ---------------- retention phase 2: parallel exclusive scan ----------------
__global__ void ret_scan(float* __restrict__ S) {
    int bh = blockIdx.x >> 6;
    int elem = ((blockIdx.x & 63) << 8) + threadIdx.x;
    int h = bh & 7;
    float gamma = 1.f - exp2f(-5.f - (float)h);
    float cdec = expf(logf(gamma) * 64.f);
    float carry = 0.f;
    size_t base = (size_t)bh * NC * 16384 + elem;
    for (int c = 0; c < NC; ++c) {
        size_t idx = base + (size_t)c * 16384;
        float loc = S[idx];
        S[idx] = carry;
        carry = carry * cdec + loc;
    }
}

// ---------------- retention phase 3 ----------------
__global__ void ret_phase3(const float* __restrict__ q, const float* __restrict__ k,
                           const float* __restrict__ v, const float* __restrict__ S,
                           float* __restrict__ o) {
    extern __shared__ float sm[];
    float* qs  = sm;
    float* ks  = qs + 64 * 129;
    float* vs  = ks + 64 * 129;
    float* Ps  = vs + 64 * 129;
    float* att = Ps + 128 * 129;
    int c = blockIdx.x, h = blockIdx.y, b = blockIdx.z;
    float gamma = 1.f - exp2f(-5.f - (float)h);
    float lg = logf(gamma);
    const float scale = 0.08838834764831845f;
    int tid = threadIdx.x;
    int lane = tid & 31;
    for (int x = tid; x < 8192; x += 256) {
        int i = x >> 7, d = x & 127;
        size_t gg = ((size_t)b * TT + c * 64 + i) * DD + h * 128 + d;
        qs[i * 129 + d] = q[gg] * scale;
        ks[i * 129 + d] = k[gg];
        vs[i * 129 + d] = v[gg];
    }
    size_t sb = (((size_t)(b * HH + h)) * NC + c) * 16384;
    for (int x = tid; x < 16384; x += 256) {
        int d = x >> 7, e = x & 127;
        Ps[d * 129 + e] = S[sb + x];
    }
    __syncthreads();
    {
        int i0 = (tid >> 4) * 4;
        int j0 = (tid & 15) * 4;
        float a4[4][4];
        #pragma unroll
        for (int i = 0; i < 4; ++i)
            #pragma unroll
            for (int j = 0; j < 4; ++j) a4[i][j] = 0.f;
        #pragma unroll 4
        for (int d = 0; d < 128; ++d) {
            float qr[4], kr[4];
            #pragma unroll
            for (int i = 0; i < 4; ++i) qr[i] = qs[(i0 + i) * 129 + d];
            #pragma unroll
            for (int j = 0; j < 4; ++j) kr[j] = ks[(j0 + j) * 129 + d];
            #pragma unroll
            for (int i = 0; i < 4; ++i)
                #pragma unroll
                for (int j = 0; j < 4; ++j) a4[i][j] = fmaf(qr[i], kr[j], a4[i][j]);
        }
        #pragma unroll
        for (int i = 0; i < 4; ++i)
            #pragma unroll
            for (int j = 0; j < 4; ++j) {
                int ia = i0 + i, ja = j0 + j;
                float f = (ia >= ja) ? expf(lg * (float)(ia - ja)) : 0.f;
                att[ia * 65 + ja] = a4[i][j] * f;
            }
    }
    __syncthreads();
    {
        int i0 = (tid >> 5) * 8 + (lane >> 4) * 4;
        int e0 = (lane & 15) * 8;
        float accA[4][8], accB[4][8];
        #pragma unroll
        for (int i = 0; i < 4; ++i)
            #pragma unroll
            for (int e = 0; e < 8; ++e) { accA[i][e] = 0.f; accB[i][e] = 0.f; }
        #pragma unroll 4
        for (int j = 0; j < 64; ++j) {
            float ar[4], vr[8];
            #pragma unroll
            for (int i = 0; i < 4; ++i) ar[i] = att[(i0 + i) * 65 + j];
            #pragma unroll
            for (int e = 0; e < 8; ++e) vr[e] = vs[j * 129 + e0 + e];
            #pragma unroll
            for (int i = 0; i < 4; ++i)
                #pragma unroll
                for (int e = 0; e < 8; ++e) accA[i][e] = fmaf(ar[i], vr[e], accA[i][e]);
        }
        #pragma unroll 4
        for (int d = 0; d < 128; ++d) {
            float qr[4], pr[8];
            #pragma unroll
            for (int i = 0; i < 4; ++i) qr[i] = qs[(i0 + i) * 129 + d];
            #pragma unroll
            for (int e = 0; e < 8; ++e) pr[e] = Ps[d * 129 + e0 + e];
            #pragma unroll
            for (int i = 0; i < 4; ++i)
                #pragma unroll
                for (int e = 0; e < 8; ++e) accB[i][e] = fmaf(qr[i], pr[e], accB[i][e]);
        }
        #pragma unroll
        for (int i = 0; i < 4; ++i) {
            float crossf = expf(lg * (float)(i0 + i + 1));
            size_t ob = ((size_t)b * TT + c * 64 + i0 + i) * DD + h * 128 + e0;
            #pragma unroll
            for (int e = 0; e < 8; ++e)
                o[ob + e] = accA[i][e] + crossf * accB[i][e];
        }
    }
}

// ---------------- gating -> fp16 out ----------------
__global__ void gate_kernel(const float* __restrict__ o, const float* __restrict__ g,
                            const float* __restrict__ w, __half* __restrict__ oh) {
    int row = blockIdx.x * 8 + (threadIdx.x >> 5);
    int lane = threadIdx.x & 31;
    const float4* orow = (const float4*)(o + (size_t)row * 128);
    const float4* grow = (const float4*)(g + (size_t)row * 128);
    float4 v = orow[lane];
    float s = v.x * v.x + v.y * v.y + v.z * v.z + v.w * v.w;
    #pragma unroll
    for (int off = 16; off > 0; off >>= 1) s += __shfl_xor_sync(0xffffffffu, s, off);
    float inv = rsqrtf(s / 128.f + GATE_EPS);
    float4 gv = grow[lane];
    float4 wv = ((const float4*)w)[lane];
    float rx = v.x * inv * wv.x * (gv.x / (1.f + expf(-gv.x)));
    float ry = v.y * inv * wv.y * (gv.y / (1.f + expf(-gv.y)));
    float rz = v.z * inv * wv.z * (gv.z / (1.f + expf(-gv.z)));
    float rw = v.w * inv * wv.w * (gv.w / (1.f + expf(-gv.w)));
    __half2* dst = (__half2*)(oh + (size_t)row * 128);
    dst[lane * 2]     = __floats2half2_rn(rx, ry);
    dst[lane * 2 + 1] = __floats2half2_rn(rz, rw);
}

// ---------------- swiglu -> fp16 out ----------------
__global__ void swiglu_kernel(const float* __restrict__ a, const float* __restrict__ b2,
                              __half* __restrict__ outh, size_t n4) {
    size_t idx = (size_t)blockIdx.x * 256 + threadIdx.x;
    if (idx >= n4) return;
    float4 x = ((const float4*)a)[idx];
    float4 y = ((const float4*)b2)[idx];
    float rx = (x.x / (1.f + expf(-x.x))) * y.x;
    float ry = (x.y / (1.f + expf(-x.y))) * y.y;
    float rz = (x.z / (1.f + expf(-x.z))) * y.z;
    float rw = (x.w / (1.f + expf(-x.w))) * y.w;
    __half2* dst = (__half2*)outh;
    dst[idx * 2]     = __floats2half2_rn(rx, ry);
    dst[idx * 2 + 1] = __floats2half2_rn(rz, rw);
}

// ---------------- launch ----------------
extern "C" void kernel_launch(void* const* d_in, const int* in_sizes, int n_in,
                              void* d_out, int out_size) {
    const float* hs    = (const float*)d_in[0];
    const float* ln1   = (const float*)d_in[1];
    const float* ln2   = (const float*)d_in[2];
    const float* wq    = (const float*)d_in[3];
    const float* wk    = (const float*)d_in[4];
    const float* wv    = (const float*)d_in[5];
    const float* wg    = (const float*)d_in[6];
    const float* wo    = (const float*)d_in[7];
    const float* cq    = (const float*)d_in[8];
    const float* ck    = (const float*)d_in[9];
    const float* cv    = (const float*)d_in[10];
    const float* gn    = (const float*)d_in[11];
    const float* wgate = (const float*)d_in[12];
    const float* wup   = (const float*)d_in[13];
    const float* wdown = (const float*)d_in[14];
    float* out = (float*)d_out;

    cudaFuncSetAttribute(hgemm_kernel, cudaFuncAttributeMaxDynamicSharedMemorySize, SMEM_GEMM);
    cudaFuncSetAttribute(ret_phase1, cudaFuncAttributeMaxDynamicSharedMemorySize, 2 * 64 * 129 * 4);
    cudaFuncSetAttribute(ret_phase3, cudaFuncAttributeMaxDynamicSharedMemorySize,
                         (3 * 64 * 129 + 128 * 129 + 64 * 65) * 4);

    float *t0, *t1, *t2, *q, *k, *v, *o, *hbuf, *S, *m1, *m2;
    __half *xh, *oh, *m1h, *bt;
    cudaGetSymbolAddress((void**)&t0, g_t0);
    cudaGetSymbolAddress((void**)&t1, g_t1);
    cudaGetSymbolAddress((void**)&t2, g_t2);
    cudaGetSymbolAddress((void**)&q,  g_q);
    cudaGetSymbolAddress((void**)&k,  g_k);
    cudaGetSymbolAddress((void**)&v,  g_v);
    cudaGetSymbolAddress((void**)&o,  g_o);
    cudaGetSymbolAddress((void**)&hbuf, g_h);
    cudaGetSymbolAddress((void**)&S,  g_S);
    cudaGetSymbolAddress((void**)&m1, g_m1);
    cudaGetSymbolAddress((void**)&m2, g_m2);
    cudaGetSymbolAddress((void**)&xh, g_xh);
    cudaGetSymbolAddress((void**)&oh, g_oh);
    cudaGetSymbolAddress((void**)&m1h, g_m1h);
    cudaGetSymbolAddress((void**)&bt, g_bt);

    const int cvblocks = BB * TT / 4;
    rope_table_kernel<<<(TT * 64 + 255) / 256, 256>>>();
    rmsnorm_kernel<<<BT, 256>>>(hs, ln1, xh, RMS_EPS);

    dim3 tD(DD / 32, DD / 32), tI1(II / 32, DD / 32), tI2(DD / 32, II / 32), tb(32, 8);
    dim3 gD(DD / 128, BT / 256), gI(II / 128, BT / 256);

    convT_kernel<<<tD, tb>>>(wq, bt, DD, DD);
    hgemm_kernel<<<gD, 256, SMEM_GEMM>>>(xh, bt, nullptr, t0, BT, DD, DD);
    conv_silu_kernel<<<cvblocks, 256>>>(t0, cq, q);
    convT_kernel<<<tD, tb>>>(wk, bt, DD, DD);
    hgemm_kernel<<<gD, 256, SMEM_GEMM>>>(xh, bt, nullptr, t1, BT, DD, DD);
    conv_silu_kernel<<<cvblocks, 256>>>(t1, ck, k);
    convT_kernel<<<tD, tb>>>(wv, bt, DD, DD);
    hgemm_kernel<<<gD, 256, SMEM_GEMM>>>(xh, bt, nullptr, t2, BT, DD, DD);
    conv_silu_kernel<<<cvblocks, 256>>>(t2, cv, v);

    const int rw = (int)(((size_t)BB * TT * HH * 64 + 255) / 256);
    rope_kernel<<<rw, 256>>>(q);
    rope_kernel<<<rw, 256>>>(k);

    dim3 gc(NC, HH, BB);
    ret_phase1<<<gc, 256, 2 * 64 * 129 * 4>>>(k, v, S);
    ret_scan<<<BB * HH * 64, 256>>>(S);
    ret_phase3<<<gc, 256, (3 * 64 * 129 + 128 * 129 + 64 * 65) * 4>>>(q, k, v, S, o);

    convT_kernel<<<tD, tb>>>(wg, bt, DD, DD);
    hgemm_kernel<<<gD, 256, SMEM_GEMM>>>(xh, bt, nullptr, t0, BT, DD, DD);
    gate_kernel<<<(BT * HH) / 8, 256>>>(o, t0, gn, oh);
    convT_kernel<<<tD, tb>>>(wo, bt, DD, DD);
    hgemm_kernel<<<gD, 256, SMEM_GEMM>>>(oh, bt, hs, hbuf, BT, DD, DD);

    rmsnorm_kernel<<<BT, 256>>>(hbuf, ln2, xh, RMS_EPS);
    convT_kernel<<<tI1, tb>>>(wgate, bt, DD, II);
    hgemm_kernel<<<gI, 256, SMEM_GEMM>>>(xh, bt, nullptr, m1, BT, II, DD);
    convT_kernel<<<tI1, tb>>>(wup, bt, DD, II);
    hgemm_kernel<<<gI, 256, SMEM_GEMM>>>(xh, bt, nullptr, m2, BT, II, DD);
    size_t nmid4 = (size_t)BT * II / 4;
    swiglu_kernel<<<(int)((nmid4 + 255) / 256), 256>>>(m1, m2, m1h, nmid4);
    convT_kernel<<<tI2, tb>>>(wdown, bt, II, DD);
    hgemm_kernel<<<gD, 256, SMEM_GEMM>>>(m1h, bt, hbuf, out, BT, DD, II);
}

// round 6
// speedup vs baseline: 4.2999x; 1.0142x over previous
#include <cuda_runtime.h>
#include <cuda_fp16.h>
#include <math.h>
#include <stdint.h>

#define BB 4
#define TT 8192
#define DD 1024
#define HH 8
#define II 2816
#define NC 128
#define BT (BB*TT)

#define RMS_EPS 1e-6f
#define GATE_EPS 1e-5f

// ---------------- scratch ----------------
__device__ float  g_t0[(size_t)BT*DD];
__device__ float  g_t1[(size_t)BT*DD];
__device__ float  g_t2[(size_t)BT*DD];
__device__ float  g_q [(size_t)BT*DD];
__device__ float  g_k [(size_t)BT*DD];
__device__ float  g_v [(size_t)BT*DD];
__device__ float  g_o [(size_t)BT*DD];
__device__ float  g_h [(size_t)BT*DD];
__device__ float  g_S [(size_t)BB*HH*NC*128*128];
__device__ float  g_m1[(size_t)BT*II];
__device__ float  g_m2[(size_t)BT*II];
__device__ __half g_xh [(size_t)BT*DD];
__device__ __half g_oh [(size_t)BT*DD];
__device__ __half g_m1h[(size_t)BT*II];
__device__ __half g_bt [(size_t)DD*II];
__device__ float  g_cos[TT*64];
__device__ float  g_sin[TT*64];

// ---------------- rmsnorm -> fp16 out ----------------
__global__ void rmsnorm_kernel(const float* __restrict__ x, const float* __restrict__ w,
                               __half* __restrict__ out, float eps) {
    int row = blockIdx.x;
    const float4* xr = (const float4*)(x + (size_t)row * DD);
    float4 v = xr[threadIdx.x];
    float s = v.x * v.x + v.y * v.y + v.z * v.z + v.w * v.w;
    __shared__ float red[8];
    #pragma unroll
    for (int o = 16; o > 0; o >>= 1) s += __shfl_down_sync(0xffffffffu, s, o);
    if ((threadIdx.x & 31) == 0) red[threadIdx.x >> 5] = s;
    __syncthreads();
    if (threadIdx.x < 8) {
        s = red[threadIdx.x];
        #pragma unroll
        for (int o = 4; o > 0; o >>= 1) s += __shfl_down_sync(0xffu, s, o);
        if (threadIdx.x == 0) red[0] = s;
    }
    __syncthreads();
    float inv = rsqrtf(red[0] / (float)DD + eps);
    float4 wv = ((const float4*)w)[threadIdx.x];
    __half2* orow = (__half2*)(out + (size_t)row * DD);
    orow[threadIdx.x * 2]     = __floats2half2_rn(v.x * inv * wv.x, v.y * inv * wv.y);
    orow[threadIdx.x * 2 + 1] = __floats2half2_rn(v.z * inv * wv.z, v.w * inv * wv.w);
}

// ---------------- weight convert + transpose: W[K][N] fp32 -> Wt[N][K] fp16 ----------------
__global__ void convT_kernel(const float* __restrict__ W, __half* __restrict__ Wt,
                             int K, int N) {
    __shared__ float tile[32][33];
    int n0 = blockIdx.x * 32, k0 = blockIdx.y * 32;
    #pragma unroll
    for (int j = threadIdx.y; j < 32; j += 8)
        tile[j][threadIdx.x] = W[(size_t)(k0 + j) * N + n0 + threadIdx.x];
    __syncthreads();
    #pragma unroll
    for (int j = threadIdx.y; j < 32; j += 8)
        Wt[(size_t)(n0 + j) * K + k0 + threadIdx.x] = __float2half_rn(tile[threadIdx.x][j]);
}

// ================= fp16 tensor-core GEMM (HMMA + ldmatrix) =================
// C = A @ B (+R), A: MxK fp16 row-major, Bt: NxK fp16 row-major (B transposed).
// 256x128 CTA tile, BK=32, 3-stage cp.async, 8 warps of 64x64, mma.m16n8k16.
#define BKH 32
#define XW 20                      // uint32 words per smem row (40 fp16: conflict-free)
#define AW (256*XW)
#define BW (128*XW)
#define SMEM_GEMM ((3*AW + 3*BW) * 4)

__device__ __forceinline__ void mma_fp16(float* c, const uint32_t* a, const uint32_t* b) {
    asm volatile("mma.sync.aligned.m16n8k16.row.col.f32.f16.f16.f32 "
        "{%0,%1,%2,%3}, {%4,%5,%6,%7}, {%8,%9}, {%0,%1,%2,%3};"
        : "+f"(c[0]), "+f"(c[1]), "+f"(c[2]), "+f"(c[3])
        : "r"(a[0]), "r"(a[1]), "r"(a[2]), "r"(a[3]), "r"(b[0]), "r"(b[1]));
}
__device__ __forceinline__ void cpasync16(uint32_t s, const void* g) {
    asm volatile("cp.async.cg.shared.global [%0], [%1], 16;" :: "r"(s), "l"(g));
}
__device__ __forceinline__ void ldsm_x4(uint32_t* r, uint32_t addr) {
    asm volatile("ldmatrix.sync.aligned.m8n8.x4.shared.b16 {%0,%1,%2,%3}, [%4];"
        : "=r"(r[0]), "=r"(r[1]), "=r"(r[2]), "=r"(r[3]) : "r"(addr));
}

__global__ __launch_bounds__(256, 1)
void hgemm_kernel(const __half* __restrict__ A, const __half* __restrict__ Bt,
                  const float* __restrict__ R, float* __restrict__ C,
                  int M, int N, int K) {
    extern __shared__ uint32_t smw[];

    const int tid = threadIdx.x;
    const int lane = tid & 31;
    const int w = tid >> 5;
    const int g = lane >> 2, q = lane & 3;
    const int wm = (w & 3) * 64;
    const int wn = (w >> 2) * 64;
    const int bm = blockIdx.y * 256, bn = blockIdx.x * 128;

    uint32_t sBase = (uint32_t)__cvta_generic_to_shared(smw);

    // per-lane ldmatrix row offsets (in words)
    // A x4: lanes 0-7 rows 0-7 k0-7 | 8-15 rows 8-15 k0-7 | 16-23 rows 0-7 k8-15 | 24-31 rows 8-15 k8-15
    const uint32_t aLane = (uint32_t)((wm + (lane & 15)) * XW + ((lane >> 4) << 2));
    // B x4: lanes 0-7 n0-7 k0-7 | 8-15 n0-7 k8-15 | 16-23 n8-15 k0-7 | 24-31 n8-15 k8-15
    const uint32_t bLane = (uint32_t)((wn + (lane & 7) + ((lane >> 4) << 3)) * XW + (((lane >> 3) & 1) << 2));

    float acc[4][8][4];
    #pragma unroll
    for (int i = 0; i < 4; ++i)
        #pragma unroll
        for (int j = 0; j < 8; ++j)
            #pragma unroll
            for (int r = 0; r < 4; ++r) acc[i][j][r] = 0.f;

    const int ntile = K / BKH;

    auto loadTile = [&](int t, int s) {
        #pragma unroll
        for (int i = 0; i < 4; ++i) {
            int idx = i * 256 + tid;
            int row = idx >> 2, kc = (idx & 3) * 8;
            cpasync16(sBase + (uint32_t)((s * AW + row * XW) * 4 + kc * 2),
                      A + (size_t)(bm + row) * K + t * BKH + kc);
        }
        #pragma unroll
        for (int i = 0; i < 2; ++i) {
            int idx = i * 256 + tid;
            int n = idx >> 2, kc = (idx & 3) * 8;
            cpasync16(sBase + (uint32_t)((3 * AW + s * BW + n * XW) * 4 + kc * 2),
                      Bt + (size_t)(bn + n) * K + t * BKH + kc);
        }
        asm volatile("cp.async.commit_group;");
    };

    loadTile(0, 0);
    loadTile(1, 1);

    for (int t = 0; t < ntile; ++t) {
        int s = t % 3;
        if (t + 2 < ntile) asm volatile("cp.async.wait_group 1;");
        else               asm volatile("cp.async.wait_group 0;");
        __syncthreads();
        if (t + 2 < ntile) loadTile(t + 2, (t + 2) % 3);

        const uint32_t aOff = sBase + (uint32_t)(s * AW) * 4;
        const uint32_t bOff = sBase + (uint32_t)(3 * AW + s * BW) * 4;
        #pragma unroll
        for (int ks = 0; ks < 2; ++ks) {
            uint32_t a[4][4], b[8][2];
            #pragma unroll
            for (int mt = 0; mt < 4; ++mt)
                ldsm_x4(a[mt], aOff + (aLane + (uint32_t)(mt * 16 * XW + ks * 8)) * 4);
            #pragma unroll
            for (int np = 0; np < 4; ++np) {
                uint32_t bb[4];
                ldsm_x4(bb, bOff + (bLane + (uint32_t)(np * 16 * XW + ks * 8)) * 4);
                b[np * 2][0]     = bb[0];
                b[np * 2][1]     = bb[1];
                b[np * 2 + 1][0] = bb[2];
                b[np * 2 + 1][1] = bb[3];
            }
            #pragma unroll
            for (int mt = 0; mt < 4; ++mt)
                #pragma unroll
                for (int nt = 0; nt < 8; ++nt)
                    mma_fp16(acc[mt][nt], a[mt], b[nt]);
        }
    }

    #pragma unroll
    for (int mt = 0; mt < 4; ++mt) {
        #pragma unroll
        for (int half = 0; half < 2; ++half) {
            int row = bm + wm + mt * 16 + g + half * 8;
            size_t rbase = (size_t)row * N + bn + wn;
            #pragma unroll
            for (int nt = 0; nt < 8; ++nt) {
                int col = nt * 8 + q * 2;
                float2 v;
                v.x = acc[mt][nt][half * 2 + 0];
                v.y = acc[mt][nt][half * 2 + 1];
                if (R) {
                    const float2 rr = *(const float2*)(R + rbase + col);
                    v.x += rr.x; v.y += rr.y;
                }
                *(float2*)(C + rbase + col) = v;
            }
        }
    }
}

// ---------------- causal short conv (K=4) + silu, 4 timesteps/thread ----------------
__global__ void conv_silu_kernel(const float* __restrict__ x, const float* __restrict__ w,
                                 float* __restrict__ y) {
    int idx = blockIdx.x * 256 + threadIdx.x;
    int d4 = idx & 255;
    int rest = idx >> 8;
    int t4 = rest & (TT / 4 - 1);
    int b = rest >> 11;
    const float4* x4 = (const float4*)x;
    const float4* w4 = (const float4*)w;
    float4 wr0 = w4[d4 * 4 + 0], wr1 = w4[d4 * 4 + 1];
    float4 wr2 = w4[d4 * 4 + 2], wr3 = w4[d4 * 4 + 3];
    int t0 = t4 * 4;
    size_t rowbase = (size_t)b * TT * 256 + d4;
    float4 xv[7];
    #pragma unroll
    for (int j = 0; j < 7; ++j) {
        int tt = t0 - 3 + j;
        xv[j] = (tt >= 0) ? x4[rowbase + (size_t)tt * 256] : make_float4(0.f, 0.f, 0.f, 0.f);
    }
    #pragma unroll
    for (int i = 0; i < 4; ++i) {
        float4 a;
        a.x = xv[i].x * wr0.x + xv[i+1].x * wr0.y + xv[i+2].x * wr0.z + xv[i+3].x * wr0.w;
        a.y = xv[i].y * wr1.x + xv[i+1].y * wr1.y + xv[i+2].y * wr1.z + xv[i+3].y * wr1.w;
        a.z = xv[i].z * wr2.x + xv[i+1].z * wr2.y + xv[i+2].z * wr2.z + xv[i+3].z * wr2.w;
        a.w = xv[i].w * wr3.x + xv[i+1].w * wr3.y + xv[i+2].w * wr3.z + xv[i+3].w * wr3.w;
        a.x = a.x / (1.f + expf(-a.x));
        a.y = a.y / (1.f + expf(-a.y));
        a.z = a.z / (1.f + expf(-a.z));
        a.w = a.w / (1.f + expf(-a.w));
        ((float4*)y)[rowbase + (size_t)(t0 + i) * 256] = a;
    }
}

// ---------------- RoPE table ----------------
__global__ void rope_table_kernel() {
    int idx = blockIdx.x * 256 + threadIdx.x;
    if (idx >= TT * 64) return;
    int t = idx >> 6, j = idx & 63;
    float invf = (float)(1.0 / pow(10000.0, (double)j / 64.0));
    float f = (float)t * invf;
    g_cos[idx] = (float)cos((double)f);
    g_sin[idx] = (float)sin((double)f);
}

// ---------------- RoPE apply ----------------
__global__ void rope_kernel(float* __restrict__ x) {
    size_t idx = (size_t)blockIdx.x * 256 + threadIdx.x;
    if (idx >= (size_t)BB * TT * HH * 64) return;
    int j = (int)(idx & 63);
    int h = (int)((idx >> 6) & 7);
    size_t bt = idx >> 9;
    int t = (int)(bt % TT);
    float c = g_cos[t * 64 + j], s = g_sin[t * 64 + j];
    size_t base = bt * DD + h * 128;
    float x1 = x[base + j], x2 = x[base + 64 + j];
    x[base + j]      = x1 * c - x2 * s;
    x[base + 64 + j] = x1 * s + x2 * c;
}

// ---------------- retention phase 1 ----------------
__global__ void ret_phase1(const float* __restrict__ k, const float* __restrict__ v,
                           float* __restrict__ S) {
    extern __shared__ float sm[];
    float* ks = sm;
    float* vs = sm + 64 * 129;
    int c = blockIdx.x, h = blockIdx.y, b = blockIdx.z;
    float gamma = 1.f - exp2f(-5.f - (float)h);
    float lg = logf(gamma);
    int tid = threadIdx.x;
    for (int x = tid; x < 8192; x += 256) {
        int i = x >> 7, d = x & 127;
        size_t gg = ((size_t)b * TT + c * 64 + i) * DD + h * 128 + d;
        ks[i * 129 + d] = k[gg] * expf(lg * (float)(63 - i));
        vs[i * 129 + d] = v[gg];
    }
    __syncthreads();
    int w = tid >> 5, lane = tid & 31;
    int d0 = w * 16 + (lane >> 3) * 4;
    int e0 = (lane & 7) * 16;
    float acc[4][16];
    #pragma unroll
    for (int i = 0; i < 4; ++i)
        #pragma unroll
        for (int j = 0; j < 16; ++j) acc[i][j] = 0.f;
    #pragma unroll 4
    for (int j = 0; j < 64; ++j) {
        float kr[4], vr[16];
        #pragma unroll
        for (int i = 0; i < 4; ++i) kr[i] = ks[j * 129 + d0 + i];
        #pragma unroll
        for (int e = 0; e < 16; ++e) vr[e] = vs[j * 129 + e0 + e];
        #pragma unroll
        for (int i = 0; i < 4; ++i)
            #pragma unroll
            for (int e = 0; e < 16; ++e) acc[i][e] = fmaf(kr[i], vr[e], acc[i][e]);
    }
    size_t sb = (((size_t)(b * HH + h)) * NC + c) * 16384;
    #pragma unroll
    for (int i = 0; i < 4; ++i)
        #pragma unroll
        for (int e = 0; e < 16; ++e)
            S[sb + (d0 + i) * 128 + e0 + e] = acc[i][e];
}

// ---------------- retention phase 2: parallel exclusive scan ----------------
__global__ void ret_scan(float* __restrict__ S) {
    int bh = blockIdx.x >> 6;
    int elem = ((blockIdx.x & 63) << 8) + threadIdx.x;
    int h = bh & 7;
    float gamma = 1.f - exp2f(-5.f - (float)h);
    float cdec = expf(logf(gamma) * 64.f);
    float carry = 0.f;
    size_t base = (size_t)bh * NC * 16384 + elem;
    for (int c = 0; c < NC; ++c) {
        size_t idx = base + (size_t)c * 16384;
        float loc = S[idx];
        S[idx] = carry;
        carry = carry * cdec + loc;
    }
}

// ---------------- retention phase 3 ----------------
__global__ void ret_phase3(const float* __restrict__ q, const float* __restrict__ k,
                           const float* __restrict__ v, const float* __restrict__ S,
                           float* __restrict__ o) {
    extern __shared__ float sm[];
    float* qs  = sm;
    float* ks  = qs + 64 * 129;
    float* vs  = ks + 64 * 129;
    float* Ps  = vs + 64 * 129;
    float* att = Ps + 128 * 129;
    int c = blockIdx.x, h = blockIdx.y, b = blockIdx.z;
    float gamma = 1.f - exp2f(-5.f - (float)h);
    float lg = logf(gamma);
    const float scale = 0.08838834764831845f;
    int tid = threadIdx.x;
    int lane = tid & 31;
    for (int x = tid; x < 8192; x += 256) {
        int i = x >> 7, d = x & 127;
        size_t gg = ((size_t)b * TT + c * 64 + i) * DD + h * 128 + d;
        qs[i * 129 + d] = q[gg] * scale;
        ks[i * 129 + d] = k[gg];
        vs[i * 129 + d] = v[gg];
    }
    size_t sb = (((size_t)(b * HH + h)) * NC + c) * 16384;
    for (int x = tid; x < 16384; x += 256) {
        int d = x >> 7, e = x & 127;
        Ps[d * 129 + e] = S[sb + x];
    }
    __syncthreads();
    {
        int i0 = (tid >> 4) * 4;
        int j0 = (tid & 15) * 4;
        float a4[4][4];
        #pragma unroll
        for (int i = 0; i < 4; ++i)
            #pragma unroll
            for (int j = 0; j < 4; ++j) a4[i][j] = 0.f;
        #pragma unroll 4
        for (int d = 0; d < 128; ++d) {
            float qr[4], kr[4];
            #pragma unroll
            for (int i = 0; i < 4; ++i) qr[i] = qs[(i0 + i) * 129 + d];
            #pragma unroll
            for (int j = 0; j < 4; ++j) kr[j] = ks[(j0 + j) * 129 + d];
            #pragma unroll
            for (int i = 0; i < 4; ++i)
                #pragma unroll
                for (int j = 0; j < 4; ++j) a4[i][j] = fmaf(qr[i], kr[j], a4[i][j]);
        }
        #pragma unroll
        for (int i = 0; i < 4; ++i)
            #pragma unroll
            for (int j = 0; j < 4; ++j) {
                int ia = i0 + i, ja = j0 + j;
                float f = (ia >= ja) ? expf(lg * (float)(ia - ja)) : 0.f;
                att[ia * 65 + ja] = a4[i][j] * f;
            }
    }
    __syncthreads();
    {
        int i0 = (tid >> 5) * 8 + (lane >> 4) * 4;
        int e0 = (lane & 15) * 8;
        float accA[4][8], accB[4][8];
        #pragma unroll
        for (int i = 0; i < 4; ++i)
            #pragma unroll
            for (int e = 0; e < 8; ++e) { accA[i][e] = 0.f; accB[i][e] = 0.f; }
        #pragma unroll 4
        for (int j = 0; j < 64; ++j) {
            float ar[4], vr[8];
            #pragma unroll
            for (int i = 0; i < 4; ++i) ar[i] = att[(i0 + i) * 65 + j];
            #pragma unroll
            for (int e = 0; e < 8; ++e) vr[e] = vs[j * 129 + e0 + e];
            #pragma unroll
            for (int i = 0; i < 4; ++i)
                #pragma unroll
                for (int e = 0; e < 8; ++e) accA[i][e] = fmaf(ar[i], vr[e], accA[i][e]);
        }
        #pragma unroll 4
        for (int d = 0; d < 128; ++d) {
            float qr[4], pr[8];
            #pragma unroll
            for (int i = 0; i < 4; ++i) qr[i] = qs[(i0 + i) * 129 + d];
            #pragma unroll
            for (int e = 0; e < 8; ++e) pr[e] = Ps[d * 129 + e0 + e];
            #pragma unroll
            for (int i = 0; i < 4; ++i)
                #pragma unroll
                for (int e = 0; e < 8; ++e) accB[i][e] = fmaf(qr[i], pr[e], accB[i][e]);
        }
        #pragma unroll
        for (int i = 0; i < 4; ++i) {
            float crossf = expf(lg * (float)(i0 + i + 1));
            size_t ob = ((size_t)b * TT + c * 64 + i0 + i) * DD + h * 128 + e0;
            #pragma unroll
            for (int e = 0; e < 8; ++e)
                o[ob + e] = accA[i][e] + crossf * accB[i][e];
        }
    }
}

// ---------------- gating -> fp16 out ----------------
__global__ void gate_kernel(const float* __restrict__ o, const float* __restrict__ g,
                            const float* __restrict__ w, __half* __restrict__ oh) {
    int row = blockIdx.x * 8 + (threadIdx.x >> 5);
    int lane = threadIdx.x & 31;
    const float4* orow = (const float4*)(o + (size_t)row * 128);
    const float4* grow = (const float4*)(g + (size_t)row * 128);
    float4 v = orow[lane];
    float s = v.x * v.x + v.y * v.y + v.z * v.z + v.w * v.w;
    #pragma unroll
    for (int off = 16; off > 0; off >>= 1) s += __shfl_xor_sync(0xffffffffu, s, off);
    float inv = rsqrtf(s / 128.f + GATE_EPS);
    float4 gv = grow[lane];
    float4 wv = ((const float4*)w)[lane];
    float rx = v.x * inv * wv.x * (gv.x / (1.f + expf(-gv.x)));
    float ry = v.y * inv * wv.y * (gv.y / (1.f + expf(-gv.y)));
    float rz = v.z * inv * wv.z * (gv.z / (1.f + expf(-gv.z)));
    float rw = v.w * inv * wv.w * (gv.w / (1.f + expf(-gv.w)));
    __half2* dst = (__half2*)(oh + (size_t)row * 128);
    dst[lane * 2]     = __floats2half2_rn(rx, ry);
    dst[lane * 2 + 1] = __floats2half2_rn(rz, rw);
}

// ---------------- swiglu -> fp16 out ----------------
__global__ void swiglu_kernel(const float* __restrict__ a, const float* __restrict__ b2,
                              __half* __restrict__ outh, size_t n4) {
    size_t idx = (size_t)blockIdx.x * 256 + threadIdx.x;
    if (idx >= n4) return;
    float4 x = ((const float4*)a)[idx];
    float4 y = ((const float4*)b2)[idx];
    float rx = (x.x / (1.f + expf(-x.x))) * y.x;
    float ry = (x.y / (1.f + expf(-x.y))) * y.y;
    float rz = (x.z / (1.f + expf(-x.z))) * y.z;
    float rw = (x.w / (1.f + expf(-x.w))) * y.w;
    __half2* dst = (__half2*)outh;
    dst[idx * 2]     = __floats2half2_rn(rx, ry);
    dst[idx * 2 + 1] = __floats2half2_rn(rz, rw);
}

// ---------------- launch ----------------
extern "C" void kernel_launch(void* const* d_in, const int* in_sizes, int n_in,
                              void* d_out, int out_size) {
    const float* hs    = (const float*)d_in[0];
    const float* ln1   = (const float*)d_in[1];
    const float* ln2   = (const float*)d_in[2];
    const float* wq    = (const float*)d_in[3];
    const float* wk    = (const float*)d_in[4];
    const float* wv    = (const float*)d_in[5];
    const float* wg    = (const float*)d_in[6];
    const float* wo    = (const float*)d_in[7];
    const float* cq    = (const float*)d_in[8];
    const float* ck    = (const float*)d_in[9];
    const float* cv    = (const float*)d_in[10];
    const float* gn    = (const float*)d_in[11];
    const float* wgate = (const float*)d_in[12];
    const float* wup   = (const float*)d_in[13];
    const float* wdown = (const float*)d_in[14];
    float* out = (float*)d_out;

    cudaFuncSetAttribute(hgemm_kernel, cudaFuncAttributeMaxDynamicSharedMemorySize, SMEM_GEMM);
    cudaFuncSetAttribute(ret_phase1, cudaFuncAttributeMaxDynamicSharedMemorySize, 2 * 64 * 129 * 4);
    cudaFuncSetAttribute(ret_phase3, cudaFuncAttributeMaxDynamicSharedMemorySize,
                         (3 * 64 * 129 + 128 * 129 + 64 * 65) * 4);

    float *t0, *t1, *t2, *q, *k, *v, *o, *hbuf, *S, *m1, *m2;
    __half *xh, *oh, *m1h, *bt;
    cudaGetSymbolAddress((void**)&t0, g_t0);
    cudaGetSymbolAddress((void**)&t1, g_t1);
    cudaGetSymbolAddress((void**)&t2, g_t2);
    cudaGetSymbolAddress((void**)&q,  g_q);
    cudaGetSymbolAddress((void**)&k,  g_k);
    cudaGetSymbolAddress((void**)&v,  g_v);
    cudaGetSymbolAddress((void**)&o,  g_o);
    cudaGetSymbolAddress((void**)&hbuf, g_h);
    cudaGetSymbolAddress((void**)&S,  g_S);
    cudaGetSymbolAddress((void**)&m1, g_m1);
    cudaGetSymbolAddress((void**)&m2, g_m2);
    cudaGetSymbolAddress((void**)&xh, g_xh);
    cudaGetSymbolAddress((void**)&oh, g_oh);
    cudaGetSymbolAddress((void**)&m1h, g_m1h);
    cudaGetSymbolAddress((void**)&bt, g_bt);

    const int cvblocks = BB * TT / 4;
    rope_table_kernel<<<(TT * 64 + 255) / 256, 256>>>();
    rmsnorm_kernel<<<BT, 256>>>(hs, ln1, xh, RMS_EPS);

    dim3 tD(DD / 32, DD / 32), tI1(II / 32, DD / 32), tI2(DD / 32, II / 32), tb(32, 8);
    dim3 gD(DD / 128, BT / 256), gI(II / 128, BT / 256);

    convT_kernel<<<tD, tb>>>(wq, bt, DD, DD);
    hgemm_kernel<<<gD, 256, SMEM_GEMM>>>(xh, bt, nullptr, t0, BT, DD, DD);
    conv_silu_kernel<<<cvblocks, 256>>>(t0, cq, q);
    convT_kernel<<<tD, tb>>>(wk, bt, DD, DD);
    hgemm_kernel<<<gD, 256, SMEM_GEMM>>>(xh, bt, nullptr, t1, BT, DD, DD);
    conv_silu_kernel<<<cvblocks, 256>>>(t1, ck, k);
    convT_kernel<<<tD, tb>>>(wv, bt, DD, DD);
    hgemm_kernel<<<gD, 256, SMEM_GEMM>>>(xh, bt, nullptr, t2, BT, DD, DD);
    conv_silu_kernel<<<cvblocks, 256>>>(t2, cv, v);

    const int rw = (int)(((size_t)BB * TT * HH * 64 + 255) / 256);
    rope_kernel<<<rw, 256>>>(q);
    rope_kernel<<<rw, 256>>>(k);

    dim3 gc(NC, HH, BB);
    ret_phase1<<<gc, 256, 2 * 64 * 129 * 4>>>(k, v, S);
    ret_scan<<<BB * HH * 64, 256>>>(S);
    ret_phase3<<<gc, 256, (3 * 64 * 129 + 128 * 129 + 64 * 65) * 4>>>(q, k, v, S, o);

    convT_kernel<<<tD, tb>>>(wg, bt, DD, DD);
    hgemm_kernel<<<gD, 256, SMEM_GEMM>>>(xh, bt, nullptr, t0, BT, DD, DD);
    gate_kernel<<<(BT * HH) / 8, 256>>>(o, t0, gn, oh);
    convT_kernel<<<tD, tb>>>(wo, bt, DD, DD);
    hgemm_kernel<<<gD, 256, SMEM_GEMM>>>(oh, bt, hs, hbuf, BT, DD, DD);

    rmsnorm_kernel<<<BT, 256>>>(hbuf, ln2, xh, RMS_EPS);
    convT_kernel<<<tI1, tb>>>(wgate, bt, DD, II);
    hgemm_kernel<<<gI, 256, SMEM_GEMM>>>(xh, bt, nullptr, m1, BT, II, DD);
    convT_kernel<<<tI1, tb>>>(wup, bt, DD, II);
    hgemm_kernel<<<gI, 256, SMEM_GEMM>>>(xh, bt, nullptr, m2, BT, II, DD);
    size_t nmid4 = (size_t)BT * II / 4;
    swiglu_kernel<<<(int)((nmid4 + 255) / 256), 256>>>(m1, m2, m1h, nmid4);
    convT_kernel<<<tI2, tb>>>(wdown, bt, II, DD);
    hgemm_kernel<<<gD, 256, SMEM_GEMM>>>(m1h, bt, hbuf, out, BT, DD, II);
}

// round 7
// speedup vs baseline: 4.7526x; 1.1053x over previous
#include <cuda_runtime.h>
#include <cuda_fp16.h>
#include <math.h>
#include <stdint.h>

#define BB 4
#define TT 8192
#define DD 1024
#define HH 8
#define II 2816
#define NC 128
#define BT (BB*TT)

#define RMS_EPS 1e-6f
#define GATE_EPS 1e-5f

// ---------------- scratch ----------------
__device__ float  g_t0[(size_t)BT*DD];
__device__ float  g_t1[(size_t)BT*DD];
__device__ float  g_t2[(size_t)BT*DD];
__device__ float  g_q [(size_t)BT*DD];
__device__ float  g_k [(size_t)BT*DD];
__device__ float  g_v [(size_t)BT*DD];
__device__ float  g_o [(size_t)BT*DD];
__device__ float  g_h [(size_t)BT*DD];
__device__ float  g_S [(size_t)BB*HH*NC*128*128];
__device__ float  g_m1[(size_t)BT*II];
__device__ float  g_m2[(size_t)BT*II];
__device__ __half g_xh [(size_t)BT*DD];
__device__ __half g_oh [(size_t)BT*DD];
__device__ __half g_m1h[(size_t)BT*II];
__device__ __half g_bt [(size_t)DD*II];
__device__ float  g_cos[TT*64];
__device__ float  g_sin[TT*64];

// ---------------- rmsnorm -> fp16 out ----------------
__global__ void rmsnorm_kernel(const float* __restrict__ x, const float* __restrict__ w,
                               __half* __restrict__ out, float eps) {
    int row = blockIdx.x;
    const float4* xr = (const float4*)(x + (size_t)row * DD);
    float4 v = xr[threadIdx.x];
    float s = v.x * v.x + v.y * v.y + v.z * v.z + v.w * v.w;
    __shared__ float red[8];
    #pragma unroll
    for (int o = 16; o > 0; o >>= 1) s += __shfl_down_sync(0xffffffffu, s, o);
    if ((threadIdx.x & 31) == 0) red[threadIdx.x >> 5] = s;
    __syncthreads();
    if (threadIdx.x < 8) {
        s = red[threadIdx.x];
        #pragma unroll
        for (int o = 4; o > 0; o >>= 1) s += __shfl_down_sync(0xffu, s, o);
        if (threadIdx.x == 0) red[0] = s;
    }
    __syncthreads();
    float inv = rsqrtf(red[0] / (float)DD + eps);
    float4 wv = ((const float4*)w)[threadIdx.x];
    __half2* orow = (__half2*)(out + (size_t)row * DD);
    orow[threadIdx.x * 2]     = __floats2half2_rn(v.x * inv * wv.x, v.y * inv * wv.y);
    orow[threadIdx.x * 2 + 1] = __floats2half2_rn(v.z * inv * wv.z, v.w * inv * wv.w);
}

// ---------------- weight convert + transpose: W[K][N] fp32 -> Wt[N][K] fp16 ----------------
__global__ void convT_kernel(const float* __restrict__ W, __half* __restrict__ Wt,
                             int K, int N) {
    __shared__ float tile[32][33];
    int n0 = blockIdx.x * 32, k0 = blockIdx.y * 32;
    #pragma unroll
    for (int j = threadIdx.y; j < 32; j += 8)
        tile[j][threadIdx.x] = W[(size_t)(k0 + j) * N + n0 + threadIdx.x];
    __syncthreads();
    #pragma unroll
    for (int j = threadIdx.y; j < 32; j += 8)
        Wt[(size_t)(n0 + j) * K + k0 + threadIdx.x] = __float2half_rn(tile[threadIdx.x][j]);
}

// ================= fp16 tensor-core GEMM (HMMA + ldmatrix, 2 CTA/SM) =================
// C = A @ B (+R), A: MxK fp16 row-major, Bt: NxK fp16 row-major.
// 128x128 CTA tile, BK=32, 3-stage cp.async, 8 warps (2M x 4N) of 64x32.
#define BKH 32
#define XW 20                      // uint32 words per smem row (40 fp16: conflict-free)
#define AW (128*XW)
#define BW (128*XW)
#define SMEM_GEMM ((3*AW + 3*BW) * 4)

__device__ __forceinline__ void mma_fp16(float* c, const uint32_t* a, const uint32_t* b) {
    asm volatile("mma.sync.aligned.m16n8k16.row.col.f32.f16.f16.f32 "
        "{%0,%1,%2,%3}, {%4,%5,%6,%7}, {%8,%9}, {%0,%1,%2,%3};"
        : "+f"(c[0]), "+f"(c[1]), "+f"(c[2]), "+f"(c[3])
        : "r"(a[0]), "r"(a[1]), "r"(a[2]), "r"(a[3]), "r"(b[0]), "r"(b[1]));
}
__device__ __forceinline__ void cpasync16(uint32_t s, const void* g) {
    asm volatile("cp.async.cg.shared.global [%0], [%1], 16;" :: "r"(s), "l"(g));
}
__device__ __forceinline__ void ldsm_x4(uint32_t* r, uint32_t addr) {
    asm volatile("ldmatrix.sync.aligned.m8n8.x4.shared.b16 {%0,%1,%2,%3}, [%4];"
        : "=r"(r[0]), "=r"(r[1]), "=r"(r[2]), "=r"(r[3]) : "r"(addr));
}

__global__ __launch_bounds__(256, 2)
void hgemm_kernel(const __half* __restrict__ A, const __half* __restrict__ Bt,
                  const float* __restrict__ R, float* __restrict__ C,
                  int M, int N, int K) {
    extern __shared__ uint32_t smw[];

    const int tid = threadIdx.x;
    const int lane = tid & 31;
    const int w = tid >> 5;
    const int g = lane >> 2, q = lane & 3;
    const int wm = (w & 1) * 64;
    const int wn = (w >> 1) * 32;
    const int bm = blockIdx.y * 128, bn = blockIdx.x * 128;

    uint32_t sBase = (uint32_t)__cvta_generic_to_shared(smw);

    // A x4: lanes 0-7 rows 0-7 k0-7 | 8-15 rows 8-15 k0-7 | 16-23 rows 0-7 k8-15 | 24-31 rows 8-15 k8-15
    const uint32_t aLane = (uint32_t)((wm + (lane & 15)) * XW + ((lane >> 4) << 2));
    // B x4: lanes 0-7 n0-7 k0-7 | 8-15 n0-7 k8-15 | 16-23 n8-15 k0-7 | 24-31 n8-15 k8-15
    const uint32_t bLane = (uint32_t)((wn + (lane & 7) + ((lane >> 4) << 3)) * XW + (((lane >> 3) & 1) << 2));

    float acc[4][4][4];
    #pragma unroll
    for (int i = 0; i < 4; ++i)
        #pragma unroll
        for (int j = 0; j < 4; ++j)
            #pragma unroll
            for (int r = 0; r < 4; ++r) acc[i][j][r] = 0.f;

    const int ntile = K / BKH;

    auto loadTile = [&](int t, int s) {
        #pragma unroll
        for (int i = 0; i < 2; ++i) {
            int idx = i * 256 + tid;
            int row = idx >> 2, kc = (idx & 3) * 8;
            cpasync16(sBase + (uint32_t)((s * AW + row * XW) * 4 + kc * 2),
                      A + (size_t)(bm + row) * K + t * BKH + kc);
        }
        #pragma unroll
        for (int i = 0; i < 2; ++i) {
            int idx = i * 256 + tid;
            int n = idx >> 2, kc = (idx & 3) * 8;
            cpasync16(sBase + (uint32_t)((3 * AW + s * BW + n * XW) * 4 + kc * 2),
                      Bt + (size_t)(bn + n) * K + t * BKH + kc);
        }
        asm volatile("cp.async.commit_group;");
    };

    loadTile(0, 0);
    loadTile(1, 1);

    for (int t = 0; t < ntile; ++t) {
        int s = t % 3;
        if (t + 2 < ntile) asm volatile("cp.async.wait_group 1;");
        else               asm volatile("cp.async.wait_group 0;");
        __syncthreads();
        if (t + 2 < ntile) loadTile(t + 2, (t + 2) % 3);

        const uint32_t aOff = sBase + (uint32_t)(s * AW) * 4;
        const uint32_t bOff = sBase + (uint32_t)(3 * AW + s * BW) * 4;
        #pragma unroll
        for (int ks = 0; ks < 2; ++ks) {
            uint32_t a[4][4], b[4][2];
            #pragma unroll
            for (int mt = 0; mt < 4; ++mt)
                ldsm_x4(a[mt], aOff + (aLane + (uint32_t)(mt * 16 * XW + ks * 8)) * 4);
            #pragma unroll
            for (int np = 0; np < 2; ++np) {
                uint32_t bb[4];
                ldsm_x4(bb, bOff + (bLane + (uint32_t)(np * 16 * XW + ks * 8)) * 4);
                b[np * 2][0]     = bb[0];
                b[np * 2][1]     = bb[1];
                b[np * 2 + 1][0] = bb[2];
                b[np * 2 + 1][1] = bb[3];
            }
            #pragma unroll
            for (int mt = 0; mt < 4; ++mt)
                #pragma unroll
                for (int nt = 0; nt < 4; ++nt)
                    mma_fp16(acc[mt][nt], a[mt], b[nt]);
        }
    }

    #pragma unroll
    for (int mt = 0; mt < 4; ++mt) {
        #pragma unroll
        for (int half = 0; half < 2; ++half) {
            int row = bm + wm + mt * 16 + g + half * 8;
            size_t rbase = (size_t)row * N + bn + wn;
            #pragma unroll
            for (int nt = 0; nt < 4; ++nt) {
                int col = nt * 8 + q * 2;
                float2 v;
                v.x = acc[mt][nt][half * 2 + 0];
                v.y = acc[mt][nt][half * 2 + 1];
                if (R) {
                    const float2 rr = *(const float2*)(R + rbase + col);
                    v.x += rr.x; v.y += rr.y;
                }
                *(float2*)(C + rbase + col) = v;
            }
        }
    }
}

// ---------------- causal short conv (K=4) + silu, 4 timesteps/thread ----------------
__global__ void conv_silu_kernel(const float* __restrict__ x, const float* __restrict__ w,
                                 float* __restrict__ y) {
    int idx = blockIdx.x * 256 + threadIdx.x;
    int d4 = idx & 255;
    int rest = idx >> 8;
    int t4 = rest & (TT / 4 - 1);
    int b = rest >> 11;
    const float4* x4 = (const float4*)x;
    const float4* w4 = (const float4*)w;
    float4 wr0 = w4[d4 * 4 + 0], wr1 = w4[d4 * 4 + 1];
    float4 wr2 = w4[d4 * 4 + 2], wr3 = w4[d4 * 4 + 3];
    int t0 = t4 * 4;
    size_t rowbase = (size_t)b * TT * 256 + d4;
    float4 xv[7];
    #pragma unroll
    for (int j = 0; j < 7; ++j) {
        int tt = t0 - 3 + j;
        xv[j] = (tt >= 0) ? x4[rowbase + (size_t)tt * 256] : make_float4(0.f, 0.f, 0.f, 0.f);
    }
    #pragma unroll
    for (int i = 0; i < 4; ++i) {
        float4 a;
        a.x = xv[i].x * wr0.x + xv[i+1].x * wr0.y + xv[i+2].x * wr0.z + xv[i+3].x * wr0.w;
        a.y = xv[i].y * wr1.x + xv[i+1].y * wr1.y + xv[i+2].y * wr1.z + xv[i+3].y * wr1.w;
        a.z = xv[i].z * wr2.x + xv[i+1].z * wr2.y + xv[i+2].z * wr2.z + xv[i+3].z * wr2.w;
        a.w = xv[i].w * wr3.x + xv[i+1].w * wr3.y + xv[i+2].w * wr3.z + xv[i+3].w * wr3.w;
        a.x = a.x / (1.f + expf(-a.x));
        a.y = a.y / (1.f + expf(-a.y));
        a.z = a.z / (1.f + expf(-a.z));
        a.w = a.w / (1.f + expf(-a.w));
        ((float4*)y)[rowbase + (size_t)(t0 + i) * 256] = a;
    }
}

// ---------------- RoPE table ----------------
__global__ void rope_table_kernel() {
    int idx = blockIdx.x * 256 + threadIdx.x;
    if (idx >= TT * 64) return;
    int t = idx >> 6, j = idx & 63;
    float invf = (float)(1.0 / pow(10000.0, (double)j / 64.0));
    float f = (float)t * invf;
    g_cos[idx] = (float)cos((double)f);
    g_sin[idx] = (float)sin((double)f);
}

// ---------------- RoPE apply ----------------
__global__ void rope_kernel(float* __restrict__ x) {
    size_t idx = (size_t)blockIdx.x * 256 + threadIdx.x;
    if (idx >= (size_t)BB * TT * HH * 64) return;
    int j = (int)(idx & 63);
    int h = (int)((idx >> 6) & 7);
    size_t bt = idx >> 9;
    int t = (int)(bt % TT);
    float c = g_cos[t * 64 + j], s = g_sin[t * 64 + j];
    size_t base = bt * DD + h * 128;
    float x1 = x[base + j], x2 = x[base + 64 + j];
    x[base + j]      = x1 * c - x2 * s;
    x[base + 64 + j] = x1 * s + x2 * c;
}

// ---------------- retention phase 1 ----------------
__global__ void ret_phase1(const float* __restrict__ k, const float* __restrict__ v,
                           float* __restrict__ S) {
    extern __shared__ float sm[];
    float* ks = sm;
    float* vs = sm + 64 * 129;
    int c = blockIdx.x, h = blockIdx.y, b = blockIdx.z;
    float gamma = 1.f - exp2f(-5.f - (float)h);
    float lg = logf(gamma);
    int tid = threadIdx.x;
    for (int x = tid; x < 8192; x += 256) {
        int i = x >> 7, d = x & 127;
        size_t gg = ((size_t)b * TT + c * 64 + i) * DD + h * 128 + d;
        ks[i * 129 + d] = k[gg] * expf(lg * (float)(63 - i));
        vs[i * 129 + d] = v[gg];
    }
    __syncthreads();
    int w = tid >> 5, lane = tid & 31;
    int d0 = w * 16 + (lane >> 3) * 4;
    int e0 = (lane & 7) * 16;
    float acc[4][16];
    #pragma unroll
    for (int i = 0; i < 4; ++i)
        #pragma unroll
        for (int j = 0; j < 16; ++j) acc[i][j] = 0.f;
    #pragma unroll 4
    for (int j = 0; j < 64; ++j) {
        float kr[4], vr[16];
        #pragma unroll
        for (int i = 0; i < 4; ++i) kr[i] = ks[j * 129 + d0 + i];
        #pragma unroll
        for (int e = 0; e < 16; ++e) vr[e] = vs[j * 129 + e0 + e];
        #pragma unroll
        for (int i = 0; i < 4; ++i)
            #pragma unroll
            for (int e = 0; e < 16; ++e) acc[i][e] = fmaf(kr[i], vr[e], acc[i][e]);
    }
    size_t sb = (((size_t)(b * HH + h)) * NC + c) * 16384;
    #pragma unroll
    for (int i = 0; i < 4; ++i)
        #pragma unroll
        for (int e = 0; e < 16; ++e)
            S[sb + (d0 + i) * 128 + e0 + e] = acc[i][e];
}

// ---------------- retention phase 2: parallel exclusive scan ----------------
__global__ void ret_scan(float* __restrict__ S) {
    int bh = blockIdx.x >> 6;
    int elem = ((blockIdx.x & 63) << 8) + threadIdx.x;
    int h = bh & 7;
    float gamma = 1.f - exp2f(-5.f - (float)h);
    float cdec = expf(logf(gamma) * 64.f);
    float carry = 0.f;
    size_t base = (size_t)bh * NC * 16384 + elem;
    for (int c = 0; c < NC; ++c) {
        size_t idx = base + (size_t)c * 16384;
        float loc = S[idx];
        S[idx] = carry;
        carry = carry * cdec + loc;
    }
}

// ---------------- retention phase 3 ----------------
__global__ void ret_phase3(const float* __restrict__ q, const float* __restrict__ k,
                           const float* __restrict__ v, const float* __restrict__ S,
                           float* __restrict__ o) {
    extern __shared__ float sm[];
    float* qs  = sm;
    float* ks  = qs + 64 * 129;
    float* vs  = ks + 64 * 129;
    float* Ps  = vs + 64 * 129;
    float* att = Ps + 128 * 129;
    int c = blockIdx.x, h = blockIdx.y, b = blockIdx.z;
    float gamma = 1.f - exp2f(-5.f - (float)h);
    float lg = logf(gamma);
    const float scale = 0.08838834764831845f;
    int tid = threadIdx.x;
    int lane = tid & 31;
    for (int x = tid; x < 8192; x += 256) {
        int i = x >> 7, d = x & 127;
        size_t gg = ((size_t)b * TT + c * 64 + i) * DD + h * 128 + d;
        qs[i * 129 + d] = q[gg] * scale;
        ks[i * 129 + d] = k[gg];
        vs[i * 129 + d] = v[gg];
    }
    size_t sb = (((size_t)(b * HH + h)) * NC + c) * 16384;
    for (int x = tid; x < 16384; x += 256) {
        int d = x >> 7, e = x & 127;
        Ps[d * 129 + e] = S[sb + x];
    }
    __syncthreads();
    {
        int i0 = (tid >> 4) * 4;
        int j0 = (tid & 15) * 4;
        float a4[4][4];
        #pragma unroll
        for (int i = 0; i < 4; ++i)
            #pragma unroll
            for (int j = 0; j < 4; ++j) a4[i][j] = 0.f;
        #pragma unroll 4
        for (int d = 0; d < 128; ++d) {
            float qr[4], kr[4];
            #pragma unroll
            for (int i = 0; i < 4; ++i) qr[i] = qs[(i0 + i) * 129 + d];
            #pragma unroll
            for (int j = 0; j < 4; ++j) kr[j] = ks[(j0 + j) * 129 + d];
            #pragma unroll
            for (int i = 0; i < 4; ++i)
                #pragma unroll
                for (int j = 0; j < 4; ++j) a4[i][j] = fmaf(qr[i], kr[j], a4[i][j]);
        }
        #pragma unroll
        for (int i = 0; i < 4; ++i)
            #pragma unroll
            for (int j = 0; j < 4; ++j) {
                int ia = i0 + i, ja = j0 + j;
                float f = (ia >= ja) ? expf(lg * (float)(ia - ja)) : 0.f;
                att[ia * 65 + ja] = a4[i][j] * f;
            }
    }
    __syncthreads();
    {
        int i0 = (tid >> 5) * 8 + (lane >> 4) * 4;
        int e0 = (lane & 15) * 8;
        float accA[4][8], accB[4][8];
        #pragma unroll
        for (int i = 0; i < 4; ++i)
            #pragma unroll
            for (int e = 0; e < 8; ++e) { accA[i][e] = 0.f; accB[i][e] = 0.f; }
        #pragma unroll 4
        for (int j = 0; j < 64; ++j) {
            float ar[4], vr[8];
            #pragma unroll
            for (int i = 0; i < 4; ++i) ar[i] = att[(i0 + i) * 65 + j];
            #pragma unroll
            for (int e = 0; e < 8; ++e) vr[e] = vs[j * 129 + e0 + e];
            #pragma unroll
            for (int i = 0; i < 4; ++i)
                #pragma unroll
                for (int e = 0; e < 8; ++e) accA[i][e] = fmaf(ar[i], vr[e], accA[i][e]);
        }
        #pragma unroll 4
        for (int d = 0; d < 128; ++d) {
            float qr[4], pr[8];
            #pragma unroll
            for (int i = 0; i < 4; ++i) qr[i] = qs[(i0 + i) * 129 + d];
            #pragma unroll
            for (int e = 0; e < 8; ++e) pr[e] = Ps[d * 129 + e0 + e];
            #pragma unroll
            for (int i = 0; i < 4; ++i)
                #pragma unroll
                for (int e = 0; e < 8; ++e) accB[i][e] = fmaf(qr[i], pr[e], accB[i][e]);
        }
        #pragma unroll
        for (int i = 0; i < 4; ++i) {
            float crossf = expf(lg * (float)(i0 + i + 1));
            size_t ob = ((size_t)b * TT + c * 64 + i0 + i) * DD + h * 128 + e0;
            #pragma unroll
            for (int e = 0; e < 8; ++e)
                o[ob + e] = accA[i][e] + crossf * accB[i][e];
        }
    }
}

// ---------------- gating -> fp16 out ----------------
__global__ void gate_kernel(const float* __restrict__ o, const float* __restrict__ g,
                            const float* __restrict__ w, __half* __restrict__ oh) {
    int row = blockIdx.x * 8 + (threadIdx.x >> 5);
    int lane = threadIdx.x & 31;
    const float4* orow = (const float4*)(o + (size_t)row * 128);
    const float4* grow = (const float4*)(g + (size_t)row * 128);
    float4 v = orow[lane];
    float s = v.x * v.x + v.y * v.y + v.z * v.z + v.w * v.w;
    #pragma unroll
    for (int off = 16; off > 0; off >>= 1) s += __shfl_xor_sync(0xffffffffu, s, off);
    float inv = rsqrtf(s / 128.f + GATE_EPS);
    float4 gv = grow[lane];
    float4 wv = ((const float4*)w)[lane];
    float rx = v.x * inv * wv.x * (gv.x / (1.f + expf(-gv.x)));
    float ry = v.y * inv * wv.y * (gv.y / (1.f + expf(-gv.y)));
    float rz = v.z * inv * wv.z * (gv.z / (1.f + expf(-gv.z)));
    float rw = v.w * inv * wv.w * (gv.w / (1.f + expf(-gv.w)));
    __half2* dst = (__half2*)(oh + (size_t)row * 128);
    dst[lane * 2]     = __floats2half2_rn(rx, ry);
    dst[lane * 2 + 1] = __floats2half2_rn(rz, rw);
}

// ---------------- swiglu -> fp16 out ----------------
__global__ void swiglu_kernel(const float* __restrict__ a, const float* __restrict__ b2,
                              __half* __restrict__ outh, size_t n4) {
    size_t idx = (size_t)blockIdx.x * 256 + threadIdx.x;
    if (idx >= n4) return;
    float4 x = ((const float4*)a)[idx];
    float4 y = ((const float4*)b2)[idx];
    float rx = (x.x / (1.f + expf(-x.x))) * y.x;
    float ry = (x.y / (1.f + expf(-x.y))) * y.y;
    float rz = (x.z / (1.f + expf(-x.z))) * y.z;
    float rw = (x.w / (1.f + expf(-x.w))) * y.w;
    __half2* dst = (__half2*)outh;
    dst[idx * 2]     = __floats2half2_rn(rx, ry);
    dst[idx * 2 + 1] = __floats2half2_rn(rz, rw);
}

// ---------------- launch ----------------
extern "C" void kernel_launch(void* const* d_in, const int* in_sizes, int n_in,
                              void* d_out, int out_size) {
    const float* hs    = (const float*)d_in[0];
    const float* ln1   = (const float*)d_in[1];
    const float* ln2   = (const float*)d_in[2];
    const float* wq    = (const float*)d_in[3];
    const float* wk    = (const float*)d_in[4];
    const float* wv    = (const float*)d_in[5];
    const float* wg    = (const float*)d_in[6];
    const float* wo    = (const float*)d_in[7];
    const float* cq    = (const float*)d_in[8];
    const float* ck    = (const float*)d_in[9];
    const float* cv    = (const float*)d_in[10];
    const float* gn    = (const float*)d_in[11];
    const float* wgate = (const float*)d_in[12];
    const float* wup   = (const float*)d_in[13];
    const float* wdown = (const float*)d_in[14];
    float* out = (float*)d_out;

    cudaFuncSetAttribute(hgemm_kernel, cudaFuncAttributeMaxDynamicSharedMemorySize, SMEM_GEMM);
    cudaFuncSetAttribute(ret_phase1, cudaFuncAttributeMaxDynamicSharedMemorySize, 2 * 64 * 129 * 4);
    cudaFuncSetAttribute(ret_phase3, cudaFuncAttributeMaxDynamicSharedMemorySize,
                         (3 * 64 * 129 + 128 * 129 + 64 * 65) * 4);

    float *t0, *t1, *t2, *q, *k, *v, *o, *hbuf, *S, *m1, *m2;
    __half *xh, *oh, *m1h, *bt;
    cudaGetSymbolAddress((void**)&t0, g_t0);
    cudaGetSymbolAddress((void**)&t1, g_t1);
    cudaGetSymbolAddress((void**)&t2, g_t2);
    cudaGetSymbolAddress((void**)&q,  g_q);
    cudaGetSymbolAddress((void**)&k,  g_k);
    cudaGetSymbolAddress((void**)&v,  g_v);
    cudaGetSymbolAddress((void**)&o,  g_o);
    cudaGetSymbolAddress((void**)&hbuf, g_h);
    cudaGetSymbolAddress((void**)&S,  g_S);
    cudaGetSymbolAddress((void**)&m1, g_m1);
    cudaGetSymbolAddress((void**)&m2, g_m2);
    cudaGetSymbolAddress((void**)&xh, g_xh);
    cudaGetSymbolAddress((void**)&oh, g_oh);
    cudaGetSymbolAddress((void**)&m1h, g_m1h);
    cudaGetSymbolAddress((void**)&bt, g_bt);

    const int cvblocks = BB * TT / 4;
    rope_table_kernel<<<(TT * 64 + 255) / 256, 256>>>();
    rmsnorm_kernel<<<BT, 256>>>(hs, ln1, xh, RMS_EPS);

    dim3 tD(DD / 32, DD / 32), tI1(II / 32, DD / 32), tI2(DD / 32, II / 32), tb(32, 8);
    dim3 gD(DD / 128, BT / 128), gI(II / 128, BT / 128);

    convT_kernel<<<tD, tb>>>(wq, bt, DD, DD);
    hgemm_kernel<<<gD, 256, SMEM_GEMM>>>(xh, bt, nullptr, t0, BT, DD, DD);
    conv_silu_kernel<<<cvblocks, 256>>>(t0, cq, q);
    convT_kernel<<<tD, tb>>>(wk, bt, DD, DD);
    hgemm_kernel<<<gD, 256, SMEM_GEMM>>>(xh, bt, nullptr, t1, BT, DD, DD);
    conv_silu_kernel<<<cvblocks, 256>>>(t1, ck, k);
    convT_kernel<<<tD, tb>>>(wv, bt, DD, DD);
    hgemm_kernel<<<gD, 256, SMEM_GEMM>>>(xh, bt, nullptr, t2, BT, DD, DD);
    conv_silu_kernel<<<cvblocks, 256>>>(t2, cv, v);

    const int rw = (int)(((size_t)BB * TT * HH * 64 + 255) / 256);
    rope_kernel<<<rw, 256>>>(q);
    rope_kernel<<<rw, 256>>>(k);

    dim3 gc(NC, HH, BB);
    ret_phase1<<<gc, 256, 2 * 64 * 129 * 4>>>(k, v, S);
    ret_scan<<<BB * HH * 64, 256>>>(S);
    ret_phase3<<<gc, 256, (3 * 64 * 129 + 128 * 129 + 64 * 65) * 4>>>(q, k, v, S, o);

    convT_kernel<<<tD, tb>>>(wg, bt, DD, DD);
    hgemm_kernel<<<gD, 256, SMEM_GEMM>>>(xh, bt, nullptr, t0, BT, DD, DD);
    gate_kernel<<<(BT * HH) / 8, 256>>>(o, t0, gn, oh);
    convT_kernel<<<tD, tb>>>(wo, bt, DD, DD);
    hgemm_kernel<<<gD, 256, SMEM_GEMM>>>(oh, bt, hs, hbuf, BT, DD, DD);

    rmsnorm_kernel<<<BT, 256>>>(hbuf, ln2, xh, RMS_EPS);
    convT_kernel<<<tI1, tb>>>(wgate, bt, DD, II);
    hgemm_kernel<<<gI, 256, SMEM_GEMM>>>(xh, bt, nullptr, m1, BT, II, DD);
    convT_kernel<<<tI1, tb>>>(wup, bt, DD, II);
    hgemm_kernel<<<gI, 256, SMEM_GEMM>>>(xh, bt, nullptr, m2, BT, II, DD);
    size_t nmid4 = (size_t)BT * II / 4;
    swiglu_kernel<<<(int)((nmid4 + 255) / 256), 256>>>(m1, m2, m1h, nmid4);
    convT_kernel<<<tI2, tb>>>(wdown, bt, II, DD);
    hgemm_kernel<<<gD, 256, SMEM_GEMM>>>(m1h, bt, hbuf, out, BT, DD, II);
}

// round 8
// speedup vs baseline: 4.9160x; 1.0344x over previous
#include <cuda_runtime.h>
#include <cuda_fp16.h>
#include <math.h>
#include <stdint.h>

#define BB 4
#define TT 8192
#define DD 1024
#define HH 8
#define II 2816
#define NC 128
#define BT (BB*TT)

#define RMS_EPS 1e-6f
#define GATE_EPS 1e-5f

// ---------------- scratch ----------------
__device__ float  g_big[(size_t)BT*4096];     // fused qkvg output
__device__ float  g_mm [(size_t)BT*5632];     // fused gate/up output
__device__ float  g_q [(size_t)BT*DD];
__device__ float  g_k [(size_t)BT*DD];
__device__ float  g_v [(size_t)BT*DD];
__device__ float  g_o [(size_t)BT*DD];
__device__ float  g_h [(size_t)BT*DD];
__device__ float  g_S [(size_t)BB*HH*NC*128*128];
__device__ __half g_xh [(size_t)BT*DD];
__device__ __half g_oh [(size_t)BT*DD];
__device__ __half g_m1h[(size_t)BT*II];
__device__ __half g_bt [(size_t)5632*DD];
__device__ float  g_cos[TT*64];
__device__ float  g_sin[TT*64];

// ---------------- rmsnorm -> fp16 out ----------------
__global__ void rmsnorm_kernel(const float* __restrict__ x, const float* __restrict__ w,
                               __half* __restrict__ out, float eps) {
    int row = blockIdx.x;
    const float4* xr = (const float4*)(x + (size_t)row * DD);
    float4 v = xr[threadIdx.x];
    float s = v.x * v.x + v.y * v.y + v.z * v.z + v.w * v.w;
    __shared__ float red[8];
    #pragma unroll
    for (int o = 16; o > 0; o >>= 1) s += __shfl_down_sync(0xffffffffu, s, o);
    if ((threadIdx.x & 31) == 0) red[threadIdx.x >> 5] = s;
    __syncthreads();
    if (threadIdx.x < 8) {
        s = red[threadIdx.x];
        #pragma unroll
        for (int o = 4; o > 0; o >>= 1) s += __shfl_down_sync(0xffu, s, o);
        if (threadIdx.x == 0) red[0] = s;
    }
    __syncthreads();
    float inv = rsqrtf(red[0] / (float)DD + eps);
    float4 wv = ((const float4*)w)[threadIdx.x];
    __half2* orow = (__half2*)(out + (size_t)row * DD);
    orow[threadIdx.x * 2]     = __floats2half2_rn(v.x * inv * wv.x, v.y * inv * wv.y);
    orow[threadIdx.x * 2 + 1] = __floats2half2_rn(v.z * inv * wv.z, v.w * inv * wv.w);
}

// ---------------- weight convert + transpose: W[K][N] fp32 -> Wt[N][K] fp16 ----------------
__global__ void convT_kernel(const float* __restrict__ W, __half* __restrict__ Wt,
                             int K, int N) {
    __shared__ float tile[32][33];
    int n0 = blockIdx.x * 32, k0 = blockIdx.y * 32;
    #pragma unroll
    for (int j = threadIdx.y; j < 32; j += 8)
        tile[j][threadIdx.x] = W[(size_t)(k0 + j) * N + n0 + threadIdx.x];
    __syncthreads();
    #pragma unroll
    for (int j = threadIdx.y; j < 32; j += 8)
        Wt[(size_t)(n0 + j) * K + k0 + threadIdx.x] = __float2half_rn(tile[threadIdx.x][j]);
}

// ================= fp16 tensor-core GEMM (HMMA + ldmatrix, BK=64, 2 CTA/SM) =================
// C = A @ B (+R), A: MxK fp16 row-major, Bt: NxK fp16 row-major.
// 128x128 CTA tile, BK=64, 3-stage cp.async, 8 warps (2M x 4N) of 64x32.
#define BKH 64
#define XW 36                      // uint32 words per smem row (72 fp16; ldsm+cpasync conflict-free)
#define AW (128*XW)
#define BW (128*XW)
#define STG (AW+BW)
#define SMEM_GEMM (3*STG*4)

__device__ __forceinline__ void mma_fp16(float* c, const uint32_t* a, const uint32_t* b) {
    asm volatile("mma.sync.aligned.m16n8k16.row.col.f32.f16.f16.f32 "
        "{%0,%1,%2,%3}, {%4,%5,%6,%7}, {%8,%9}, {%0,%1,%2,%3};"
        : "+f"(c[0]), "+f"(c[1]), "+f"(c[2]), "+f"(c[3])
        : "r"(a[0]), "r"(a[1]), "r"(a[2]), "r"(a[3]), "r"(b[0]), "r"(b[1]));
}
__device__ __forceinline__ void cpasync16(uint32_t s, const void* g) {
    asm volatile("cp.async.cg.shared.global [%0], [%1], 16;" :: "r"(s), "l"(g));
}
__device__ __forceinline__ void ldsm_x4(uint32_t* r, uint32_t addr) {
    asm volatile("ldmatrix.sync.aligned.m8n8.x4.shared.b16 {%0,%1,%2,%3}, [%4];"
        : "=r"(r[0]), "=r"(r[1]), "=r"(r[2]), "=r"(r[3]) : "r"(addr));
}

__global__ __launch_bounds__(256, 2)
void hgemm_kernel(const __half* __restrict__ A, const __half* __restrict__ Bt,
                  const float* __restrict__ R, float* __restrict__ C,
                  int M, int N, int K) {
    extern __shared__ uint32_t smw[];

    const int tid = threadIdx.x;
    const int lane = tid & 31;
    const int w = tid >> 5;
    const int g = lane >> 2, q = lane & 3;
    const int wm = (w & 1) * 64;
    const int wn = (w >> 1) * 32;
    const int bm = blockIdx.y * 128, bn = blockIdx.x * 128;

    uint32_t sBase = (uint32_t)__cvta_generic_to_shared(smw);

    const uint32_t aLane = (uint32_t)((wm + (lane & 15)) * XW + ((lane >> 4) << 2));
    const uint32_t bLane = (uint32_t)((wn + (lane & 7) + ((lane >> 4) << 3)) * XW + (((lane >> 3) & 1) << 2));

    float acc[4][4][4];
    #pragma unroll
    for (int i = 0; i < 4; ++i)
        #pragma unroll
        for (int j = 0; j < 4; ++j)
            #pragma unroll
            for (int r = 0; r < 4; ++r) acc[i][j][r] = 0.f;

    const int ntile = K / BKH;

    auto loadTile = [&](int t, int s) {
        #pragma unroll
        for (int i = 0; i < 4; ++i) {
            int idx = i * 256 + tid;
            int row = idx >> 3, kc = (idx & 7) * 8;      // kc in halves
            cpasync16(sBase + (uint32_t)((s * STG + row * XW) * 4 + kc * 2),
                      A + (size_t)(bm + row) * K + t * BKH + kc);
        }
        #pragma unroll
        for (int i = 0; i < 4; ++i) {
            int idx = i * 256 + tid;
            int n = idx >> 3, kc = (idx & 7) * 8;
            cpasync16(sBase + (uint32_t)((s * STG + AW + n * XW) * 4 + kc * 2),
                      Bt + (size_t)(bn + n) * K + t * BKH + kc);
        }
        asm volatile("cp.async.commit_group;");
    };

    loadTile(0, 0);
    if (ntile > 1) loadTile(1, 1);

    for (int t = 0; t < ntile; ++t) {
        int s = t % 3;
        if (t + 2 < ntile) asm volatile("cp.async.wait_group 1;");
        else               asm volatile("cp.async.wait_group 0;");
        __syncthreads();
        if (t + 2 < ntile) loadTile(t + 2, (t + 2) % 3);

        const uint32_t aOff = sBase + (uint32_t)(s * STG) * 4;
        const uint32_t bOff = sBase + (uint32_t)(s * STG + AW) * 4;
        #pragma unroll
        for (int ks = 0; ks < 4; ++ks) {
            uint32_t a[4][4], b[4][2];
            #pragma unroll
            for (int mt = 0; mt < 4; ++mt)
                ldsm_x4(a[mt], aOff + (aLane + (uint32_t)(mt * 16 * XW + ks * 8)) * 4);
            #pragma unroll
            for (int np = 0; np < 2; ++np) {
                uint32_t bb[4];
                ldsm_x4(bb, bOff + (bLane + (uint32_t)(np * 16 * XW + ks * 8)) * 4);
                b[np * 2][0]     = bb[0];
                b[np * 2][1]     = bb[1];
                b[np * 2 + 1][0] = bb[2];
                b[np * 2 + 1][1] = bb[3];
            }
            #pragma unroll
            for (int mt = 0; mt < 4; ++mt)
                #pragma unroll
                for (int nt = 0; nt < 4; ++nt)
                    mma_fp16(acc[mt][nt], a[mt], b[nt]);
        }
    }

    #pragma unroll
    for (int mt = 0; mt < 4; ++mt) {
        #pragma unroll
        for (int half = 0; half < 2; ++half) {
            int row = bm + wm + mt * 16 + g + half * 8;
            size_t rbase = (size_t)row * N + bn + wn;
            #pragma unroll
            for (int nt = 0; nt < 4; ++nt) {
                int col = nt * 8 + q * 2;
                float2 v;
                v.x = acc[mt][nt][half * 2 + 0];
                v.y = acc[mt][nt][half * 2 + 1];
                if (R) {
                    const float2 rr = *(const float2*)(R + rbase + col);
                    v.x += rr.x; v.y += rr.y;
                }
                *(float2*)(C + rbase + col) = v;
            }
        }
    }
}

// ---------------- causal short conv (K=4) + silu, strided input, 4 timesteps/thread ----------------
__global__ void conv_silu_kernel(const float* __restrict__ x, const float* __restrict__ w,
                                 float* __restrict__ y, int rs4 /*input row stride in float4*/) {
    int idx = blockIdx.x * 256 + threadIdx.x;
    int d4 = idx & 255;
    int rest = idx >> 8;
    int t4 = rest & (TT / 4 - 1);
    int b = rest >> 11;
    const float4* x4 = (const float4*)x;
    const float4* w4 = (const float4*)w;
    float4 wr0 = w4[d4 * 4 + 0], wr1 = w4[d4 * 4 + 1];
    float4 wr2 = w4[d4 * 4 + 2], wr3 = w4[d4 * 4 + 3];
    int t0 = t4 * 4;
    size_t inbase  = (size_t)b * TT * rs4 + d4;
    size_t outbase = (size_t)b * TT * 256 + d4;
    float4 xv[7];
    #pragma unroll
    for (int j = 0; j < 7; ++j) {
        int tt = t0 - 3 + j;
        xv[j] = (tt >= 0) ? x4[inbase + (size_t)tt * rs4] : make_float4(0.f, 0.f, 0.f, 0.f);
    }
    #pragma unroll
    for (int i = 0; i < 4; ++i) {
        float4 a;
        a.x = xv[i].x * wr0.x + xv[i+1].x * wr0.y + xv[i+2].x * wr0.z + xv[i+3].x * wr0.w;
        a.y = xv[i].y * wr1.x + xv[i+1].y * wr1.y + xv[i+2].y * wr1.z + xv[i+3].y * wr1.w;
        a.z = xv[i].z * wr2.x + xv[i+1].z * wr2.y + xv[i+2].z * wr2.z + xv[i+3].z * wr2.w;
        a.w = xv[i].w * wr3.x + xv[i+1].w * wr3.y + xv[i+2].w * wr3.z + xv[i+3].w * wr3.w;
        a.x = a.x / (1.f + expf(-a.x));
        a.y = a.y / (1.f + expf(-a.y));
        a.z = a.z / (1.f + expf(-a.z));
        a.w = a.w / (1.f + expf(-a.w));
        ((float4*)y)[outbase + (size_t)(t0 + i) * 256] = a;
    }
}

// ---------------- RoPE table ----------------
__global__ void rope_table_kernel() {
    int idx = blockIdx.x * 256 + threadIdx.x;
    if (idx >= TT * 64) return;
    int t = idx >> 6, j = idx & 63;
    float invf = (float)(1.0 / pow(10000.0, (double)j / 64.0));
    float f = (float)t * invf;
    g_cos[idx] = (float)cos((double)f);
    g_sin[idx] = (float)sin((double)f);
}

// ---------------- RoPE apply ----------------
__global__ void rope_kernel(float* __restrict__ x) {
    size_t idx = (size_t)blockIdx.x * 256 + threadIdx.x;
    if (idx >= (size_t)BB * TT * HH * 64) return;
    int j = (int)(idx & 63);
    int h = (int)((idx >> 6) & 7);
    size_t bt = idx >> 9;
    int t = (int)(bt % TT);
    float c = g_cos[t * 64 + j], s = g_sin[t * 64 + j];
    size_t base = bt * DD + h * 128;
    float x1 = x[base + j], x2 = x[base + 64 + j];
    x[base + j]      = x1 * c - x2 * s;
    x[base + 64 + j] = x1 * s + x2 * c;
}

// ---------------- retention phase 1 ----------------
__global__ void ret_phase1(const float* __restrict__ k, const float* __restrict__ v,
                           float* __restrict__ S) {
    extern __shared__ float sm[];
    float* ks = sm;
    float* vs = sm + 64 * 129;
    int c = blockIdx.x, h = blockIdx.y, b = blockIdx.z;
    float gamma = 1.f - exp2f(-5.f - (float)h);
    float lg = logf(gamma);
    int tid = threadIdx.x;
    for (int x = tid; x < 8192; x += 256) {
        int i = x >> 7, d = x & 127;
        size_t gg = ((size_t)b * TT + c * 64 + i) * DD + h * 128 + d;
        ks[i * 129 + d] = k[gg] * expf(lg * (float)(63 - i));
        vs[i * 129 + d] = v[gg];
    }
    __syncthreads();
    int w = tid >> 5, lane = tid & 31;
    int d0 = w * 16 + (lane >> 3) * 4;
    int e0 = (lane & 7) * 16;
    float acc[4][16];
    #pragma unroll
    for (int i = 0; i < 4; ++i)
        #pragma unroll
        for (int j = 0; j < 16; ++j) acc[i][j] = 0.f;
    #pragma unroll 4
    for (int j = 0; j < 64; ++j) {
        float kr[4], vr[16];
        #pragma unroll
        for (int i = 0; i < 4; ++i) kr[i] = ks[j * 129 + d0 + i];
        #pragma unroll
        for (int e = 0; e < 16; ++e) vr[e] = vs[j * 129 + e0 + e];
        #pragma unroll
        for (int i = 0; i < 4; ++i)
            #pragma unroll
            for (int e = 0; e < 16; ++e) acc[i][e] = fmaf(kr[i], vr[e], acc[i][e]);
    }
    size_t sb = (((size_t)(b * HH + h)) * NC + c) * 16384;
    #pragma unroll
    for (int i = 0; i < 4; ++i)
        #pragma unroll
        for (int e = 0; e < 16; ++e)
            S[sb + (d0 + i) * 128 + e0 + e] = acc[i][e];
}

// ---------------- retention phase 2: parallel exclusive scan ----------------
__global__ void ret_scan(float* __restrict__ S) {
    int bh = blockIdx.x >> 6;
    int elem = ((blockIdx.x & 63) << 8) + threadIdx.x;
    int h = bh & 7;
    float gamma = 1.f - exp2f(-5.f - (float)h);
    float cdec = expf(logf(gamma) * 64.f);
    float carry = 0.f;
    size_t base = (size_t)bh * NC * 16384 + elem;
    for (int c = 0; c < NC; ++c) {
        size_t idx = base + (size_t)c * 16384;
        float loc = S[idx];
        S[idx] = carry;
        carry = carry * cdec + loc;
    }
}

// ---------------- retention phase 3 ----------------
__global__ void ret_phase3(const float* __restrict__ q, const float* __restrict__ k,
                           const float* __restrict__ v, const float* __restrict__ S,
                           float* __restrict__ o) {
    extern __shared__ float sm[];
    float* qs  = sm;
    float* ks  = qs + 64 * 129;
    float* vs  = ks + 64 * 129;
    float* Ps  = vs + 64 * 129;
    float* att = Ps + 128 * 129;
    int c = blockIdx.x, h = blockIdx.y, b = blockIdx.z;
    float gamma = 1.f - exp2f(-5.f - (float)h);
    float lg = logf(gamma);
    const float scale = 0.08838834764831845f;
    int tid = threadIdx.x;
    int lane = tid & 31;
    for (int x = tid; x < 8192; x += 256) {
        int i = x >> 7, d = x & 127;
        size_t gg = ((size_t)b * TT + c * 64 + i) * DD + h * 128 + d;
        qs[i * 129 + d] = q[gg] * scale;
        ks[i * 129 + d] = k[gg];
        vs[i * 129 + d] = v[gg];
    }
    size_t sb = (((size_t)(b * HH + h)) * NC + c) * 16384;
    for (int x = tid; x < 16384; x += 256) {
        int d = x >> 7, e = x & 127;
        Ps[d * 129 + e] = S[sb + x];
    }
    __syncthreads();
    {
        int i0 = (tid >> 4) * 4;
        int j0 = (tid & 15) * 4;
        float a4[4][4];
        #pragma unroll
        for (int i = 0; i < 4; ++i)
            #pragma unroll
            for (int j = 0; j < 4; ++j) a4[i][j] = 0.f;
        #pragma unroll 4
        for (int d = 0; d < 128; ++d) {
            float qr[4], kr[4];
            #pragma unroll
            for (int i = 0; i < 4; ++i) qr[i] = qs[(i0 + i) * 129 + d];
            #pragma unroll
            for (int j = 0; j < 4; ++j) kr[j] = ks[(j0 + j) * 129 + d];
            #pragma unroll
            for (int i = 0; i < 4; ++i)
                #pragma unroll
                for (int j = 0; j < 4; ++j) a4[i][j] = fmaf(qr[i], kr[j], a4[i][j]);
        }
        #pragma unroll
        for (int i = 0; i < 4; ++i)
            #pragma unroll
            for (int j = 0; j < 4; ++j) {
                int ia = i0 + i, ja = j0 + j;
                float f = (ia >= ja) ? expf(lg * (float)(ia - ja)) : 0.f;
                att[ia * 65 + ja] = a4[i][j] * f;
            }
    }
    __syncthreads();
    {
        int i0 = (tid >> 5) * 8 + (lane >> 4) * 4;
        int e0 = (lane & 15) * 8;
        float accA[4][8], accB[4][8];
        #pragma unroll
        for (int i = 0; i < 4; ++i)
            #pragma unroll
            for (int e = 0; e < 8; ++e) { accA[i][e] = 0.f; accB[i][e] = 0.f; }
        #pragma unroll 4
        for (int j = 0; j < 64; ++j) {
            float ar[4], vr[8];
            #pragma unroll
            for (int i = 0; i < 4; ++i) ar[i] = att[(i0 + i) * 65 + j];
            #pragma unroll
            for (int e = 0; e < 8; ++e) vr[e] = vs[j * 129 + e0 + e];
            #pragma unroll
            for (int i = 0; i < 4; ++i)
                #pragma unroll
                for (int e = 0; e < 8; ++e) accA[i][e] = fmaf(ar[i], vr[e], accA[i][e]);
        }
        #pragma unroll 4
        for (int d = 0; d < 128; ++d) {
            float qr[4], pr[8];
            #pragma unroll
            for (int i = 0; i < 4; ++i) qr[i] = qs[(i0 + i) * 129 + d];
            #pragma unroll
            for (int e = 0; e < 8; ++e) pr[e] = Ps[d * 129 + e0 + e];
            #pragma unroll
            for (int i = 0; i < 4; ++i)
                #pragma unroll
                for (int e = 0; e < 8; ++e) accB[i][e] = fmaf(qr[i], pr[e], accB[i][e]);
        }
        #pragma unroll
        for (int i = 0; i < 4; ++i) {
            float crossf = expf(lg * (float)(i0 + i + 1));
            size_t ob = ((size_t)b * TT + c * 64 + i0 + i) * DD + h * 128 + e0;
            #pragma unroll
            for (int e = 0; e < 8; ++e)
                o[ob + e] = accA[i][e] + crossf * accB[i][e];
        }
    }
}

// ---------------- gating -> fp16 out (g read strided from fused buffer, col offset 3072) ----------------
__global__ void gate_kernel(const float* __restrict__ o, const float* __restrict__ gbig,
                            const float* __restrict__ w, __half* __restrict__ oh) {
    int row = blockIdx.x * 8 + (threadIdx.x >> 5);   // row = bt*8 + h
    int lane = threadIdx.x & 31;
    int bt = row >> 3, h = row & 7;
    const float4* orow = (const float4*)(o + (size_t)row * 128);
    const float4* grow = (const float4*)(gbig + (size_t)bt * 4096 + 3072 + h * 128);
    float4 v = orow[lane];
    float s = v.x * v.x + v.y * v.y + v.z * v.z + v.w * v.w;
    #pragma unroll
    for (int off = 16; off > 0; off >>= 1) s += __shfl_xor_sync(0xffffffffu, s, off);
    float inv = rsqrtf(s / 128.f + GATE_EPS);
    float4 gv = grow[lane];
    float4 wv = ((const float4*)w)[lane];
    float rx = v.x * inv * wv.x * (gv.x / (1.f + expf(-gv.x)));
    float ry = v.y * inv * wv.y * (gv.y / (1.f + expf(-gv.y)));
    float rz = v.z * inv * wv.z * (gv.z / (1.f + expf(-gv.z)));
    float rw = v.w * inv * wv.w * (gv.w / (1.f + expf(-gv.w)));
    __half2* dst = (__half2*)(oh + (size_t)row * 128);
    dst[lane * 2]     = __floats2half2_rn(rx, ry);
    dst[lane * 2 + 1] = __floats2half2_rn(rz, rw);
}

// ---------------- swiglu fused: row of mm [BT][5632] -> m1h [BT][2816] fp16 ----------------
__global__ void swiglu_kernel(const float* __restrict__ mm, __half* __restrict__ outh) {
    int row = blockIdx.x;
    const float4* a  = (const float4*)(mm + (size_t)row * 5632);
    const float4* b2 = a + 704;
    __half2* dst = (__half2*)(outh + (size_t)row * 2816);
    for (int c = threadIdx.x; c < 704; c += 256) {
        float4 x = a[c];
        float4 y = b2[c];
        float rx = (x.x / (1.f + expf(-x.x))) * y.x;
        float ry = (x.y / (1.f + expf(-x.y))) * y.y;
        float rz = (x.z / (1.f + expf(-x.z))) * y.z;
        float rw = (x.w / (1.f + expf(-x.w))) * y.w;
        dst[c * 2]     = __floats2half2_rn(rx, ry);
        dst[c * 2 + 1] = __floats2half2_rn(rz, rw);
    }
}

// ---------------- launch ----------------
extern "C" void kernel_launch(void* const* d_in, const int* in_sizes, int n_in,
                              void* d_out, int out_size) {
    const float* hs    = (const float*)d_in[0];
    const float* ln1   = (const float*)d_in[1];
    const float* ln2   = (const float*)d_in[2];
    const float* wq    = (const float*)d_in[3];
    const float* wk    = (const float*)d_in[4];
    const float* wv    = (const float*)d_in[5];
    const float* wg    = (const float*)d_in[6];
    const float* wo    = (const float*)d_in[7];
    const float* cq    = (const float*)d_in[8];
    const float* ck    = (const float*)d_in[9];
    const float* cv    = (const float*)d_in[10];
    const float* gn    = (const float*)d_in[11];
    const float* wgate = (const float*)d_in[12];
    const float* wup   = (const float*)d_in[13];
    const float* wdown = (const float*)d_in[14];
    float* out = (float*)d_out;

    cudaFuncSetAttribute(hgemm_kernel, cudaFuncAttributeMaxDynamicSharedMemorySize, SMEM_GEMM);
    cudaFuncSetAttribute(ret_phase1, cudaFuncAttributeMaxDynamicSharedMemorySize, 2 * 64 * 129 * 4);
    cudaFuncSetAttribute(ret_phase3, cudaFuncAttributeMaxDynamicSharedMemorySize,
                         (3 * 64 * 129 + 128 * 129 + 64 * 65) * 4);

    float *big, *mm, *q, *k, *v, *o, *hbuf, *S;
    __half *xh, *oh, *m1h, *bt;
    cudaGetSymbolAddress((void**)&big, g_big);
    cudaGetSymbolAddress((void**)&mm,  g_mm);
    cudaGetSymbolAddress((void**)&q,  g_q);
    cudaGetSymbolAddress((void**)&k,  g_k);
    cudaGetSymbolAddress((void**)&v,  g_v);
    cudaGetSymbolAddress((void**)&o,  g_o);
    cudaGetSymbolAddress((void**)&hbuf, g_h);
    cudaGetSymbolAddress((void**)&S,  g_S);
    cudaGetSymbolAddress((void**)&xh, g_xh);
    cudaGetSymbolAddress((void**)&oh, g_oh);
    cudaGetSymbolAddress((void**)&m1h, g_m1h);
    cudaGetSymbolAddress((void**)&bt, g_bt);

    const int cvblocks = BB * TT / 4;
    rope_table_kernel<<<(TT * 64 + 255) / 256, 256>>>();
    rmsnorm_kernel<<<BT, 256>>>(hs, ln1, xh, RMS_EPS);

    dim3 tD(DD / 32, DD / 32), tI1(II / 32, DD / 32), tI2(DD / 32, II / 32), tb(32, 8);

    // fused qkvg: Bt rows [0,1024)=wq_t, [1024,2048)=wk_t, [2048,3072)=wv_t, [3072,4096)=wg_t
    convT_kernel<<<tD, tb>>>(wq, bt,                 DD, DD);
    convT_kernel<<<tD, tb>>>(wk, bt + 1024 * DD,     DD, DD);
    convT_kernel<<<tD, tb>>>(wv, bt + 2048 * DD,     DD, DD);
    convT_kernel<<<tD, tb>>>(wg, bt + 3072 * DD,     DD, DD);
    dim3 gQKVG(4096 / 128, BT / 128);
    hgemm_kernel<<<gQKVG, 256, SMEM_GEMM>>>(xh, bt, nullptr, big, BT, 4096, DD);

    conv_silu_kernel<<<cvblocks, 256>>>(big,        cq, q, 1024);
    conv_silu_kernel<<<cvblocks, 256>>>(big + 1024, ck, k, 1024);
    conv_silu_kernel<<<cvblocks, 256>>>(big + 2048, cv, v, 1024);

    const int rw = (int)(((size_t)BB * TT * HH * 64 + 255) / 256);
    rope_kernel<<<rw, 256>>>(q);
    rope_kernel<<<rw, 256>>>(k);

    dim3 gc(NC, HH, BB);
    ret_phase1<<<gc, 256, 2 * 64 * 129 * 4>>>(k, v, S);
    ret_scan<<<BB * HH * 64, 256>>>(S);
    ret_phase3<<<gc, 256, (3 * 64 * 129 + 128 * 129 + 64 * 65) * 4>>>(q, k, v, S, o);

    gate_kernel<<<(BT * HH) / 8, 256>>>(o, big, gn, oh);
    convT_kernel<<<tD, tb>>>(wo, bt, DD, DD);
    dim3 gD(DD / 128, BT / 128);
    hgemm_kernel<<<gD, 256, SMEM_GEMM>>>(oh, bt, hs, hbuf, BT, DD, DD);

    rmsnorm_kernel<<<BT, 256>>>(hbuf, ln2, xh, RMS_EPS);
    // fused gate+up: Bt rows [0,2816)=wgate_t, [2816,5632)=wup_t
    convT_kernel<<<tI1, tb>>>(wgate, bt,             DD, II);
    convT_kernel<<<tI1, tb>>>(wup,   bt + 2816 * DD, DD, II);
    dim3 gMLP(5632 / 128, BT / 128);
    hgemm_kernel<<<gMLP, 256, SMEM_GEMM>>>(xh, bt, nullptr, mm, BT, 5632, DD);
    swiglu_kernel<<<BT, 256>>>(mm, m1h);
    convT_kernel<<<tI2, tb>>>(wdown, bt, II, DD);
    hgemm_kernel<<<gD, 256, SMEM_GEMM>>>(m1h, bt, hbuf, out, BT, DD, II);
}

// round 9
// speedup vs baseline: 5.1835x; 1.0544x over previous
#include <cuda_runtime.h>
#include <cuda_fp16.h>
#include <math.h>
#include <stdint.h>

#define BB 4
#define TT 8192
#define DD 1024
#define HH 8
#define II 2816
#define NC 128
#define BT (BB*TT)

#define RMS_EPS 1e-6f
#define GATE_EPS 1e-5f

// ---------------- scratch ----------------
__device__ float  g_big[(size_t)BT*4096];     // fused qkvg output
__device__ float  g_mm [(size_t)BT*5632];     // fused gate/up output
__device__ __half g_qh [(size_t)BT*DD];
__device__ __half g_kh [(size_t)BT*DD];
__device__ __half g_vh [(size_t)BT*DD];
__device__ float  g_o [(size_t)BT*DD];
__device__ float  g_h [(size_t)BT*DD];
__device__ __half g_Sh[(size_t)BB*HH*NC*128*128];
__device__ __half g_xh [(size_t)BT*DD];
__device__ __half g_oh [(size_t)BT*DD];
__device__ __half g_m1h[(size_t)BT*II];
__device__ __half g_bt [(size_t)5632*DD];
__device__ float  g_cos[TT*64];
__device__ float  g_sin[TT*64];

// ---------------- rmsnorm -> fp16 out ----------------
__global__ void rmsnorm_kernel(const float* __restrict__ x, const float* __restrict__ w,
                               __half* __restrict__ out, float eps) {
    int row = blockIdx.x;
    const float4* xr = (const float4*)(x + (size_t)row * DD);
    float4 v = xr[threadIdx.x];
    float s = v.x * v.x + v.y * v.y + v.z * v.z + v.w * v.w;
    __shared__ float red[8];
    #pragma unroll
    for (int o = 16; o > 0; o >>= 1) s += __shfl_down_sync(0xffffffffu, s, o);
    if ((threadIdx.x & 31) == 0) red[threadIdx.x >> 5] = s;
    __syncthreads();
    if (threadIdx.x < 8) {
        s = red[threadIdx.x];
        #pragma unroll
        for (int o = 4; o > 0; o >>= 1) s += __shfl_down_sync(0xffu, s, o);
        if (threadIdx.x == 0) red[0] = s;
    }
    __syncthreads();
    float inv = rsqrtf(red[0] / (float)DD + eps);
    float4 wv = ((const float4*)w)[threadIdx.x];
    __half2* orow = (__half2*)(out + (size_t)row * DD);
    orow[threadIdx.x * 2]     = __floats2half2_rn(v.x * inv * wv.x, v.y * inv * wv.y);
    orow[threadIdx.x * 2 + 1] = __floats2half2_rn(v.z * inv * wv.z, v.w * inv * wv.w);
}

// ---------------- weight convert + transpose: W[K][N] fp32 -> Wt[N][K] fp16 ----------------
__global__ void convT_kernel(const float* __restrict__ W, __half* __restrict__ Wt,
                             int K, int N) {
    __shared__ float tile[32][33];
    int n0 = blockIdx.x * 32, k0 = blockIdx.y * 32;
    #pragma unroll
    for (int j = threadIdx.y; j < 32; j += 8)
        tile[j][threadIdx.x] = W[(size_t)(k0 + j) * N + n0 + threadIdx.x];
    __syncthreads();
    #pragma unroll
    for (int j = threadIdx.y; j < 32; j += 8)
        Wt[(size_t)(n0 + j) * K + k0 + threadIdx.x] = __float2half_rn(tile[threadIdx.x][j]);
}

// ================= fp16 tensor-core GEMM (HMMA + ldmatrix, BK=64, 2 CTA/SM) =================
#define BKH 64
#define XW 36
#define AW (128*XW)
#define BW (128*XW)
#define STG (AW+BW)
#define SMEM_GEMM (3*STG*4)

__device__ __forceinline__ void mma_fp16(float* c, const uint32_t* a, const uint32_t* b) {
    asm volatile("mma.sync.aligned.m16n8k16.row.col.f32.f16.f16.f32 "
        "{%0,%1,%2,%3}, {%4,%5,%6,%7}, {%8,%9}, {%0,%1,%2,%3};"
        : "+f"(c[0]), "+f"(c[1]), "+f"(c[2]), "+f"(c[3])
        : "r"(a[0]), "r"(a[1]), "r"(a[2]), "r"(a[3]), "r"(b[0]), "r"(b[1]));
}
__device__ __forceinline__ void cpasync16(uint32_t s, const void* g) {
    asm volatile("cp.async.cg.shared.global [%0], [%1], 16;" :: "r"(s), "l"(g));
}
__device__ __forceinline__ void ldsm_x4(uint32_t* r, uint32_t addr) {
    asm volatile("ldmatrix.sync.aligned.m8n8.x4.shared.b16 {%0,%1,%2,%3}, [%4];"
        : "=r"(r[0]), "=r"(r[1]), "=r"(r[2]), "=r"(r[3]) : "r"(addr));
}

__global__ __launch_bounds__(256, 2)
void hgemm_kernel(const __half* __restrict__ A, const __half* __restrict__ Bt,
                  const float* __restrict__ R, float* __restrict__ C,
                  int M, int N, int K) {
    extern __shared__ uint32_t smw[];

    const int tid = threadIdx.x;
    const int lane = tid & 31;
    const int w = tid >> 5;
    const int g = lane >> 2, q = lane & 3;
    const int wm = (w & 1) * 64;
    const int wn = (w >> 1) * 32;
    const int bm = blockIdx.y * 128, bn = blockIdx.x * 128;

    uint32_t sBase = (uint32_t)__cvta_generic_to_shared(smw);

    const uint32_t aLane = (uint32_t)((wm + (lane & 15)) * XW + ((lane >> 4) << 2));
    const uint32_t bLane = (uint32_t)((wn + (lane & 7) + ((lane >> 4) << 3)) * XW + (((lane >> 3) & 1) << 2));

    float acc[4][4][4];
    #pragma unroll
    for (int i = 0; i < 4; ++i)
        #pragma unroll
        for (int j = 0; j < 4; ++j)
            #pragma unroll
            for (int r = 0; r < 4; ++r) acc[i][j][r] = 0.f;

    const int ntile = K / BKH;

    auto loadTile = [&](int t, int s) {
        #pragma unroll
        for (int i = 0; i < 4; ++i) {
            int idx = i * 256 + tid;
            int row = idx >> 3, kc = (idx & 7) * 8;
            cpasync16(sBase + (uint32_t)((s * STG + row * XW) * 4 + kc * 2),
                      A + (size_t)(bm + row) * K + t * BKH + kc);
        }
        #pragma unroll
        for (int i = 0; i < 4; ++i) {
            int idx = i * 256 + tid;
            int n = idx >> 3, kc = (idx & 7) * 8;
            cpasync16(sBase + (uint32_t)((s * STG + AW + n * XW) * 4 + kc * 2),
                      Bt + (size_t)(bn + n) * K + t * BKH + kc);
        }
        asm volatile("cp.async.commit_group;");
    };

    loadTile(0, 0);
    if (ntile > 1) loadTile(1, 1);

    for (int t = 0; t < ntile; ++t) {
        int s = t % 3;
        if (t + 2 < ntile) asm volatile("cp.async.wait_group 1;");
        else               asm volatile("cp.async.wait_group 0;");
        __syncthreads();
        if (t + 2 < ntile) loadTile(t + 2, (t + 2) % 3);

        const uint32_t aOff = sBase + (uint32_t)(s * STG) * 4;
        const uint32_t bOff = sBase + (uint32_t)(s * STG + AW) * 4;
        #pragma unroll
        for (int ks = 0; ks < 4; ++ks) {
            uint32_t a[4][4], b[4][2];
            #pragma unroll
            for (int mt = 0; mt < 4; ++mt)
                ldsm_x4(a[mt], aOff + (aLane + (uint32_t)(mt * 16 * XW + ks * 8)) * 4);
            #pragma unroll
            for (int np = 0; np < 2; ++np) {
                uint32_t bb[4];
                ldsm_x4(bb, bOff + (bLane + (uint32_t)(np * 16 * XW + ks * 8)) * 4);
                b[np * 2][0]     = bb[0];
                b[np * 2][1]     = bb[1];
                b[np * 2 + 1][0] = bb[2];
                b[np * 2 + 1][1] = bb[3];
            }
            #pragma unroll
            for (int mt = 0; mt < 4; ++mt)
                #pragma unroll
                for (int nt = 0; nt < 4; ++nt)
                    mma_fp16(acc[mt][nt], a[mt], b[nt]);
        }
    }

    #pragma unroll
    for (int mt = 0; mt < 4; ++mt) {
        #pragma unroll
        for (int half = 0; half < 2; ++half) {
            int row = bm + wm + mt * 16 + g + half * 8;
            size_t rbase = (size_t)row * N + bn + wn;
            #pragma unroll
            for (int nt = 0; nt < 4; ++nt) {
                int col = nt * 8 + q * 2;
                float2 v;
                v.x = acc[mt][nt][half * 2 + 0];
                v.y = acc[mt][nt][half * 2 + 1];
                if (R) {
                    const float2 rr = *(const float2*)(R + rbase + col);
                    v.x += rr.x; v.y += rr.y;
                }
                *(float2*)(C + rbase + col) = v;
            }
        }
    }
}

// ---------------- conv(K=4)+silu+RoPE fused, fp16 out (q,k path) ----------------
// thread owns rotation pair: dims j..j+3 and j+64..j+67 of head h, 4 timesteps.
__global__ void conv_silu_rope_kernel(const float* __restrict__ x, const float* __restrict__ w,
                                      __half* __restrict__ y, int rs4) {
    int idx = blockIdx.x * 256 + threadIdx.x;    // BB * TT/4 * HH * 16 threads
    int j4 = idx & 15;
    int h  = (idx >> 4) & 7;
    int t4 = (idx >> 7) & 2047;
    int b  = idx >> 18;
    const float4* x4 = (const float4*)x;
    const float4* w4 = (const float4*)w;
    int d1 = h * 128 + j4 * 4;                   // first-half dims
    int c1 = d1 >> 2, c2 = c1 + 16;              // float4 cols
    float4 wa[4], wb[4];
    #pragma unroll
    for (int r = 0; r < 4; ++r) { wa[r] = w4[d1 + r]; wb[r] = w4[d1 + 64 + r]; }
    int t0 = t4 * 4;
    size_t inbase = (size_t)b * TT * rs4;
    float4 xv1[7], xv2[7];
    #pragma unroll
    for (int j = 0; j < 7; ++j) {
        int tt = t0 - 3 + j;
        if (tt >= 0) {
            xv1[j] = x4[inbase + (size_t)tt * rs4 + c1];
            xv2[j] = x4[inbase + (size_t)tt * rs4 + c2];
        } else {
            xv1[j] = make_float4(0.f, 0.f, 0.f, 0.f);
            xv2[j] = make_float4(0.f, 0.f, 0.f, 0.f);
        }
    }
    const float4* cos4 = (const float4*)g_cos;
    const float4* sin4 = (const float4*)g_sin;
    __half2* y2 = (__half2*)y;
    #pragma unroll
    for (int i = 0; i < 4; ++i) {
        float4 a1, a2;
        a1.x = xv1[i].x * wa[0].x + xv1[i+1].x * wa[0].y + xv1[i+2].x * wa[0].z + xv1[i+3].x * wa[0].w;
        a1.y = xv1[i].y * wa[1].x + xv1[i+1].y * wa[1].y + xv1[i+2].y * wa[1].z + xv1[i+3].y * wa[1].w;
        a1.z = xv1[i].z * wa[2].x + xv1[i+1].z * wa[2].y + xv1[i+2].z * wa[2].z + xv1[i+3].z * wa[2].w;
        a1.w = xv1[i].w * wa[3].x + xv1[i+1].w * wa[3].y + xv1[i+2].w * wa[3].z + xv1[i+3].w * wa[3].w;
        a2.x = xv2[i].x * wb[0].x + xv2[i+1].x * wb[0].y + xv2[i+2].x * wb[0].z + xv2[i+3].x * wb[0].w;
        a2.y = xv2[i].y * wb[1].x + xv2[i+1].y * wb[1].y + xv2[i+2].y * wb[1].z + xv2[i+3].y * wb[1].w;
        a2.z = xv2[i].z * wb[2].x + xv2[i+1].z * wb[2].y + xv2[i+2].z * wb[2].z + xv2[i+3].z * wb[2].w;
        a2.w = xv2[i].w * wb[3].x + xv2[i+1].w * wb[3].y + xv2[i+2].w * wb[3].z + xv2[i+3].w * wb[3].w;
        a1.x /= (1.f + expf(-a1.x)); a1.y /= (1.f + expf(-a1.y));
        a1.z /= (1.f + expf(-a1.z)); a1.w /= (1.f + expf(-a1.w));
        a2.x /= (1.f + expf(-a2.x)); a2.y /= (1.f + expf(-a2.y));
        a2.z /= (1.f + expf(-a2.z)); a2.w /= (1.f + expf(-a2.w));
        int t = t0 + i;
        float4 c = cos4[t * 16 + j4];
        float4 s = sin4[t * 16 + j4];
        float4 o1, o2;
        o1.x = a1.x * c.x - a2.x * s.x;  o2.x = a1.x * s.x + a2.x * c.x;
        o1.y = a1.y * c.y - a2.y * s.y;  o2.y = a1.y * s.y + a2.y * c.y;
        o1.z = a1.z * c.z - a2.z * s.z;  o2.z = a1.z * s.z + a2.z * c.z;
        o1.w = a1.w * c.w - a2.w * s.w;  o2.w = a1.w * s.w + a2.w * c.w;
        size_t base1 = (((size_t)(b * TT + t)) * DD + d1) >> 1;
        y2[base1]          = __floats2half2_rn(o1.x, o1.y);
        y2[base1 + 1]      = __floats2half2_rn(o1.z, o1.w);
        y2[base1 + 32]     = __floats2half2_rn(o2.x, o2.y);
        y2[base1 + 33]     = __floats2half2_rn(o2.z, o2.w);
    }
}

// ---------------- conv(K=4)+silu, fp16 out (v path) ----------------
__global__ void conv_silu_h_kernel(const float* __restrict__ x, const float* __restrict__ w,
                                   __half* __restrict__ y, int rs4) {
    int idx = blockIdx.x * 256 + threadIdx.x;
    int d4 = idx & 255;
    int rest = idx >> 8;
    int t4 = rest & (TT / 4 - 1);
    int b = rest >> 11;
    const float4* x4 = (const float4*)x;
    const float4* w4 = (const float4*)w;
    float4 wr0 = w4[d4 * 4 + 0], wr1 = w4[d4 * 4 + 1];
    float4 wr2 = w4[d4 * 4 + 2], wr3 = w4[d4 * 4 + 3];
    int t0 = t4 * 4;
    size_t inbase  = (size_t)b * TT * rs4 + d4;
    float4 xv[7];
    #pragma unroll
    for (int j = 0; j < 7; ++j) {
        int tt = t0 - 3 + j;
        xv[j] = (tt >= 0) ? x4[inbase + (size_t)tt * rs4] : make_float4(0.f, 0.f, 0.f, 0.f);
    }
    __half2* y2 = (__half2*)y;
    #pragma unroll
    for (int i = 0; i < 4; ++i) {
        float4 a;
        a.x = xv[i].x * wr0.x + xv[i+1].x * wr0.y + xv[i+2].x * wr0.z + xv[i+3].x * wr0.w;
        a.y = xv[i].y * wr1.x + xv[i+1].y * wr1.y + xv[i+2].y * wr1.z + xv[i+3].y * wr1.w;
        a.z = xv[i].z * wr2.x + xv[i+1].z * wr2.y + xv[i+2].z * wr2.z + xv[i+3].z * wr2.w;
        a.w = xv[i].w * wr3.x + xv[i+1].w * wr3.y + xv[i+2].w * wr3.z + xv[i+3].w * wr3.w;
        a.x /= (1.f + expf(-a.x)); a.y /= (1.f + expf(-a.y));
        a.z /= (1.f + expf(-a.z)); a.w /= (1.f + expf(-a.w));
        size_t bh = ((size_t)(b * TT + t0 + i)) * 512 + d4 * 2;
        y2[bh]     = __floats2half2_rn(a.x, a.y);
        y2[bh + 1] = __floats2half2_rn(a.z, a.w);
    }
}

// ---------------- RoPE table ----------------
__global__ void rope_table_kernel() {
    int idx = blockIdx.x * 256 + threadIdx.x;
    if (idx >= TT * 64) return;
    int t = idx >> 6, j = idx & 63;
    float invf = (float)(1.0 / pow(10000.0, (double)j / 64.0));
    float f = (float)t * invf;
    g_cos[idx] = (float)cos((double)f);
    g_sin[idx] = (float)sin((double)f);
}

// ---------------- retention phase 1 (fp16 in, fp16 S out) ----------------
__global__ void ret_phase1(const __half* __restrict__ k, const __half* __restrict__ v,
                           __half* __restrict__ S) {
    extern __shared__ float sm[];
    float* ks = sm;
    float* vs = sm + 64 * 129;
    int c = blockIdx.x, h = blockIdx.y, b = blockIdx.z;
    float gamma = 1.f - exp2f(-5.f - (float)h);
    float lg = logf(gamma);
    int tid = threadIdx.x;
    const __half2* k2 = (const __half2*)k;
    const __half2* v2 = (const __half2*)v;
    for (int x = tid; x < 4096; x += 256) {
        int i = x >> 6, d2 = x & 63;
        size_t gg = (((size_t)b * TT + c * 64 + i) * DD + h * 128) / 2 + d2;
        float dec = expf(lg * (float)(63 - i));
        float2 kf = __half22float2(k2[gg]);
        float2 vf = __half22float2(v2[gg]);
        ks[i * 129 + d2 * 2]     = kf.x * dec;
        ks[i * 129 + d2 * 2 + 1] = kf.y * dec;
        vs[i * 129 + d2 * 2]     = vf.x;
        vs[i * 129 + d2 * 2 + 1] = vf.y;
    }
    __syncthreads();
    int w = tid >> 5, lane = tid & 31;
    int d0 = w * 16 + (lane >> 3) * 4;
    int e0 = (lane & 7) * 16;
    float acc[4][16];
    #pragma unroll
    for (int i = 0; i < 4; ++i)
        #pragma unroll
        for (int j = 0; j < 16; ++j) acc[i][j] = 0.f;
    #pragma unroll 4
    for (int j = 0; j < 64; ++j) {
        float kr[4], vr[16];
        #pragma unroll
        for (int i = 0; i < 4; ++i) kr[i] = ks[j * 129 + d0 + i];
        #pragma unroll
        for (int e = 0; e < 16; ++e) vr[e] = vs[j * 129 + e0 + e];
        #pragma unroll
        for (int i = 0; i < 4; ++i)
            #pragma unroll
            for (int e = 0; e < 16; ++e) acc[i][e] = fmaf(kr[i], vr[e], acc[i][e]);
    }
    size_t sb = (((size_t)(b * HH + h)) * NC + c) * 16384;
    __half2* S2 = (__half2*)S;
    #pragma unroll
    for (int i = 0; i < 4; ++i)
        #pragma unroll
        for (int e = 0; e < 16; e += 2)
            S2[(sb + (d0 + i) * 128 + e0 + e) >> 1] = __floats2half2_rn(acc[i][e], acc[i][e + 1]);
}

// ---------------- retention phase 2: parallel exclusive scan (half2) ----------------
__global__ void ret_scan(__half* __restrict__ S) {
    int bh = blockIdx.x >> 5;
    int pairIdx = ((blockIdx.x & 31) << 8) + threadIdx.x;   // 0..8191
    int h = bh & 7;
    float gamma = 1.f - exp2f(-5.f - (float)h);
    float cdec = expf(logf(gamma) * 64.f);
    float2 carry = make_float2(0.f, 0.f);
    __half2* S2 = (__half2*)S;
    size_t base = (size_t)bh * NC * 8192 + pairIdx;
    for (int c = 0; c < NC; ++c) {
        size_t idx = base + (size_t)c * 8192;
        float2 loc = __half22float2(S2[idx]);
        S2[idx] = __floats2half2_rn(carry.x, carry.y);
        carry.x = carry.x * cdec + loc.x;
        carry.y = carry.y * cdec + loc.y;
    }
}

// ---------------- retention phase 3 (fp16 in, fp32 out) ----------------
__global__ void ret_phase3(const __half* __restrict__ q, const __half* __restrict__ k,
                           const __half* __restrict__ v, const __half* __restrict__ S,
                           float* __restrict__ o) {
    extern __shared__ float sm[];
    float* qs  = sm;
    float* ks  = qs + 64 * 129;
    float* vs  = ks + 64 * 129;
    float* Ps  = vs + 64 * 129;
    float* att = Ps + 128 * 129;
    int c = blockIdx.x, h = blockIdx.y, b = blockIdx.z;
    float gamma = 1.f - exp2f(-5.f - (float)h);
    float lg = logf(gamma);
    const float scale = 0.08838834764831845f;
    int tid = threadIdx.x;
    int lane = tid & 31;
    const __half2* q2 = (const __half2*)q;
    const __half2* k2 = (const __half2*)k;
    const __half2* v2 = (const __half2*)v;
    for (int x = tid; x < 4096; x += 256) {
        int i = x >> 6, d2 = x & 63;
        size_t gg = (((size_t)b * TT + c * 64 + i) * DD + h * 128) / 2 + d2;
        float2 qf = __half22float2(q2[gg]);
        float2 kf = __half22float2(k2[gg]);
        float2 vf = __half22float2(v2[gg]);
        qs[i * 129 + d2 * 2]     = qf.x * scale;
        qs[i * 129 + d2 * 2 + 1] = qf.y * scale;
        ks[i * 129 + d2 * 2]     = kf.x;
        ks[i * 129 + d2 * 2 + 1] = kf.y;
        vs[i * 129 + d2 * 2]     = vf.x;
        vs[i * 129 + d2 * 2 + 1] = vf.y;
    }
    size_t sb = (((size_t)(b * HH + h)) * NC + c) * 16384;
    const __half2* S2 = (const __half2*)S;
    for (int x = tid; x < 8192; x += 256) {
        int d = x >> 6, e2 = x & 63;
        float2 sf = __half22float2(S2[(sb >> 1) + d * 64 + e2]);
        Ps[d * 129 + e2 * 2]     = sf.x;
        Ps[d * 129 + e2 * 2 + 1] = sf.y;
    }
    __syncthreads();
    {
        int i0 = (tid >> 4) * 4;
        int j0 = (tid & 15) * 4;
        float a4[4][4];
        #pragma unroll
        for (int i = 0; i < 4; ++i)
            #pragma unroll
            for (int j = 0; j < 4; ++j) a4[i][j] = 0.f;
        #pragma unroll 4
        for (int d = 0; d < 128; ++d) {
            float qr[4], kr[4];
            #pragma unroll
            for (int i = 0; i < 4; ++i) qr[i] = qs[(i0 + i) * 129 + d];
            #pragma unroll
            for (int j = 0; j < 4; ++j) kr[j] = ks[(j0 + j) * 129 + d];
            #pragma unroll
            for (int i = 0; i < 4; ++i)
                #pragma unroll
                for (int j = 0; j < 4; ++j) a4[i][j] = fmaf(qr[i], kr[j], a4[i][j]);
        }
        #pragma unroll
        for (int i = 0; i < 4; ++i)
            #pragma unroll
            for (int j = 0; j < 4; ++j) {
                int ia = i0 + i, ja = j0 + j;
                float f = (ia >= ja) ? expf(lg * (float)(ia - ja)) : 0.f;
                att[ia * 65 + ja] = a4[i][j] * f;
            }
    }
    __syncthreads();
    {
        int i0 = (tid >> 5) * 8 + (lane >> 4) * 4;
        int e0 = (lane & 15) * 8;
        float accA[4][8], accB[4][8];
        #pragma unroll
        for (int i = 0; i < 4; ++i)
            #pragma unroll
            for (int e = 0; e < 8; ++e) { accA[i][e] = 0.f; accB[i][e] = 0.f; }
        #pragma unroll 4
        for (int j = 0; j < 64; ++j) {
            float ar[4], vr[8];
            #pragma unroll
            for (int i = 0; i < 4; ++i) ar[i] = att[(i0 + i) * 65 + j];
            #pragma unroll
            for (int e = 0; e < 8; ++e) vr[e] = vs[j * 129 + e0 + e];
            #pragma unroll
            for (int i = 0; i < 4; ++i)
                #pragma unroll
                for (int e = 0; e < 8; ++e) accA[i][e] = fmaf(ar[i], vr[e], accA[i][e]);
        }
        #pragma unroll 4
        for (int d = 0; d < 128; ++d) {
            float qr[4], pr[8];
            #pragma unroll
            for (int i = 0; i < 4; ++i) qr[i] = qs[(i0 + i) * 129 + d];
            #pragma unroll
            for (int e = 0; e < 8; ++e) pr[e] = Ps[d * 129 + e0 + e];
            #pragma unroll
            for (int i = 0; i < 4; ++i)
                #pragma unroll
                for (int e = 0; e < 8; ++e) accB[i][e] = fmaf(qr[i], pr[e], accB[i][e]);
        }
        #pragma unroll
        for (int i = 0; i < 4; ++i) {
            float crossf = expf(lg * (float)(i0 + i + 1));
            size_t ob = ((size_t)b * TT + c * 64 + i0 + i) * DD + h * 128 + e0;
            #pragma unroll
            for (int e = 0; e < 8; ++e)
                o[ob + e] = accA[i][e] + crossf * accB[i][e];
        }
    }
}

// ---------------- gating -> fp16 out ----------------
__global__ void gate_kernel(const float* __restrict__ o, const float* __restrict__ gbig,
                            const float* __restrict__ w, __half* __restrict__ oh) {
    int row = blockIdx.x * 8 + (threadIdx.x >> 5);
    int lane = threadIdx.x & 31;
    int bt = row >> 3, h = row & 7;
    const float4* orow = (const float4*)(o + (size_t)row * 128);
    const float4* grow = (const float4*)(gbig + (size_t)bt * 4096 + 3072 + h * 128);
    float4 v = orow[lane];
    float s = v.x * v.x + v.y * v.y + v.z * v.z + v.w * v.w;
    #pragma unroll
    for (int off = 16; off > 0; off >>= 1) s += __shfl_xor_sync(0xffffffffu, s, off);
    float inv = rsqrtf(s / 128.f + GATE_EPS);
    float4 gv = grow[lane];
    float4 wv = ((const float4*)w)[lane];
    float rx = v.x * inv * wv.x * (gv.x / (1.f + expf(-gv.x)));
    float ry = v.y * inv * wv.y * (gv.y / (1.f + expf(-gv.y)));
    float rz = v.z * inv * wv.z * (gv.z / (1.f + expf(-gv.z)));
    float rw = v.w * inv * wv.w * (gv.w / (1.f + expf(-gv.w)));
    __half2* dst = (__half2*)(oh + (size_t)row * 128);
    dst[lane * 2]     = __floats2half2_rn(rx, ry);
    dst[lane * 2 + 1] = __floats2half2_rn(rz, rw);
}

// ---------------- swiglu fused ----------------
__global__ void swiglu_kernel(const float* __restrict__ mm, __half* __restrict__ outh) {
    int row = blockIdx.x;
    const float4* a  = (const float4*)(mm + (size_t)row * 5632);
    const float4* b2 = a + 704;
    __half2* dst = (__half2*)(outh + (size_t)row * 2816);
    for (int c = threadIdx.x; c < 704; c += 256) {
        float4 x = a[c];
        float4 y = b2[c];
        float rx = (x.x / (1.f + expf(-x.x))) * y.x;
        float ry = (x.y / (1.f + expf(-x.y))) * y.y;
        float rz = (x.z / (1.f + expf(-x.z))) * y.z;
        float rw = (x.w / (1.f + expf(-x.w))) * y.w;
        dst[c * 2]     = __floats2half2_rn(rx, ry);
        dst[c * 2 + 1] = __floats2half2_rn(rz, rw);
    }
}

// ---------------- launch ----------------
extern "C" void kernel_launch(void* const* d_in, const int* in_sizes, int n_in,
                              void* d_out, int out_size) {
    const float* hs    = (const float*)d_in[0];
    const float* ln1   = (const float*)d_in[1];
    const float* ln2   = (const float*)d_in[2];
    const float* wq    = (const float*)d_in[3];
    const float* wk    = (const float*)d_in[4];
    const float* wv    = (const float*)d_in[5];
    const float* wg    = (const float*)d_in[6];
    const float* wo    = (const float*)d_in[7];
    const float* cq    = (const float*)d_in[8];
    const float* ck    = (const float*)d_in[9];
    const float* cv    = (const float*)d_in[10];
    const float* gn    = (const float*)d_in[11];
    const float* wgate = (const float*)d_in[12];
    const float* wup   = (const float*)d_in[13];
    const float* wdown = (const float*)d_in[14];
    float* out = (float*)d_out;

    cudaFuncSetAttribute(hgemm_kernel, cudaFuncAttributeMaxDynamicSharedMemorySize, SMEM_GEMM);
    cudaFuncSetAttribute(ret_phase1, cudaFuncAttributeMaxDynamicSharedMemorySize, 2 * 64 * 129 * 4);
    cudaFuncSetAttribute(ret_phase3, cudaFuncAttributeMaxDynamicSharedMemorySize,
                         (3 * 64 * 129 + 128 * 129 + 64 * 65) * 4);

    float *big, *mm, *o, *hbuf;
    __half *qh, *kh, *vh, *Sh, *xh, *oh, *m1h, *bt;
    cudaGetSymbolAddress((void**)&big, g_big);
    cudaGetSymbolAddress((void**)&mm,  g_mm);
    cudaGetSymbolAddress((void**)&qh,  g_qh);
    cudaGetSymbolAddress((void**)&kh,  g_kh);
    cudaGetSymbolAddress((void**)&vh,  g_vh);
    cudaGetSymbolAddress((void**)&o,   g_o);
    cudaGetSymbolAddress((void**)&hbuf, g_h);
    cudaGetSymbolAddress((void**)&Sh,  g_Sh);
    cudaGetSymbolAddress((void**)&xh,  g_xh);
    cudaGetSymbolAddress((void**)&oh,  g_oh);
    cudaGetSymbolAddress((void**)&m1h, g_m1h);
    cudaGetSymbolAddress((void**)&bt,  g_bt);

    rope_table_kernel<<<(TT * 64 + 255) / 256, 256>>>();
    rmsnorm_kernel<<<BT, 256>>>(hs, ln1, xh, RMS_EPS);

    dim3 tD(DD / 32, DD / 32), tI1(II / 32, DD / 32), tI2(DD / 32, II / 32), tb(32, 8);

    convT_kernel<<<tD, tb>>>(wq, bt,             DD, DD);
    convT_kernel<<<tD, tb>>>(wk, bt + 1024 * DD, DD, DD);
    convT_kernel<<<tD, tb>>>(wv, bt + 2048 * DD, DD, DD);
    convT_kernel<<<tD, tb>>>(wg, bt + 3072 * DD, DD, DD);
    dim3 gQKVG(4096 / 128, BT / 128);
    hgemm_kernel<<<gQKVG, 256, SMEM_GEMM>>>(xh, bt, nullptr, big, BT, 4096, DD);

    const int crblocks = (BB * (TT / 4) * HH * 16) / 256;   // 4096
    const int cvblocks = BB * TT / 4;                        // 8192
    conv_silu_rope_kernel<<<crblocks, 256>>>(big,        cq, qh, 1024);
    conv_silu_rope_kernel<<<crblocks, 256>>>(big + 1024, ck, kh, 1024);
    conv_silu_h_kernel<<<cvblocks, 256>>>(big + 2048, cv, vh, 1024);

    dim3 gc(NC, HH, BB);
    ret_phase1<<<gc, 256, 2 * 64 * 129 * 4>>>(kh, vh, Sh);
    ret_scan<<<BB * HH * 32, 256>>>(Sh);
    ret_phase3<<<gc, 256, (3 * 64 * 129 + 128 * 129 + 64 * 65) * 4>>>(qh, kh, vh, Sh, o);

    gate_kernel<<<(BT * HH) / 8, 256>>>(o, big, gn, oh);
    convT_kernel<<<tD, tb>>>(wo, bt, DD, DD);
    dim3 gD(DD / 128, BT / 128);
    hgemm_kernel<<<gD, 256, SMEM_GEMM>>>(oh, bt, hs, hbuf, BT, DD, DD);

    rmsnorm_kernel<<<BT, 256>>>(hbuf, ln2, xh, RMS_EPS);
    convT_kernel<<<tI1, tb>>>(wgate, bt,             DD, II);
    convT_kernel<<<tI1, tb>>>(wup,   bt + 2816 * DD, DD, II);
    dim3 gMLP(5632 / 128, BT / 128);
    hgemm_kernel<<<gMLP, 256, SMEM_GEMM>>>(xh, bt, nullptr, mm, BT, 5632, DD);
    swiglu_kernel<<<BT, 256>>>(mm, m1h);
    convT_kernel<<<tI2, tb>>>(wdown, bt, II, DD);
    hgemm_kernel<<<gD, 256, SMEM_GEMM>>>(m1h, bt, hbuf, out, BT, DD, II);
}

// round 10
// speedup vs baseline: 5.2945x; 1.0214x over previous
#include <cuda_runtime.h>
#include <cuda_fp16.h>
#include <math.h>
#include <stdint.h>

#define BB 4
#define TT 8192
#define DD 1024
#define HH 8
#define II 2816
#define NC 128
#define BT (BB*TT)

#define RMS_EPS 1e-6f
#define GATE_EPS 1e-5f

// ---------------- scratch ----------------
__device__ __half g_big[(size_t)BT*4096];     // fused qkvg output (fp16)
__device__ __half g_qh [(size_t)BT*DD];
__device__ __half g_kh [(size_t)BT*DD];
__device__ __half g_vh [(size_t)BT*DD];
__device__ float  g_o [(size_t)BT*DD];
__device__ float  g_h [(size_t)BT*DD];
__device__ __half g_Sh[(size_t)BB*HH*NC*128*128];
__device__ __half g_xh [(size_t)BT*DD];
__device__ __half g_oh [(size_t)BT*DD];
__device__ __half g_m1h[(size_t)BT*II];
__device__ __half g_bt [(size_t)5632*DD];
__device__ float  g_cos[TT*64];
__device__ float  g_sin[TT*64];

// ---------------- helpers ----------------
__device__ __forceinline__ float4 ldh4(const __half* p) {
    uint2 u = *(const uint2*)p;
    float2 f0 = __half22float2(*(__half2*)&u.x);
    float2 f1 = __half22float2(*(__half2*)&u.y);
    return make_float4(f0.x, f0.y, f1.x, f1.y);
}

// ---------------- rmsnorm -> fp16 out ----------------
__global__ void rmsnorm_kernel(const float* __restrict__ x, const float* __restrict__ w,
                               __half* __restrict__ out, float eps) {
    int row = blockIdx.x;
    const float4* xr = (const float4*)(x + (size_t)row * DD);
    float4 v = xr[threadIdx.x];
    float s = v.x * v.x + v.y * v.y + v.z * v.z + v.w * v.w;
    __shared__ float red[8];
    #pragma unroll
    for (int o = 16; o > 0; o >>= 1) s += __shfl_down_sync(0xffffffffu, s, o);
    if ((threadIdx.x & 31) == 0) red[threadIdx.x >> 5] = s;
    __syncthreads();
    if (threadIdx.x < 8) {
        s = red[threadIdx.x];
        #pragma unroll
        for (int o = 4; o > 0; o >>= 1) s += __shfl_down_sync(0xffu, s, o);
        if (threadIdx.x == 0) red[0] = s;
    }
    __syncthreads();
    float inv = rsqrtf(red[0] / (float)DD + eps);
    float4 wv = ((const float4*)w)[threadIdx.x];
    __half2* orow = (__half2*)(out + (size_t)row * DD);
    orow[threadIdx.x * 2]     = __floats2half2_rn(v.x * inv * wv.x, v.y * inv * wv.y);
    orow[threadIdx.x * 2 + 1] = __floats2half2_rn(v.z * inv * wv.z, v.w * inv * wv.w);
}

// ---------------- weight convert + transpose with row remap ----------------
// Wt[(n*rs + ro)*K + k] = fp16(W[k*N + n])
__global__ void convT_kernel(const float* __restrict__ W, __half* __restrict__ Wt,
                             int K, int N, int rs, int ro) {
    __shared__ float tile[32][33];
    int n0 = blockIdx.x * 32, k0 = blockIdx.y * 32;
    #pragma unroll
    for (int j = threadIdx.y; j < 32; j += 8)
        tile[j][threadIdx.x] = W[(size_t)(k0 + j) * N + n0 + threadIdx.x];
    __syncthreads();
    #pragma unroll
    for (int j = threadIdx.y; j < 32; j += 8)
        Wt[((size_t)(n0 + j) * rs + ro) * K + k0 + threadIdx.x] = __float2half_rn(tile[threadIdx.x][j]);
}

// ================= fp16 tensor-core GEMM (HMMA + ldmatrix, BK=64, 2 CTA/SM) =================
// MODE 0: fp32 C (+optional fp32 R).  MODE 1: fp16 C.  MODE 2: swiglu fp16 C (N halved).
#define BKH 64
#define XW 36
#define AW (128*XW)
#define BW (128*XW)
#define STG (AW+BW)
#define SMEM_GEMM (3*STG*4)

__device__ __forceinline__ void mma_fp16(float* c, const uint32_t* a, const uint32_t* b) {
    asm volatile("mma.sync.aligned.m16n8k16.row.col.f32.f16.f16.f32 "
        "{%0,%1,%2,%3}, {%4,%5,%6,%7}, {%8,%9}, {%0,%1,%2,%3};"
        : "+f"(c[0]), "+f"(c[1]), "+f"(c[2]), "+f"(c[3])
        : "r"(a[0]), "r"(a[1]), "r"(a[2]), "r"(a[3]), "r"(b[0]), "r"(b[1]));
}
__device__ __forceinline__ void cpasync16(uint32_t s, const void* g) {
    asm volatile("cp.async.cg.shared.global [%0], [%1], 16;" :: "r"(s), "l"(g));
}
__device__ __forceinline__ void ldsm_x4(uint32_t* r, uint32_t addr) {
    asm volatile("ldmatrix.sync.aligned.m8n8.x4.shared.b16 {%0,%1,%2,%3}, [%4];"
        : "=r"(r[0]), "=r"(r[1]), "=r"(r[2]), "=r"(r[3]) : "r"(addr));
}

template <int MODE>
__global__ __launch_bounds__(256, 2)
void hgemm_t(const __half* __restrict__ A, const __half* __restrict__ Bt,
             const float* __restrict__ R, void* __restrict__ Cv,
             int M, int N, int K) {
    extern __shared__ uint32_t smw[];

    const int tid = threadIdx.x;
    const int lane = tid & 31;
    const int w = tid >> 5;
    const int g = lane >> 2, q = lane & 3;
    const int wm = (w & 1) * 64;
    const int wn = (w >> 1) * 32;
    const int bm = blockIdx.y * 128, bn = blockIdx.x * 128;

    uint32_t sBase = (uint32_t)__cvta_generic_to_shared(smw);

    const uint32_t aLane = (uint32_t)((wm + (lane & 15)) * XW + ((lane >> 4) << 2));
    const uint32_t bLane = (uint32_t)((wn + (lane & 7) + ((lane >> 4) << 3)) * XW + (((lane >> 3) & 1) << 2));

    float acc[4][4][4];
    #pragma unroll
    for (int i = 0; i < 4; ++i)
        #pragma unroll
        for (int j = 0; j < 4; ++j)
            #pragma unroll
            for (int r = 0; r < 4; ++r) acc[i][j][r] = 0.f;

    const int ntile = K / BKH;

    auto loadTile = [&](int t, int s) {
        #pragma unroll
        for (int i = 0; i < 4; ++i) {
            int idx = i * 256 + tid;
            int row = idx >> 3, kc = (idx & 7) * 8;
            cpasync16(sBase + (uint32_t)((s * STG + row * XW) * 4 + kc * 2),
                      A + (size_t)(bm + row) * K + t * BKH + kc);
        }
        #pragma unroll
        for (int i = 0; i < 4; ++i) {
            int idx = i * 256 + tid;
            int n = idx >> 3, kc = (idx & 7) * 8;
            cpasync16(sBase + (uint32_t)((s * STG + AW + n * XW) * 4 + kc * 2),
                      Bt + (size_t)(bn + n) * K + t * BKH + kc);
        }
        asm volatile("cp.async.commit_group;");
    };

    loadTile(0, 0);
    if (ntile > 1) loadTile(1, 1);

    for (int t = 0; t < ntile; ++t) {
        int s = t % 3;
        if (t + 2 < ntile) asm volatile("cp.async.wait_group 1;");
        else               asm volatile("cp.async.wait_group 0;");
        __syncthreads();
        if (t + 2 < ntile) loadTile(t + 2, (t + 2) % 3);

        const uint32_t aOff = sBase + (uint32_t)(s * STG) * 4;
        const uint32_t bOff = sBase + (uint32_t)(s * STG + AW) * 4;
        #pragma unroll
        for (int ks = 0; ks < 4; ++ks) {
            uint32_t a[4][4], b[4][2];
            #pragma unroll
            for (int mt = 0; mt < 4; ++mt)
                ldsm_x4(a[mt], aOff + (aLane + (uint32_t)(mt * 16 * XW + ks * 8)) * 4);
            #pragma unroll
            for (int np = 0; np < 2; ++np) {
                uint32_t bb[4];
                ldsm_x4(bb, bOff + (bLane + (uint32_t)(np * 16 * XW + ks * 8)) * 4);
                b[np * 2][0]     = bb[0];
                b[np * 2][1]     = bb[1];
                b[np * 2 + 1][0] = bb[2];
                b[np * 2 + 1][1] = bb[3];
            }
            #pragma unroll
            for (int mt = 0; mt < 4; ++mt)
                #pragma unroll
                for (int nt = 0; nt < 4; ++nt)
                    mma_fp16(acc[mt][nt], a[mt], b[nt]);
        }
    }

    #pragma unroll
    for (int mt = 0; mt < 4; ++mt) {
        #pragma unroll
        for (int half = 0; half < 2; ++half) {
            int row = bm + wm + mt * 16 + g + half * 8;
            #pragma unroll
            for (int nt = 0; nt < 4; ++nt) {
                float vx = acc[mt][nt][half * 2 + 0];
                float vy = acc[mt][nt][half * 2 + 1];
                if (MODE == 0) {
                    int col = bn + wn + nt * 8 + q * 2;
                    size_t off = (size_t)row * N + col;
                    float* C = (float*)Cv;
                    float2 v2;
                    v2.x = vx; v2.y = vy;
                    if (R) {
                        const float2 rr = *(const float2*)(R + off);
                        v2.x += rr.x; v2.y += rr.y;
                    }
                    *(float2*)(C + off) = v2;
                } else if (MODE == 1) {
                    int col = bn + wn + nt * 8 + q * 2;
                    __half2* C = (__half2*)Cv;
                    C[((size_t)row * N + col) >> 1] = __floats2half2_rn(vx, vy);
                } else {
                    // even col = gate, odd col = up
                    int oc = (bn + wn) / 2 + nt * 4 + q;
                    float r = (vx / (1.f + expf(-vx))) * vy;
                    __half* C = (__half*)Cv;
                    C[(size_t)row * (N >> 1) + oc] = __float2half_rn(r);
                }
            }
        }
    }
}

// ---------------- conv(K=4)+silu+RoPE fused, fp16 in/out (q,k path) ----------------
__global__ void conv_silu_rope_kernel(const __half* __restrict__ x, const float* __restrict__ w,
                                      __half* __restrict__ y) {
    int idx = blockIdx.x * 256 + threadIdx.x;
    int j4 = idx & 15;
    int h  = (idx >> 4) & 7;
    int t4 = (idx >> 7) & 2047;
    int b  = idx >> 18;
    const float4* w4 = (const float4*)w;
    int d1 = h * 128 + j4 * 4;
    float4 wa[4], wb[4];
    #pragma unroll
    for (int r = 0; r < 4; ++r) { wa[r] = w4[d1 + r]; wb[r] = w4[d1 + 64 + r]; }
    int t0 = t4 * 4;
    float4 xv1[7], xv2[7];
    #pragma unroll
    for (int j = 0; j < 7; ++j) {
        int tt = t0 - 3 + j;
        if (tt >= 0) {
            const __half* p = x + ((size_t)(b * TT + tt)) * 4096 + d1;
            xv1[j] = ldh4(p);
            xv2[j] = ldh4(p + 64);
        } else {
            xv1[j] = make_float4(0.f, 0.f, 0.f, 0.f);
            xv2[j] = make_float4(0.f, 0.f, 0.f, 0.f);
        }
    }
    const float4* cos4 = (const float4*)g_cos;
    const float4* sin4 = (const float4*)g_sin;
    __half2* y2 = (__half2*)y;
    #pragma unroll
    for (int i = 0; i < 4; ++i) {
        float4 a1, a2;
        a1.x = xv1[i].x * wa[0].x + xv1[i+1].x * wa[0].y + xv1[i+2].x * wa[0].z + xv1[i+3].x * wa[0].w;
        a1.y = xv1[i].y * wa[1].x + xv1[i+1].y * wa[1].y + xv1[i+2].y * wa[1].z + xv1[i+3].y * wa[1].w;
        a1.z = xv1[i].z * wa[2].x + xv1[i+1].z * wa[2].y + xv1[i+2].z * wa[2].z + xv1[i+3].z * wa[2].w;
        a1.w = xv1[i].w * wa[3].x + xv1[i+1].w * wa[3].y + xv1[i+2].w * wa[3].z + xv1[i+3].w * wa[3].w;
        a2.x = xv2[i].x * wb[0].x + xv2[i+1].x * wb[0].y + xv2[i+2].x * wb[0].z + xv2[i+3].x * wb[0].w;
        a2.y = xv2[i].y * wb[1].x + xv2[i+1].y * wb[1].y + xv2[i+2].y * wb[1].z + xv2[i+3].y * wb[1].w;
        a2.z = xv2[i].z * wb[2].x + xv2[i+1].z * wb[2].y + xv2[i+2].z * wb[2].z + xv2[i+3].z * wb[2].w;
        a2.w = xv2[i].w * wb[3].x + xv2[i+1].w * wb[3].y + xv2[i+2].w * wb[3].z + xv2[i+3].w * wb[3].w;
        a1.x /= (1.f + expf(-a1.x)); a1.y /= (1.f + expf(-a1.y));
        a1.z /= (1.f + expf(-a1.z)); a1.w /= (1.f + expf(-a1.w));
        a2.x /= (1.f + expf(-a2.x)); a2.y /= (1.f + expf(-a2.y));
        a2.z /= (1.f + expf(-a2.z)); a2.w /= (1.f + expf(-a2.w));
        int t = t0 + i;
        float4 c = cos4[t * 16 + j4];
        float4 s = sin4[t * 16 + j4];
        float4 o1, o2;
        o1.x = a1.x * c.x - a2.x * s.x;  o2.x = a1.x * s.x + a2.x * c.x;
        o1.y = a1.y * c.y - a2.y * s.y;  o2.y = a1.y * s.y + a2.y * c.y;
        o1.z = a1.z * c.z - a2.z * s.z;  o2.z = a1.z * s.z + a2.z * c.z;
        o1.w = a1.w * c.w - a2.w * s.w;  o2.w = a1.w * s.w + a2.w * c.w;
        size_t base1 = (((size_t)(b * TT + t)) * DD + d1) >> 1;
        y2[base1]      = __floats2half2_rn(o1.x, o1.y);
        y2[base1 + 1]  = __floats2half2_rn(o1.z, o1.w);
        y2[base1 + 32] = __floats2half2_rn(o2.x, o2.y);
        y2[base1 + 33] = __floats2half2_rn(o2.z, o2.w);
    }
}

// ---------------- conv(K=4)+silu, fp16 in/out (v path; input at col offset 2048) ----------------
__global__ void conv_silu_h_kernel(const __half* __restrict__ x, const float* __restrict__ w,
                                   __half* __restrict__ y) {
    int idx = blockIdx.x * 256 + threadIdx.x;
    int d4 = idx & 255;
    int rest = idx >> 8;
    int t4 = rest & (TT / 4 - 1);
    int b = rest >> 11;
    const float4* w4 = (const float4*)w;
    float4 wr0 = w4[d4 * 4 + 0], wr1 = w4[d4 * 4 + 1];
    float4 wr2 = w4[d4 * 4 + 2], wr3 = w4[d4 * 4 + 3];
    int t0 = t4 * 4;
    float4 xv[7];
    #pragma unroll
    for (int j = 0; j < 7; ++j) {
        int tt = t0 - 3 + j;
        xv[j] = (tt >= 0) ? ldh4(x + ((size_t)(b * TT + tt)) * 4096 + d4 * 4)
                          : make_float4(0.f, 0.f, 0.f, 0.f);
    }
    __half2* y2 = (__half2*)y;
    #pragma unroll
    for (int i = 0; i < 4; ++i) {
        float4 a;
        a.x = xv[i].x * wr0.x + xv[i+1].x * wr0.y + xv[i+2].x * wr0.z + xv[i+3].x * wr0.w;
        a.y = xv[i].y * wr1.x + xv[i+1].y * wr1.y + xv[i+2].y * wr1.z + xv[i+3].y * wr1.w;
        a.z = xv[i].z * wr2.x + xv[i+1].z * wr2.y + xv[i+2].z * wr2.z + xv[i+3].z * wr2.w;
        a.w = xv[i].w * wr3.x + xv[i+1].w * wr3.y + xv[i+2].w * wr3.z + xv[i+3].w * wr3.w;
        a.x /= (1.f + expf(-a.x)); a.y /= (1.f + expf(-a.y));
        a.z /= (1.f + expf(-a.z)); a.w /= (1.f + expf(-a.w));
        size_t bh = ((size_t)(b * TT + t0 + i)) * 512 + d4 * 2;
        y2[bh]     = __floats2half2_rn(a.x, a.y);
        y2[bh + 1] = __floats2half2_rn(a.z, a.w);
    }
}

// ---------------- RoPE table ----------------
__global__ void rope_table_kernel() {
    int idx = blockIdx.x * 256 + threadIdx.x;
    if (idx >= TT * 64) return;
    int t = idx >> 6, j = idx & 63;
    float invf = (float)(1.0 / pow(10000.0, (double)j / 64.0));
    float f = (float)t * invf;
    g_cos[idx] = (float)cos((double)f);
    g_sin[idx] = (float)sin((double)f);
}

// ---------------- retention phase 1 (fp16 in, fp16 S out) ----------------
__global__ void ret_phase1(const __half* __restrict__ k, const __half* __restrict__ v,
                           __half* __restrict__ S) {
    extern __shared__ float sm[];
    float* ks = sm;
    float* vs = sm + 64 * 129;
    int c = blockIdx.x, h = blockIdx.y, b = blockIdx.z;
    float gamma = 1.f - exp2f(-5.f - (float)h);
    float lg = logf(gamma);
    int tid = threadIdx.x;
    const __half2* k2 = (const __half2*)k;
    const __half2* v2 = (const __half2*)v;
    for (int x = tid; x < 4096; x += 256) {
        int i = x >> 6, d2 = x & 63;
        size_t gg = (((size_t)b * TT + c * 64 + i) * DD + h * 128) / 2 + d2;
        float dec = expf(lg * (float)(63 - i));
        float2 kf = __half22float2(k2[gg]);
        float2 vf = __half22float2(v2[gg]);
        ks[i * 129 + d2 * 2]     = kf.x * dec;
        ks[i * 129 + d2 * 2 + 1] = kf.y * dec;
        vs[i * 129 + d2 * 2]     = vf.x;
        vs[i * 129 + d2 * 2 + 1] = vf.y;
    }
    __syncthreads();
    int w = tid >> 5, lane = tid & 31;
    int d0 = w * 16 + (lane >> 3) * 4;
    int e0 = (lane & 7) * 16;
    float acc[4][16];
    #pragma unroll
    for (int i = 0; i < 4; ++i)
        #pragma unroll
        for (int j = 0; j < 16; ++j) acc[i][j] = 0.f;
    #pragma unroll 4
    for (int j = 0; j < 64; ++j) {
        float kr[4], vr[16];
        #pragma unroll
        for (int i = 0; i < 4; ++i) kr[i] = ks[j * 129 + d0 + i];
        #pragma unroll
        for (int e = 0; e < 16; ++e) vr[e] = vs[j * 129 + e0 + e];
        #pragma unroll
        for (int i = 0; i < 4; ++i)
            #pragma unroll
            for (int e = 0; e < 16; ++e) acc[i][e] = fmaf(kr[i], vr[e], acc[i][e]);
    }
    size_t sb = (((size_t)(b * HH + h)) * NC + c) * 16384;
    __half2* S2 = (__half2*)S;
    #pragma unroll
    for (int i = 0; i < 4; ++i)
        #pragma unroll
        for (int e = 0; e < 16; e += 2)
            S2[(sb + (d0 + i) * 128 + e0 + e) >> 1] = __floats2half2_rn(acc[i][e], acc[i][e + 1]);
}

// ---------------- retention phase 2: parallel exclusive scan (half2) ----------------
__global__ void ret_scan(__half* __restrict__ S) {
    int bh = blockIdx.x >> 5;
    int pairIdx = ((blockIdx.x & 31) << 8) + threadIdx.x;
    int h = bh & 7;
    float gamma = 1.f - exp2f(-5.f - (float)h);
    float cdec = expf(logf(gamma) * 64.f);
    float2 carry = make_float2(0.f, 0.f);
    __half2* S2 = (__half2*)S;
    size_t base = (size_t)bh * NC * 8192 + pairIdx;
    for (int c = 0; c < NC; ++c) {
        size_t idx = base + (size_t)c * 8192;
        float2 loc = __half22float2(S2[idx]);
        S2[idx] = __floats2half2_rn(carry.x, carry.y);
        carry.x = carry.x * cdec + loc.x;
        carry.y = carry.y * cdec + loc.y;
    }
}

// ---------------- retention phase 3 (fp16 in, fp32 out) ----------------
__global__ void ret_phase3(const __half* __restrict__ q, const __half* __restrict__ k,
                           const __half* __restrict__ v, const __half* __restrict__ S,
                           float* __restrict__ o) {
    extern __shared__ float sm[];
    float* qs  = sm;
    float* ks  = qs + 64 * 129;
    float* vs  = ks + 64 * 129;
    float* Ps  = vs + 64 * 129;
    float* att = Ps + 128 * 129;
    int c = blockIdx.x, h = blockIdx.y, b = blockIdx.z;
    float gamma = 1.f - exp2f(-5.f - (float)h);
    float lg = logf(gamma);
    const float scale = 0.08838834764831845f;
    int tid = threadIdx.x;
    int lane = tid & 31;
    const __half2* q2 = (const __half2*)q;
    const __half2* k2 = (const __half2*)k;
    const __half2* v2 = (const __half2*)v;
    for (int x = tid; x < 4096; x += 256) {
        int i = x >> 6, d2 = x & 63;
        size_t gg = (((size_t)b * TT + c * 64 + i) * DD + h * 128) / 2 + d2;
        float2 qf = __half22float2(q2[gg]);
        float2 kf = __half22float2(k2[gg]);
        float2 vf = __half22float2(v2[gg]);
        qs[i * 129 + d2 * 2]     = qf.x * scale;
        qs[i * 129 + d2 * 2 + 1] = qf.y * scale;
        ks[i * 129 + d2 * 2]     = kf.x;
        ks[i * 129 + d2 * 2 + 1] = kf.y;
        vs[i * 129 + d2 * 2]     = vf.x;
        vs[i * 129 + d2 * 2 + 1] = vf.y;
    }
    size_t sb = (((size_t)(b * HH + h)) * NC + c) * 16384;
    const __half2* S2 = (const __half2*)S;
    for (int x = tid; x < 8192; x += 256) {
        int d = x >> 6, e2 = x & 63;
        float2 sf = __half22float2(S2[(sb >> 1) + d * 64 + e2]);
        Ps[d * 129 + e2 * 2]     = sf.x;
        Ps[d * 129 + e2 * 2 + 1] = sf.y;
    }
    __syncthreads();
    {
        int i0 = (tid >> 4) * 4;
        int j0 = (tid & 15) * 4;
        float a4[4][4];
        #pragma unroll
        for (int i = 0; i < 4; ++i)
            #pragma unroll
            for (int j = 0; j < 4; ++j) a4[i][j] = 0.f;
        #pragma unroll 4
        for (int d = 0; d < 128; ++d) {
            float qr[4], kr[4];
            #pragma unroll
            for (int i = 0; i < 4; ++i) qr[i] = qs[(i0 + i) * 129 + d];
            #pragma unroll
            for (int j = 0; j < 4; ++j) kr[j] = ks[(j0 + j) * 129 + d];
            #pragma unroll
            for (int i = 0; i < 4; ++i)
                #pragma unroll
                for (int j = 0; j < 4; ++j) a4[i][j] = fmaf(qr[i], kr[j], a4[i][j]);
        }
        #pragma unroll
        for (int i = 0; i < 4; ++i)
            #pragma unroll
            for (int j = 0; j < 4; ++j) {
                int ia = i0 + i, ja = j0 + j;
                float f = (ia >= ja) ? expf(lg * (float)(ia - ja)) : 0.f;
                att[ia * 65 + ja] = a4[i][j] * f;
            }
    }
    __syncthreads();
    {
        int i0 = (tid >> 5) * 8 + (lane >> 4) * 4;
        int e0 = (lane & 15) * 8;
        float accA[4][8], accB[4][8];
        #pragma unroll
        for (int i = 0; i < 4; ++i)
            #pragma unroll
            for (int e = 0; e < 8; ++e) { accA[i][e] = 0.f; accB[i][e] = 0.f; }
        #pragma unroll 4
        for (int j = 0; j < 64; ++j) {
            float ar[4], vr[8];
            #pragma unroll
            for (int i = 0; i < 4; ++i) ar[i] = att[(i0 + i) * 65 + j];
            #pragma unroll
            for (int e = 0; e < 8; ++e) vr[e] = vs[j * 129 + e0 + e];
            #pragma unroll
            for (int i = 0; i < 4; ++i)
                #pragma unroll
                for (int e = 0; e < 8; ++e) accA[i][e] = fmaf(ar[i], vr[e], accA[i][e]);
        }
        #pragma unroll 4
        for (int d = 0; d < 128; ++d) {
            float qr[4], pr[8];
            #pragma unroll
            for (int i = 0; i < 4; ++i) qr[i] = qs[(i0 + i) * 129 + d];
            #pragma unroll
            for (int e = 0; e < 8; ++e) pr[e] = Ps[d * 129 + e0 + e];
            #pragma unroll
            for (int i = 0; i < 4; ++i)
                #pragma unroll
                for (int e = 0; e < 8; ++e) accB[i][e] = fmaf(qr[i], pr[e], accB[i][e]);
        }
        #pragma unroll
        for (int i = 0; i < 4; ++i) {
            float crossf = expf(lg * (float)(i0 + i + 1));
            size_t ob = ((size_t)b * TT + c * 64 + i0 + i) * DD + h * 128 + e0;
            #pragma unroll
            for (int e = 0; e < 8; ++e)
                o[ob + e] = accA[i][e] + crossf * accB[i][e];
        }
    }
}

// ---------------- gating (g from fp16 big at col 3072) -> fp16 out ----------------
__global__ void gate_kernel(const float* __restrict__ o, const __half* __restrict__ gbig,
                            const float* __restrict__ w, __half* __restrict__ oh) {
    int row = blockIdx.x * 8 + (threadIdx.x >> 5);
    int lane = threadIdx.x & 31;
    int bt = row >> 3, h = row & 7;
    const float4* orow = (const float4*)(o + (size_t)row * 128);
    float4 v = orow[lane];
    float s = v.x * v.x + v.y * v.y + v.z * v.z + v.w * v.w;
    #pragma unroll
    for (int off = 16; off > 0; off >>= 1) s += __shfl_xor_sync(0xffffffffu, s, off);
    float inv = rsqrtf(s / 128.f + GATE_EPS);
    float4 gv = ldh4(gbig + (size_t)bt * 4096 + 3072 + h * 128 + lane * 4);
    float4 wv = ((const float4*)w)[lane];
    float rx = v.x * inv * wv.x * (gv.x / (1.f + expf(-gv.x)));
    float ry = v.y * inv * wv.y * (gv.y / (1.f + expf(-gv.y)));
    float rz = v.z * inv * wv.z * (gv.z / (1.f + expf(-gv.z)));
    float rw = v.w * inv * wv.w * (gv.w / (1.f + expf(-gv.w)));
    __half2* dst = (__half2*)(oh + (size_t)row * 128);
    dst[lane * 2]     = __floats2half2_rn(rx, ry);
    dst[lane * 2 + 1] = __floats2half2_rn(rz, rw);
}

// ---------------- launch ----------------
extern "C" void kernel_launch(void* const* d_in, const int* in_sizes, int n_in,
                              void* d_out, int out_size) {
    const float* hs    = (const float*)d_in[0];
    const float* ln1   = (const float*)d_in[1];
    const float* ln2   = (const float*)d_in[2];
    const float* wq    = (const float*)d_in[3];
    const float* wk    = (const float*)d_in[4];
    const float* wv    = (const float*)d_in[5];
    const float* wg    = (const float*)d_in[6];
    const float* wo    = (const float*)d_in[7];
    const float* cq    = (const float*)d_in[8];
    const float* ck    = (const float*)d_in[9];
    const float* cv    = (const float*)d_in[10];
    const float* gn    = (const float*)d_in[11];
    const float* wgate = (const float*)d_in[12];
    const float* wup   = (const float*)d_in[13];
    const float* wdown = (const float*)d_in[14];
    float* out = (float*)d_out;

    cudaFuncSetAttribute(hgemm_t<0>, cudaFuncAttributeMaxDynamicSharedMemorySize, SMEM_GEMM);
    cudaFuncSetAttribute(hgemm_t<1>, cudaFuncAttributeMaxDynamicSharedMemorySize, SMEM_GEMM);
    cudaFuncSetAttribute(hgemm_t<2>, cudaFuncAttributeMaxDynamicSharedMemorySize, SMEM_GEMM);
    cudaFuncSetAttribute(ret_phase1, cudaFuncAttributeMaxDynamicSharedMemorySize, 2 * 64 * 129 * 4);
    cudaFuncSetAttribute(ret_phase3, cudaFuncAttributeMaxDynamicSharedMemorySize,
                         (3 * 64 * 129 + 128 * 129 + 64 * 65) * 4);

    float *o, *hbuf;
    __half *big, *qh, *kh, *vh, *Sh, *xh, *oh, *m1h, *bt;
    cudaGetSymbolAddress((void**)&big, g_big);
    cudaGetSymbolAddress((void**)&qh,  g_qh);
    cudaGetSymbolAddress((void**)&kh,  g_kh);
    cudaGetSymbolAddress((void**)&vh,  g_vh);
    cudaGetSymbolAddress((void**)&o,   g_o);
    cudaGetSymbolAddress((void**)&hbuf, g_h);
    cudaGetSymbolAddress((void**)&Sh,  g_Sh);
    cudaGetSymbolAddress((void**)&xh,  g_xh);
    cudaGetSymbolAddress((void**)&oh,  g_oh);
    cudaGetSymbolAddress((void**)&m1h, g_m1h);
    cudaGetSymbolAddress((void**)&bt,  g_bt);

    rope_table_kernel<<<(TT * 64 + 255) / 256, 256>>>();
    rmsnorm_kernel<<<BT, 256>>>(hs, ln1, xh, RMS_EPS);

    dim3 tD(DD / 32, DD / 32), tI1(II / 32, DD / 32), tI2(DD / 32, II / 32), tb(32, 8);

    // fused qkvg weights
    convT_kernel<<<tD, tb>>>(wq, bt,             DD, DD, 1, 0);
    convT_kernel<<<tD, tb>>>(wk, bt + 1024 * DD, DD, DD, 1, 0);
    convT_kernel<<<tD, tb>>>(wv, bt + 2048 * DD, DD, DD, 1, 0);
    convT_kernel<<<tD, tb>>>(wg, bt + 3072 * DD, DD, DD, 1, 0);
    dim3 gQKVG(4096 / 128, BT / 128);
    hgemm_t<1><<<gQKVG, 256, SMEM_GEMM>>>(xh, bt, nullptr, big, BT, 4096, DD);

    const int crblocks = (BB * (TT / 4) * HH * 16) / 256;
    const int cvblocks = BB * TT / 4;
    conv_silu_rope_kernel<<<crblocks, 256>>>(big,        cq, qh);
    conv_silu_rope_kernel<<<crblocks, 256>>>(big + 1024, ck, kh);
    conv_silu_h_kernel<<<cvblocks, 256>>>(big + 2048, cv, vh);

    dim3 gc(NC, HH, BB);
    ret_phase1<<<gc, 256, 2 * 64 * 129 * 4>>>(kh, vh, Sh);
    ret_scan<<<BB * HH * 32, 256>>>(Sh);
    ret_phase3<<<gc, 256, (3 * 64 * 129 + 128 * 129 + 64 * 65) * 4>>>(qh, kh, vh, Sh, o);

    gate_kernel<<<(BT * HH) / 8, 256>>>(o, big, gn, oh);
    convT_kernel<<<tD, tb>>>(wo, bt, DD, DD, 1, 0);
    dim3 gD(DD / 128, BT / 128);
    hgemm_t<0><<<gD, 256, SMEM_GEMM>>>(oh, bt, hs, hbuf, BT, DD, DD);

    rmsnorm_kernel<<<BT, 256>>>(hbuf, ln2, xh, RMS_EPS);
    // interleaved gate/up weights: gate col j -> row 2j, up col j -> row 2j+1
    convT_kernel<<<tI1, tb>>>(wgate, bt, DD, II, 2, 0);
    convT_kernel<<<tI1, tb>>>(wup,   bt, DD, II, 2, 1);
    dim3 gMLP(5632 / 128, BT / 128);
    hgemm_t<2><<<gMLP, 256, SMEM_GEMM>>>(xh, bt, nullptr, m1h, BT, 5632, DD);
    convT_kernel<<<tI2, tb>>>(wdown, bt, II, DD, 1, 0);
    hgemm_t<0><<<gD, 256, SMEM_GEMM>>>(m1h, bt, hbuf, out, BT, DD, II);
}

// round 11
// speedup vs baseline: 7.4651x; 1.4100x over previous
#include <cuda_runtime.h>
#include <cuda_fp16.h>
#include <math.h>
#include <stdint.h>

#define BB 4
#define TT 8192
#define DD 1024
#define HH 8
#define II 2816
#define NC 128
#define BT (BB*TT)

#define RMS_EPS 1e-6f
#define GATE_EPS 1e-5f

// ---------------- scratch ----------------
__device__ __half g_big[(size_t)BT*4096];
__device__ __half g_qh [(size_t)BT*DD];
__device__ __half g_kh [(size_t)BT*DD];
__device__ __half g_vh [(size_t)BT*DD];
__device__ float  g_o [(size_t)BT*DD];
__device__ float  g_h [(size_t)BT*DD];
__device__ __half g_Sh[(size_t)BB*HH*NC*128*128];
__device__ __half g_xh [(size_t)BT*DD];
__device__ __half g_oh [(size_t)BT*DD];
__device__ __half g_m1h[(size_t)BT*II];
__device__ __half g_bt [(size_t)5632*DD];
__device__ float  g_cos[TT*64];
__device__ float  g_sin[TT*64];

// ---------------- helpers ----------------
__device__ __forceinline__ float4 ldh4(const __half* p) {
    uint2 u = *(const uint2*)p;
    float2 f0 = __half22float2(*(__half2*)&u.x);
    float2 f1 = __half22float2(*(__half2*)&u.y);
    return make_float4(f0.x, f0.y, f1.x, f1.y);
}
__device__ __forceinline__ void mma_fp16(float* c, const uint32_t* a, const uint32_t* b) {
    asm volatile("mma.sync.aligned.m16n8k16.row.col.f32.f16.f16.f32 "
        "{%0,%1,%2,%3}, {%4,%5,%6,%7}, {%8,%9}, {%0,%1,%2,%3};"
        : "+f"(c[0]), "+f"(c[1]), "+f"(c[2]), "+f"(c[3])
        : "r"(a[0]), "r"(a[1]), "r"(a[2]), "r"(a[3]), "r"(b[0]), "r"(b[1]));
}
__device__ __forceinline__ void cpasync16(uint32_t s, const void* g) {
    asm volatile("cp.async.cg.shared.global [%0], [%1], 16;" :: "r"(s), "l"(g));
}
__device__ __forceinline__ void ldsm_x4(uint32_t* r, uint32_t addr) {
    asm volatile("ldmatrix.sync.aligned.m8n8.x4.shared.b16 {%0,%1,%2,%3}, [%4];"
        : "=r"(r[0]), "=r"(r[1]), "=r"(r[2]), "=r"(r[3]) : "r"(addr));
}
__device__ __forceinline__ void ldsm_x4_t(uint32_t* r, uint32_t addr) {
    asm volatile("ldmatrix.sync.aligned.m8n8.x4.trans.shared.b16 {%0,%1,%2,%3}, [%4];"
        : "=r"(r[0]), "=r"(r[1]), "=r"(r[2]), "=r"(r[3]) : "r"(addr));
}

// ---------------- rmsnorm -> fp16 out ----------------
__global__ void rmsnorm_kernel(const float* __restrict__ x, const float* __restrict__ w,
                               __half* __restrict__ out, float eps) {
    int row = blockIdx.x;
    const float4* xr = (const float4*)(x + (size_t)row * DD);
    float4 v = xr[threadIdx.x];
    float s = v.x * v.x + v.y * v.y + v.z * v.z + v.w * v.w;
    __shared__ float red[8];
    #pragma unroll
    for (int o = 16; o > 0; o >>= 1) s += __shfl_down_sync(0xffffffffu, s, o);
    if ((threadIdx.x & 31) == 0) red[threadIdx.x >> 5] = s;
    __syncthreads();
    if (threadIdx.x < 8) {
        s = red[threadIdx.x];
        #pragma unroll
        for (int o = 4; o > 0; o >>= 1) s += __shfl_down_sync(0xffu, s, o);
        if (threadIdx.x == 0) red[0] = s;
    }
    __syncthreads();
    float inv = rsqrtf(red[0] / (float)DD + eps);
    float4 wv = ((const float4*)w)[threadIdx.x];
    __half2* orow = (__half2*)(out + (size_t)row * DD);
    orow[threadIdx.x * 2]     = __floats2half2_rn(v.x * inv * wv.x, v.y * inv * wv.y);
    orow[threadIdx.x * 2 + 1] = __floats2half2_rn(v.z * inv * wv.z, v.w * inv * wv.w);
}

// ---------------- weight convert + transpose with row remap ----------------
__global__ void convT_kernel(const float* __restrict__ W, __half* __restrict__ Wt,
                             int K, int N, int rs, int ro) {
    __shared__ float tile[32][33];
    int n0 = blockIdx.x * 32, k0 = blockIdx.y * 32;
    #pragma unroll
    for (int j = threadIdx.y; j < 32; j += 8)
        tile[j][threadIdx.x] = W[(size_t)(k0 + j) * N + n0 + threadIdx.x];
    __syncthreads();
    #pragma unroll
    for (int j = threadIdx.y; j < 32; j += 8)
        Wt[((size_t)(n0 + j) * rs + ro) * K + k0 + threadIdx.x] = __float2half_rn(tile[threadIdx.x][j]);
}

// ================= fp16 tensor-core GEMM =================
#define BKH 64
#define XW 36
#define AW (128*XW)
#define BW (128*XW)
#define STG (AW+BW)
#define SMEM_GEMM (3*STG*4)

template <int MODE>
__global__ __launch_bounds__(256, 2)
void hgemm_t(const __half* __restrict__ A, const __half* __restrict__ Bt,
             const float* __restrict__ R, void* __restrict__ Cv,
             int M, int N, int K) {
    extern __shared__ uint32_t smw[];

    const int tid = threadIdx.x;
    const int lane = tid & 31;
    const int w = tid >> 5;
    const int g = lane >> 2, q = lane & 3;
    const int wm = (w & 1) * 64;
    const int wn = (w >> 1) * 32;
    const int bm = blockIdx.y * 128, bn = blockIdx.x * 128;

    uint32_t sBase = (uint32_t)__cvta_generic_to_shared(smw);

    const uint32_t aLane = (uint32_t)((wm + (lane & 15)) * XW + ((lane >> 4) << 2));
    const uint32_t bLane = (uint32_t)((wn + (lane & 7) + ((lane >> 4) << 3)) * XW + (((lane >> 3) & 1) << 2));

    float acc[4][4][4];
    #pragma unroll
    for (int i = 0; i < 4; ++i)
        #pragma unroll
        for (int j = 0; j < 4; ++j)
            #pragma unroll
            for (int r = 0; r < 4; ++r) acc[i][j][r] = 0.f;

    const int ntile = K / BKH;

    auto loadTile = [&](int t, int s) {
        #pragma unroll
        for (int i = 0; i < 4; ++i) {
            int idx = i * 256 + tid;
            int row = idx >> 3, kc = (idx & 7) * 8;
            cpasync16(sBase + (uint32_t)((s * STG + row * XW) * 4 + kc * 2),
                      A + (size_t)(bm + row) * K + t * BKH + kc);
        }
        #pragma unroll
        for (int i = 0; i < 4; ++i) {
            int idx = i * 256 + tid;
            int n = idx >> 3, kc = (idx & 7) * 8;
            cpasync16(sBase + (uint32_t)((s * STG + AW + n * XW) * 4 + kc * 2),
                      Bt + (size_t)(bn + n) * K + t * BKH + kc);
        }
        asm volatile("cp.async.commit_group;");
    };

    loadTile(0, 0);
    if (ntile > 1) loadTile(1, 1);

    for (int t = 0; t < ntile; ++t) {
        int s = t % 3;
        if (t + 2 < ntile) asm volatile("cp.async.wait_group 1;");
        else               asm volatile("cp.async.wait_group 0;");
        __syncthreads();
        if (t + 2 < ntile) loadTile(t + 2, (t + 2) % 3);

        const uint32_t aOff = sBase + (uint32_t)(s * STG) * 4;
        const uint32_t bOff = sBase + (uint32_t)(s * STG + AW) * 4;
        #pragma unroll
        for (int ks = 0; ks < 4; ++ks) {
            uint32_t a[4][4], b[4][2];
            #pragma unroll
            for (int mt = 0; mt < 4; ++mt)
                ldsm_x4(a[mt], aOff + (aLane + (uint32_t)(mt * 16 * XW + ks * 8)) * 4);
            #pragma unroll
            for (int np = 0; np < 2; ++np) {
                uint32_t bb[4];
                ldsm_x4(bb, bOff + (bLane + (uint32_t)(np * 16 * XW + ks * 8)) * 4);
                b[np * 2][0]     = bb[0];
                b[np * 2][1]     = bb[1];
                b[np * 2 + 1][0] = bb[2];
                b[np * 2 + 1][1] = bb[3];
            }
            #pragma unroll
            for (int mt = 0; mt < 4; ++mt)
                #pragma unroll
                for (int nt = 0; nt < 4; ++nt)
                    mma_fp16(acc[mt][nt], a[mt], b[nt]);
        }
    }

    #pragma unroll
    for (int mt = 0; mt < 4; ++mt) {
        #pragma unroll
        for (int half = 0; half < 2; ++half) {
            int row = bm + wm + mt * 16 + g + half * 8;
            #pragma unroll
            for (int nt = 0; nt < 4; ++nt) {
                float vx = acc[mt][nt][half * 2 + 0];
                float vy = acc[mt][nt][half * 2 + 1];
                if (MODE == 0) {
                    int col = bn + wn + nt * 8 + q * 2;
                    size_t off = (size_t)row * N + col;
                    float* C = (float*)Cv;
                    float2 v2;
                    v2.x = vx; v2.y = vy;
                    if (R) {
                        const float2 rr = *(const float2*)(R + off);
                        v2.x += rr.x; v2.y += rr.y;
                    }
                    *(float2*)(C + off) = v2;
                } else if (MODE == 1) {
                    int col = bn + wn + nt * 8 + q * 2;
                    __half2* C = (__half2*)Cv;
                    C[((size_t)row * N + col) >> 1] = __floats2half2_rn(vx, vy);
                } else {
                    int oc = (bn + wn) / 2 + nt * 4 + q;
                    float r = (vx / (1.f + expf(-vx))) * vy;
                    __half* C = (__half*)Cv;
                    C[(size_t)row * (N >> 1) + oc] = __float2half_rn(r);
                }
            }
        }
    }
}

// ---------------- conv(K=4)+silu+RoPE fused (q,k path) ----------------
__global__ void conv_silu_rope_kernel(const __half* __restrict__ x, const float* __restrict__ w,
                                      __half* __restrict__ y) {
    int idx = blockIdx.x * 256 + threadIdx.x;
    int j4 = idx & 15;
    int h  = (idx >> 4) & 7;
    int t4 = (idx >> 7) & 2047;
    int b  = idx >> 18;
    const float4* w4 = (const float4*)w;
    int d1 = h * 128 + j4 * 4;
    float4 wa[4], wb[4];
    #pragma unroll
    for (int r = 0; r < 4; ++r) { wa[r] = w4[d1 + r]; wb[r] = w4[d1 + 64 + r]; }
    int t0 = t4 * 4;
    float4 xv1[7], xv2[7];
    #pragma unroll
    for (int j = 0; j < 7; ++j) {
        int tt = t0 - 3 + j;
        if (tt >= 0) {
            const __half* p = x + ((size_t)(b * TT + tt)) * 4096 + d1;
            xv1[j] = ldh4(p);
            xv2[j] = ldh4(p + 64);
        } else {
            xv1[j] = make_float4(0.f, 0.f, 0.f, 0.f);
            xv2[j] = make_float4(0.f, 0.f, 0.f, 0.f);
        }
    }
    const float4* cos4 = (const float4*)g_cos;
    const float4* sin4 = (const float4*)g_sin;
    __half2* y2 = (__half2*)y;
    #pragma unroll
    for (int i = 0; i < 4; ++i) {
        float4 a1, a2;
        a1.x = xv1[i].x * wa[0].x + xv1[i+1].x * wa[0].y + xv1[i+2].x * wa[0].z + xv1[i+3].x * wa[0].w;
        a1.y = xv1[i].y * wa[1].x + xv1[i+1].y * wa[1].y + xv1[i+2].y * wa[1].z + xv1[i+3].y * wa[1].w;
        a1.z = xv1[i].z * wa[2].x + xv1[i+1].z * wa[2].y + xv1[i+2].z * wa[2].z + xv1[i+3].z * wa[2].w;
        a1.w = xv1[i].w * wa[3].x + xv1[i+1].w * wa[3].y + xv1[i+2].w * wa[3].z + xv1[i+3].w * wa[3].w;
        a2.x = xv2[i].x * wb[0].x + xv2[i+1].x * wb[0].y + xv2[i+2].x * wb[0].z + xv2[i+3].x * wb[0].w;
        a2.y = xv2[i].y * wb[1].x + xv2[i+1].y * wb[1].y + xv2[i+2].y * wb[1].z + xv2[i+3].y * wb[1].w;
        a2.z = xv2[i].z * wb[2].x + xv2[i+1].z * wb[2].y + xv2[i+2].z * wb[2].z + xv2[i+3].z * wb[2].w;
        a2.w = xv2[i].w * wb[3].x + xv2[i+1].w * wb[3].y + xv2[i+2].w * wb[3].z + xv2[i+3].w * wb[3].w;
        a1.x /= (1.f + expf(-a1.x)); a1.y /= (1.f + expf(-a1.y));
        a1.z /= (1.f + expf(-a1.z)); a1.w /= (1.f + expf(-a1.w));
        a2.x /= (1.f + expf(-a2.x)); a2.y /= (1.f + expf(-a2.y));
        a2.z /= (1.f + expf(-a2.z)); a2.w /= (1.f + expf(-a2.w));
        int t = t0 + i;
        float4 c = cos4[t * 16 + j4];
        float4 s = sin4[t * 16 + j4];
        float4 o1, o2;
        o1.x = a1.x * c.x - a2.x * s.x;  o2.x = a1.x * s.x + a2.x * c.x;
        o1.y = a1.y * c.y - a2.y * s.y;  o2.y = a1.y * s.y + a2.y * c.y;
        o1.z = a1.z * c.z - a2.z * s.z;  o2.z = a1.z * s.z + a2.z * c.z;
        o1.w = a1.w * c.w - a2.w * s.w;  o2.w = a1.w * s.w + a2.w * c.w;
        size_t base1 = (((size_t)(b * TT + t)) * DD + d1) >> 1;
        y2[base1]      = __floats2half2_rn(o1.x, o1.y);
        y2[base1 + 1]  = __floats2half2_rn(o1.z, o1.w);
        y2[base1 + 32] = __floats2half2_rn(o2.x, o2.y);
        y2[base1 + 33] = __floats2half2_rn(o2.z, o2.w);
    }
}

// ---------------- conv(K=4)+silu (v path) ----------------
__global__ void conv_silu_h_kernel(const __half* __restrict__ x, const float* __restrict__ w,
                                   __half* __restrict__ y) {
    int idx = blockIdx.x * 256 + threadIdx.x;
    int d4 = idx & 255;
    int rest = idx >> 8;
    int t4 = rest & (TT / 4 - 1);
    int b = rest >> 11;
    const float4* w4 = (const float4*)w;
    float4 wr0 = w4[d4 * 4 + 0], wr1 = w4[d4 * 4 + 1];
    float4 wr2 = w4[d4 * 4 + 2], wr3 = w4[d4 * 4 + 3];
    int t0 = t4 * 4;
    float4 xv[7];
    #pragma unroll
    for (int j = 0; j < 7; ++j) {
        int tt = t0 - 3 + j;
        xv[j] = (tt >= 0) ? ldh4(x + ((size_t)(b * TT + tt)) * 4096 + d4 * 4)
                          : make_float4(0.f, 0.f, 0.f, 0.f);
    }
    __half2* y2 = (__half2*)y;
    #pragma unroll
    for (int i = 0; i < 4; ++i) {
        float4 a;
        a.x = xv[i].x * wr0.x + xv[i+1].x * wr0.y + xv[i+2].x * wr0.z + xv[i+3].x * wr0.w;
        a.y = xv[i].y * wr1.x + xv[i+1].y * wr1.y + xv[i+2].y * wr1.z + xv[i+3].y * wr1.w;
        a.z = xv[i].z * wr2.x + xv[i+1].z * wr2.y + xv[i+2].z * wr2.z + xv[i+3].z * wr2.w;
        a.w = xv[i].w * wr3.x + xv[i+1].w * wr3.y + xv[i+2].w * wr3.z + xv[i+3].w * wr3.w;
        a.x /= (1.f + expf(-a.x)); a.y /= (1.f + expf(-a.y));
        a.z /= (1.f + expf(-a.z)); a.w /= (1.f + expf(-a.w));
        size_t bh = ((size_t)(b * TT + t0 + i)) * 512 + d4 * 2;
        y2[bh]     = __floats2half2_rn(a.x, a.y);
        y2[bh + 1] = __floats2half2_rn(a.z, a.w);
    }
}

// ---------------- RoPE table ----------------
__global__ void rope_table_kernel() {
    int idx = blockIdx.x * 256 + threadIdx.x;
    if (idx >= TT * 64) return;
    int t = idx >> 6, j = idx & 63;
    float invf = (float)(1.0 / pow(10000.0, (double)j / 64.0));
    float f = (float)t * invf;
    g_cos[idx] = (float)cos((double)f);
    g_sin[idx] = (float)sin((double)f);
}

// ================= retention phase 1 (HMMA): S = (k*dec)^T @ v =================
// smem: ks 64x136 fp16 (dec applied), vs 64x136 fp16. 256 thr.
#define RSTR 136
#define SMEM_P1 ((64*RSTR + 64*RSTR) * 2)
__global__ __launch_bounds__(256, 2)
void ret_phase1(const __half* __restrict__ k, const __half* __restrict__ v,
                __half* __restrict__ S) {
    extern __shared__ __half smh[];
    __half* ks = smh;
    __half* vs = smh + 64 * RSTR;
    int c = blockIdx.x, h = blockIdx.y, b = blockIdx.z;
    float gamma = 1.f - exp2f(-5.f - (float)h);
    float lg = logf(gamma);
    int tid = threadIdx.x, lane = tid & 31, w = tid >> 5;
    int g = lane >> 2, q = lane & 3;
    uint32_t sk = (uint32_t)__cvta_generic_to_shared(ks);
    uint32_t sv = (uint32_t)__cvta_generic_to_shared(vs);

    // v via cp.async
    #pragma unroll
    for (int it = 0; it < 4; ++it) {
        int x = it * 256 + tid;
        int row = x >> 4, ch = x & 15;
        cpasync16(sv + (uint32_t)(row * RSTR + ch * 8) * 2,
                  v + ((size_t)(b * TT + c * 64 + row) * DD + h * 128 + ch * 8));
    }
    asm volatile("cp.async.commit_group;");
    // k with dec
    const __half2* k2 = (const __half2*)k;
    for (int x = tid; x < 4096; x += 256) {
        int row = x >> 6, d2 = x & 63;
        float dec = expf(lg * (float)(63 - row));
        float2 kf = __half22float2(k2[((size_t)(b * TT + c * 64 + row) * DD + h * 128) / 2 + d2]);
        *(__half2*)(ks + row * RSTR + d2 * 2) = __floats2half2_rn(kf.x * dec, kf.y * dec);
    }
    asm volatile("cp.async.wait_group 0;");
    __syncthreads();

    int m0 = (w & 3) * 32;           // 2 m-tiles (d)
    int e0w = (w >> 2) * 64;         // 8 n-tiles (e)
    float acc[2][8][4];
    #pragma unroll
    for (int i = 0; i < 2; ++i)
        #pragma unroll
        for (int j = 0; j < 8; ++j)
            #pragma unroll
            for (int r = 0; r < 4; ++r) acc[i][j][r] = 0.f;

    // trans A lane addressing (within k-step j0, m-tile d0):
    int aRow = (lane & 7) + ((lane >> 4) << 3);             // + j0
    int aCol = ((lane >> 3) & 1) << 3;                      // + d0
    int bRow = (lane & 7) + (((lane >> 3) & 1) << 3);       // + j0
    int bCol = (lane >> 4) << 3;                            // + e0

    #pragma unroll
    for (int kt = 0; kt < 4; ++kt) {
        int j0 = kt * 16;
        uint32_t a[2][4];
        #pragma unroll
        for (int mt = 0; mt < 2; ++mt)
            ldsm_x4_t(a[mt], sk + (uint32_t)((j0 + aRow) * RSTR + m0 + mt * 16 + aCol) * 2);
        #pragma unroll
        for (int np = 0; np < 4; ++np) {
            uint32_t bb[4];
            ldsm_x4_t(bb, sv + (uint32_t)((j0 + bRow) * RSTR + e0w + np * 16 + bCol) * 2);
            #pragma unroll
            for (int mt = 0; mt < 2; ++mt) {
                mma_fp16(acc[mt][np * 2],     a[mt], bb);
                mma_fp16(acc[mt][np * 2 + 1], a[mt], bb + 2);
            }
        }
    }

    size_t sb = (((size_t)(b * HH + h)) * NC + c) * 16384;
    __half2* S2 = (__half2*)S;
    #pragma unroll
    for (int mt = 0; mt < 2; ++mt) {
        #pragma unroll
        for (int nt = 0; nt < 8; ++nt) {
            int e = e0w + nt * 8 + q * 2;
            int d1 = m0 + mt * 16 + g;
            S2[(sb + (size_t)d1 * 128 + e) >> 1]       = __floats2half2_rn(acc[mt][nt][0], acc[mt][nt][1]);
            S2[(sb + (size_t)(d1 + 8) * 128 + e) >> 1] = __floats2half2_rn(acc[mt][nt][2], acc[mt][nt][3]);
        }
    }
}

// ---------------- retention phase 2: parallel exclusive scan (half2) ----------------
__global__ void ret_scan(__half* __restrict__ S) {
    int bh = blockIdx.x >> 5;
    int pairIdx = ((blockIdx.x & 31) << 8) + threadIdx.x;
    int h = bh & 7;
    float gamma = 1.f - exp2f(-5.f - (float)h);
    float cdec = expf(logf(gamma) * 64.f);
    float2 carry = make_float2(0.f, 0.f);
    __half2* S2 = (__half2*)S;
    size_t base = (size_t)bh * NC * 8192 + pairIdx;
    for (int c = 0; c < NC; ++c) {
        size_t idx = base + (size_t)c * 8192;
        float2 loc = __half22float2(S2[idx]);
        S2[idx] = __floats2half2_rn(carry.x, carry.y);
        carry.x = carry.x * cdec + loc.x;
        carry.y = carry.y * cdec + loc.y;
    }
}

// ================= retention phase 3 (HMMA) =================
// smem: qs 64x136, ks 64x136 (reused for S[0:64]), vs 64x136 (reused for S[64:128]), att 64x72
#define ASTR3 72
#define SMEM_P3 ((3*64*RSTR + 64*ASTR3) * 2)
__global__ __launch_bounds__(256, 2)
void ret_phase3(const __half* __restrict__ q, const __half* __restrict__ k,
                const __half* __restrict__ v, const __half* __restrict__ S,
                float* __restrict__ o) {
    extern __shared__ __half smh[];
    __half* qs  = smh;
    __half* ksb = smh + 64 * RSTR;
    __half* vsb = smh + 2 * 64 * RSTR;
    __half* ats = smh + 3 * 64 * RSTR;
    int c = blockIdx.x, h = blockIdx.y, b = blockIdx.z;
    float gamma = 1.f - exp2f(-5.f - (float)h);
    float lg = logf(gamma);
    const float scale = 0.08838834764831845f;
    int tid = threadIdx.x, lane = tid & 31, w = tid >> 5;
    int g = lane >> 2, qq = lane & 3;
    uint32_t sq = (uint32_t)__cvta_generic_to_shared(qs);
    uint32_t sk = (uint32_t)__cvta_generic_to_shared(ksb);
    uint32_t sv = (uint32_t)__cvta_generic_to_shared(vsb);
    uint32_t sa = (uint32_t)__cvta_generic_to_shared(ats);

    // stage q,k,v via cp.async
    #pragma unroll
    for (int it = 0; it < 4; ++it) {
        int x = it * 256 + tid;
        int row = x >> 4, ch = x & 15;
        size_t gg = (size_t)(b * TT + c * 64 + row) * DD + h * 128 + ch * 8;
        uint32_t off = (uint32_t)(row * RSTR + ch * 8) * 2;
        cpasync16(sq + off, q + gg);
        cpasync16(sk + off, k + gg);
        cpasync16(sv + off, v + gg);
    }
    asm volatile("cp.async.commit_group;");
    asm volatile("cp.async.wait_group 0;");
    __syncthreads();

    const int mt = w & 3;              // m-tile (i)
    const int m0 = mt * 16;
    const int eh = w >> 2;             // 0/1
    size_t sbg = (((size_t)(b * HH + h)) * NC + c) * 16384;

    // lane addressing
    int aRow = m0 + (lane & 15);                         // A rows (q / att)
    int aCol = (lane >> 4) << 3;                         // + ks*16
    int bRowN = (lane & 7) + ((lane >> 4) << 3);         // non-trans B rows (+n0)
    int bColN = ((lane >> 3) & 1) << 3;                  // + ks*16
    int tRow = (lane & 7) + (((lane >> 3) & 1) << 3);    // trans B rows (+j0)
    int tCol = (lane >> 4) << 3;                         // + e0

    // ---- Step A: att = q @ k^T (64x64xK128), warp covers n0 = eh*32, 4 n-tiles
    {
        int n0 = eh * 32;
        float accT[4][4];
        #pragma unroll
        for (int i = 0; i < 4; ++i)
            #pragma unroll
            for (int r = 0; r < 4; ++r) accT[i][r] = 0.f;
        #pragma unroll
        for (int kt = 0; kt < 8; ++kt) {
            uint32_t a[4];
            ldsm_x4(a, sq + (uint32_t)(aRow * RSTR + aCol + kt * 16) * 2);
            #pragma unroll
            for (int np = 0; np < 2; ++np) {
                uint32_t bb[4];
                ldsm_x4(bb, sk + (uint32_t)((n0 + np * 16 + bRowN) * RSTR + bColN + kt * 16) * 2);
                mma_fp16(accT[np * 2],     a, bb);
                mma_fp16(accT[np * 2 + 1], a, bb + 2);
            }
        }
        // mask*scale, store fp16 att
        #pragma unroll
        for (int nt = 0; nt < 4; ++nt) {
            int j0 = n0 + nt * 8 + qq * 2;
            int i1 = m0 + g, i2 = i1 + 8;
            float f0 = (i1 >= j0)     ? scale * expf(lg * (float)(i1 - j0))     : 0.f;
            float f1 = (i1 >= j0 + 1) ? scale * expf(lg * (float)(i1 - j0 - 1)) : 0.f;
            float f2 = (i2 >= j0)     ? scale * expf(lg * (float)(i2 - j0))     : 0.f;
            float f3 = (i2 >= j0 + 1) ? scale * expf(lg * (float)(i2 - j0 - 1)) : 0.f;
            *(__half2*)(ats + i1 * ASTR3 + j0) = __floats2half2_rn(accT[nt][0] * f0, accT[nt][1] * f1);
            *(__half2*)(ats + i2 * ASTR3 + j0) = __floats2half2_rn(accT[nt][2] * f2, accT[nt][3] * f3);
        }
    }
    __syncthreads();   // att visible; ks buffer now dead

    // prefetch S[0:64] into ks buffer (overlap with o1)
    #pragma unroll
    for (int it = 0; it < 4; ++it) {
        int x = it * 256 + tid;
        int row = x >> 4, ch = x & 15;
        cpasync16(sk + (uint32_t)(row * RSTR + ch * 8) * 2, S + sbg + (size_t)row * 128 + ch * 8);
    }
    asm volatile("cp.async.commit_group;");

    // ---- Step B: o1 = att @ v  (64x128xK64), warp: 8 n-tiles at e0w
    const int e0w = eh * 64;
    float accA[8][4];
    #pragma unroll
    for (int i = 0; i < 8; ++i)
        #pragma unroll
        for (int r = 0; r < 4; ++r) accA[i][r] = 0.f;
    #pragma unroll
    for (int kt = 0; kt < 4; ++kt) {
        int j0 = kt * 16;
        uint32_t a[4];
        ldsm_x4(a, sa + (uint32_t)(aRow * ASTR3 + aCol + kt * 16) * 2);
        #pragma unroll
        for (int np = 0; np < 4; ++np) {
            uint32_t bb[4];
            ldsm_x4_t(bb, sv + (uint32_t)((j0 + tRow) * RSTR + e0w + np * 16 + tCol) * 2);
            mma_fp16(accA[np * 2],     a, bb);
            mma_fp16(accA[np * 2 + 1], a, bb + 2);
        }
    }
    asm volatile("cp.async.wait_group 0;");
    __syncthreads();   // S-lo ready; v buffer dead

    // prefetch S[64:128] into vs buffer
    #pragma unroll
    for (int it = 0; it < 4; ++it) {
        int x = it * 256 + tid;
        int row = x >> 4, ch = x & 15;
        cpasync16(sv + (uint32_t)(row * RSTR + ch * 8) * 2, S + sbg + (size_t)(64 + row) * 128 + ch * 8);
    }
    asm volatile("cp.async.commit_group;");

    // ---- Step C part 1: accB += q @ S[0:64]
    float accB[8][4];
    #pragma unroll
    for (int i = 0; i < 8; ++i)
        #pragma unroll
        for (int r = 0; r < 4; ++r) accB[i][r] = 0.f;
    #pragma unroll
    for (int kt = 0; kt < 4; ++kt) {
        int d0 = kt * 16;
        uint32_t a[4];
        ldsm_x4(a, sq + (uint32_t)(aRow * RSTR + aCol + kt * 16) * 2);
        #pragma unroll
        for (int np = 0; np < 4; ++np) {
            uint32_t bb[4];
            ldsm_x4_t(bb, sk + (uint32_t)((d0 + tRow) * RSTR + e0w + np * 16 + tCol) * 2);
            mma_fp16(accB[np * 2],     a, bb);
            mma_fp16(accB[np * 2 + 1], a, bb + 2);
        }
    }
    asm volatile("cp.async.wait_group 0;");
    __syncthreads();   // S-hi ready

    // ---- Step C part 2: accB += q @ S[64:128]
    #pragma unroll
    for (int kt = 4; kt < 8; ++kt) {
        int d0 = (kt - 4) * 16;
        uint32_t a[4];
        ldsm_x4(a, sq + (uint32_t)(aRow * RSTR + aCol + kt * 16) * 2);
        #pragma unroll
        for (int np = 0; np < 4; ++np) {
            uint32_t bb[4];
            ldsm_x4_t(bb, sv + (uint32_t)((d0 + tRow) * RSTR + e0w + np * 16 + tCol) * 2);
            mma_fp16(accB[np * 2],     a, bb);
            mma_fp16(accB[np * 2 + 1], a, bb + 2);
        }
    }

    // epilogue
    int i1 = m0 + g;
    float cf1 = scale * expf(lg * (float)(i1 + 1));
    float cf2 = scale * expf(lg * (float)(i1 + 9));
    #pragma unroll
    for (int nt = 0; nt < 8; ++nt) {
        int e = e0w + nt * 8 + qq * 2;
        size_t ob1 = ((size_t)(b * TT + c * 64 + i1) * DD + h * 128 + e);
        size_t ob2 = ((size_t)(b * TT + c * 64 + i1 + 8) * DD + h * 128 + e);
        float2 v1, v2;
        v1.x = accA[nt][0] + cf1 * accB[nt][0];
        v1.y = accA[nt][1] + cf1 * accB[nt][1];
        v2.x = accA[nt][2] + cf2 * accB[nt][2];
        v2.y = accA[nt][3] + cf2 * accB[nt][3];
        *(float2*)(o + ob1) = v1;
        *(float2*)(o + ob2) = v2;
    }
}

// ---------------- gating -> fp16 out ----------------
__global__ void gate_kernel(const float* __restrict__ o, const __half* __restrict__ gbig,
                            const float* __restrict__ w, __half* __restrict__ oh) {
    int row = blockIdx.x * 8 + (threadIdx.x >> 5);
    int lane = threadIdx.x & 31;
    int bt = row >> 3, h = row & 7;
    const float4* orow = (const float4*)(o + (size_t)row * 128);
    float4 v = orow[lane];
    float s = v.x * v.x + v.y * v.y + v.z * v.z + v.w * v.w;
    #pragma unroll
    for (int off = 16; off > 0; off >>= 1) s += __shfl_xor_sync(0xffffffffu, s, off);
    float inv = rsqrtf(s / 128.f + GATE_EPS);
    float4 gv = ldh4(gbig + (size_t)bt * 4096 + 3072 + h * 128 + lane * 4);
    float4 wv = ((const float4*)w)[lane];
    float rx = v.x * inv * wv.x * (gv.x / (1.f + expf(-gv.x)));
    float ry = v.y * inv * wv.y * (gv.y / (1.f + expf(-gv.y)));
    float rz = v.z * inv * wv.z * (gv.z / (1.f + expf(-gv.z)));
    float rw = v.w * inv * wv.w * (gv.w / (1.f + expf(-gv.w)));
    __half2* dst = (__half2*)(oh + (size_t)row * 128);
    dst[lane * 2]     = __floats2half2_rn(rx, ry);
    dst[lane * 2 + 1] = __floats2half2_rn(rz, rw);
}

// ---------------- launch ----------------
extern "C" void kernel_launch(void* const* d_in, const int* in_sizes, int n_in,
                              void* d_out, int out_size) {
    const float* hs    = (const float*)d_in[0];
    const float* ln1   = (const float*)d_in[1];
    const float* ln2   = (const float*)d_in[2];
    const float* wq    = (const float*)d_in[3];
    const float* wk    = (const float*)d_in[4];
    const float* wv    = (const float*)d_in[5];
    const float* wg    = (const float*)d_in[6];
    const float* wo    = (const float*)d_in[7];
    const float* cq    = (const float*)d_in[8];
    const float* ck    = (const float*)d_in[9];
    const float* cv    = (const float*)d_in[10];
    const float* gn    = (const float*)d_in[11];
    const float* wgate = (const float*)d_in[12];
    const float* wup   = (const float*)d_in[13];
    const float* wdown = (const float*)d_in[14];
    float* out = (float*)d_out;

    cudaFuncSetAttribute(hgemm_t<0>, cudaFuncAttributeMaxDynamicSharedMemorySize, SMEM_GEMM);
    cudaFuncSetAttribute(hgemm_t<1>, cudaFuncAttributeMaxDynamicSharedMemorySize, SMEM_GEMM);
    cudaFuncSetAttribute(hgemm_t<2>, cudaFuncAttributeMaxDynamicSharedMemorySize, SMEM_GEMM);
    cudaFuncSetAttribute(ret_phase1, cudaFuncAttributeMaxDynamicSharedMemorySize, SMEM_P1);
    cudaFuncSetAttribute(ret_phase3, cudaFuncAttributeMaxDynamicSharedMemorySize, SMEM_P3);

    float *o, *hbuf;
    __half *big, *qh, *kh, *vh, *Sh, *xh, *oh, *m1h, *bt;
    cudaGetSymbolAddress((void**)&big, g_big);
    cudaGetSymbolAddress((void**)&qh,  g_qh);
    cudaGetSymbolAddress((void**)&kh,  g_kh);
    cudaGetSymbolAddress((void**)&vh,  g_vh);
    cudaGetSymbolAddress((void**)&o,   g_o);
    cudaGetSymbolAddress((void**)&hbuf, g_h);
    cudaGetSymbolAddress((void**)&Sh,  g_Sh);
    cudaGetSymbolAddress((void**)&xh,  g_xh);
    cudaGetSymbolAddress((void**)&oh,  g_oh);
    cudaGetSymbolAddress((void**)&m1h, g_m1h);
    cudaGetSymbolAddress((void**)&bt,  g_bt);

    rope_table_kernel<<<(TT * 64 + 255) / 256, 256>>>();
    rmsnorm_kernel<<<BT, 256>>>(hs, ln1, xh, RMS_EPS);

    dim3 tD(DD / 32, DD / 32), tI1(II / 32, DD / 32), tI2(DD / 32, II / 32), tb(32, 8);

    convT_kernel<<<tD, tb>>>(wq, bt,             DD, DD, 1, 0);
    convT_kernel<<<tD, tb>>>(wk, bt + 1024 * DD, DD, DD, 1, 0);
    convT_kernel<<<tD, tb>>>(wv, bt + 2048 * DD, DD, DD, 1, 0);
    convT_kernel<<<tD, tb>>>(wg, bt + 3072 * DD, DD, DD, 1, 0);
    dim3 gQKVG(4096 / 128, BT / 128);
    hgemm_t<1><<<gQKVG, 256, SMEM_GEMM>>>(xh, bt, nullptr, big, BT, 4096, DD);

    const int crblocks = (BB * (TT / 4) * HH * 16) / 256;
    const int cvblocks = BB * TT / 4;
    conv_silu_rope_kernel<<<crblocks, 256>>>(big,        cq, qh);
    conv_silu_rope_kernel<<<crblocks, 256>>>(big + 1024, ck, kh);
    conv_silu_h_kernel<<<cvblocks, 256>>>(big + 2048, cv, vh);

    dim3 gc(NC, HH, BB);
    ret_phase1<<<gc, 256, SMEM_P1>>>(kh, vh, Sh);
    ret_scan<<<BB * HH * 32, 256>>>(Sh);
    ret_phase3<<<gc, 256, SMEM_P3>>>(qh, kh, vh, Sh, o);

    gate_kernel<<<(BT * HH) / 8, 256>>>(o, big, gn, oh);
    convT_kernel<<<tD, tb>>>(wo, bt, DD, DD, 1, 0);
    dim3 gD(DD / 128, BT / 128);
    hgemm_t<0><<<gD, 256, SMEM_GEMM>>>(oh, bt, hs, hbuf, BT, DD, DD);

    rmsnorm_kernel<<<BT, 256>>>(hbuf, ln2, xh, RMS_EPS);
    convT_kernel<<<tI1, tb>>>(wgate, bt, DD, II, 2, 0);
    convT_kernel<<<tI1, tb>>>(wup,   bt, DD, II, 2, 1);
    dim3 gMLP(5632 / 128, BT / 128);
    hgemm_t<2><<<gMLP, 256, SMEM_GEMM>>>(xh, bt, nullptr, m1h, BT, 5632, DD);
    convT_kernel<<<tI2, tb>>>(wdown, bt, II, DD, 1, 0);
    hgemm_t<0><<<gD, 256, SMEM_GEMM>>>(m1h, bt, hbuf, out, BT, DD, II);
}

// round 12
// speedup vs baseline: 7.4933x; 1.0038x over previous
#include <cuda_runtime.h>
#include <cuda_fp16.h>
#include <math.h>
#include <stdint.h>

#define BB 4
#define TT 8192
#define DD 1024
#define HH 8
#define II 2816
#define NC 128
#define BT (BB*TT)

#define RMS_EPS 1e-6f
#define GATE_EPS 1e-5f

// ---------------- scratch ----------------
__device__ __half g_big[(size_t)BT*4096];
__device__ __half g_qh [(size_t)BT*DD];
__device__ __half g_kh [(size_t)BT*DD];
__device__ __half g_vh [(size_t)BT*DD];
__device__ float  g_h [(size_t)BT*DD];
__device__ __half g_Sh[(size_t)BB*HH*NC*128*128];
__device__ __half g_xh [(size_t)BT*DD];
__device__ __half g_oh [(size_t)BT*DD];
__device__ __half g_m1h[(size_t)BT*II];
__device__ __half g_bt [(size_t)13568*DD];   // rows: 0..4095 qkvg | 4096..5119 wo | 5120..10751 mlp(il) | 10752..13567 down
__device__ float  g_cos[TT*64];
__device__ float  g_sin[TT*64];

// ---------------- helpers ----------------
__device__ __forceinline__ float4 ldh4(const __half* p) {
    uint2 u = *(const uint2*)p;
    float2 f0 = __half22float2(*(__half2*)&u.x);
    float2 f1 = __half22float2(*(__half2*)&u.y);
    return make_float4(f0.x, f0.y, f1.x, f1.y);
}
__device__ __forceinline__ void mma_fp16(float* c, const uint32_t* a, const uint32_t* b) {
    asm volatile("mma.sync.aligned.m16n8k16.row.col.f32.f16.f16.f32 "
        "{%0,%1,%2,%3}, {%4,%5,%6,%7}, {%8,%9}, {%0,%1,%2,%3};"
        : "+f"(c[0]), "+f"(c[1]), "+f"(c[2]), "+f"(c[3])
        : "r"(a[0]), "r"(a[1]), "r"(a[2]), "r"(a[3]), "r"(b[0]), "r"(b[1]));
}
__device__ __forceinline__ void cpasync16(uint32_t s, const void* g) {
    asm volatile("cp.async.cg.shared.global [%0], [%1], 16;" :: "r"(s), "l"(g));
}
__device__ __forceinline__ void ldsm_x4(uint32_t* r, uint32_t addr) {
    asm volatile("ldmatrix.sync.aligned.m8n8.x4.shared.b16 {%0,%1,%2,%3}, [%4];"
        : "=r"(r[0]), "=r"(r[1]), "=r"(r[2]), "=r"(r[3]) : "r"(addr));
}
__device__ __forceinline__ void ldsm_x4_t(uint32_t* r, uint32_t addr) {
    asm volatile("ldmatrix.sync.aligned.m8n8.x4.trans.shared.b16 {%0,%1,%2,%3}, [%4];"
        : "=r"(r[0]), "=r"(r[1]), "=r"(r[2]), "=r"(r[3]) : "r"(addr));
}

// ---------------- rmsnorm -> fp16 out ----------------
__global__ void rmsnorm_kernel(const float* __restrict__ x, const float* __restrict__ w,
                               __half* __restrict__ out, float eps) {
    int row = blockIdx.x;
    const float4* xr = (const float4*)(x + (size_t)row * DD);
    float4 v = xr[threadIdx.x];
    float s = v.x * v.x + v.y * v.y + v.z * v.z + v.w * v.w;
    __shared__ float red[8];
    #pragma unroll
    for (int o = 16; o > 0; o >>= 1) s += __shfl_down_sync(0xffffffffu, s, o);
    if ((threadIdx.x & 31) == 0) red[threadIdx.x >> 5] = s;
    __syncthreads();
    if (threadIdx.x < 8) {
        s = red[threadIdx.x];
        #pragma unroll
        for (int o = 4; o > 0; o >>= 1) s += __shfl_down_sync(0xffu, s, o);
        if (threadIdx.x == 0) red[0] = s;
    }
    __syncthreads();
    float inv = rsqrtf(red[0] / (float)DD + eps);
    float4 wv = ((const float4*)w)[threadIdx.x];
    __half2* orow = (__half2*)(out + (size_t)row * DD);
    orow[threadIdx.x * 2]     = __floats2half2_rn(v.x * inv * wv.x, v.y * inv * wv.y);
    orow[threadIdx.x * 2 + 1] = __floats2half2_rn(v.z * inv * wv.z, v.w * inv * wv.w);
}

// ---------------- batched weight convert+transpose ----------------
// 5 DxD weights -> rows z*1024
__global__ void convT5(const float* __restrict__ w0, const float* __restrict__ w1,
                       const float* __restrict__ w2, const float* __restrict__ w3,
                       const float* __restrict__ w4, __half* __restrict__ Wt) {
    __shared__ float tile[32][33];
    const float* W = (blockIdx.z == 0) ? w0 : (blockIdx.z == 1) ? w1 :
                     (blockIdx.z == 2) ? w2 : (blockIdx.z == 3) ? w3 : w4;
    __half* dst = Wt + (size_t)blockIdx.z * 1024 * DD;
    int n0 = blockIdx.x * 32, k0 = blockIdx.y * 32;
    #pragma unroll
    for (int j = threadIdx.y; j < 32; j += 8)
        tile[j][threadIdx.x] = W[(size_t)(k0 + j) * DD + n0 + threadIdx.x];
    __syncthreads();
    #pragma unroll
    for (int j = threadIdx.y; j < 32; j += 8)
        dst[(size_t)(n0 + j) * DD + k0 + threadIdx.x] = __float2half_rn(tile[threadIdx.x][j]);
}
// wgate/wup (DxII), interleaved rows: gate col j -> 2j, up col j -> 2j+1
__global__ void convTI(const float* __restrict__ wg, const float* __restrict__ wu,
                       __half* __restrict__ Wt) {
    __shared__ float tile[32][33];
    const float* W = blockIdx.z ? wu : wg;
    int ro = blockIdx.z;
    int n0 = blockIdx.x * 32, k0 = blockIdx.y * 32;
    #pragma unroll
    for (int j = threadIdx.y; j < 32; j += 8)
        tile[j][threadIdx.x] = W[(size_t)(k0 + j) * II + n0 + threadIdx.x];
    __syncthreads();
    #pragma unroll
    for (int j = threadIdx.y; j < 32; j += 8)
        Wt[((size_t)(n0 + j) * 2 + ro) * DD + k0 + threadIdx.x] = __float2half_rn(tile[threadIdx.x][j]);
}
// wdown (IIxD)
__global__ void convTW(const float* __restrict__ W, __half* __restrict__ Wt) {
    __shared__ float tile[32][33];
    int n0 = blockIdx.x * 32, k0 = blockIdx.y * 32;
    #pragma unroll
    for (int j = threadIdx.y; j < 32; j += 8)
        tile[j][threadIdx.x] = W[(size_t)(k0 + j) * DD + n0 + threadIdx.x];
    __syncthreads();
    #pragma unroll
    for (int j = threadIdx.y; j < 32; j += 8)
        Wt[(size_t)(n0 + j) * II + k0 + threadIdx.x] = __float2half_rn(tile[threadIdx.x][j]);
}

// ================= fp16 tensor-core GEMM =================
#define BKH 64
#define XW 36
#define AW (128*XW)
#define BW (128*XW)
#define STG (AW+BW)
#define SMEM_GEMM (3*STG*4)

template <int MODE>
__global__ __launch_bounds__(256, 2)
void hgemm_t(const __half* __restrict__ A, const __half* __restrict__ Bt,
             const float* __restrict__ R, void* __restrict__ Cv,
             int M, int N, int K) {
    extern __shared__ uint32_t smw[];

    const int tid = threadIdx.x;
    const int lane = tid & 31;
    const int w = tid >> 5;
    const int g = lane >> 2, q = lane & 3;
    const int wm = (w & 1) * 64;
    const int wn = (w >> 1) * 32;
    const int bm = blockIdx.y * 128, bn = blockIdx.x * 128;

    uint32_t sBase = (uint32_t)__cvta_generic_to_shared(smw);

    const uint32_t aLane = (uint32_t)((wm + (lane & 15)) * XW + ((lane >> 4) << 2));
    const uint32_t bLane = (uint32_t)((wn + (lane & 7) + ((lane >> 4) << 3)) * XW + (((lane >> 3) & 1) << 2));

    float acc[4][4][4];
    #pragma unroll
    for (int i = 0; i < 4; ++i)
        #pragma unroll
        for (int j = 0; j < 4; ++j)
            #pragma unroll
            for (int r = 0; r < 4; ++r) acc[i][j][r] = 0.f;

    const int ntile = K / BKH;

    auto loadTile = [&](int t, int s) {
        #pragma unroll
        for (int i = 0; i < 4; ++i) {
            int idx = i * 256 + tid;
            int row = idx >> 3, kc = (idx & 7) * 8;
            cpasync16(sBase + (uint32_t)((s * STG + row * XW) * 4 + kc * 2),
                      A + (size_t)(bm + row) * K + t * BKH + kc);
        }
        #pragma unroll
        for (int i = 0; i < 4; ++i) {
            int idx = i * 256 + tid;
            int n = idx >> 3, kc = (idx & 7) * 8;
            cpasync16(sBase + (uint32_t)((s * STG + AW + n * XW) * 4 + kc * 2),
                      Bt + (size_t)(bn + n) * K + t * BKH + kc);
        }
        asm volatile("cp.async.commit_group;");
    };

    loadTile(0, 0);
    if (ntile > 1) loadTile(1, 1);

    for (int t = 0; t < ntile; ++t) {
        int s = t % 3;
        if (t + 2 < ntile) asm volatile("cp.async.wait_group 1;");
        else               asm volatile("cp.async.wait_group 0;");
        __syncthreads();
        if (t + 2 < ntile) loadTile(t + 2, (t + 2) % 3);

        const uint32_t aOff = sBase + (uint32_t)(s * STG) * 4;
        const uint32_t bOff = sBase + (uint32_t)(s * STG + AW) * 4;
        #pragma unroll
        for (int ks = 0; ks < 4; ++ks) {
            uint32_t a[4][4], b[4][2];
            #pragma unroll
            for (int mt = 0; mt < 4; ++mt)
                ldsm_x4(a[mt], aOff + (aLane + (uint32_t)(mt * 16 * XW + ks * 8)) * 4);
            #pragma unroll
            for (int np = 0; np < 2; ++np) {
                uint32_t bb[4];
                ldsm_x4(bb, bOff + (bLane + (uint32_t)(np * 16 * XW + ks * 8)) * 4);
                b[np * 2][0]     = bb[0];
                b[np * 2][1]     = bb[1];
                b[np * 2 + 1][0] = bb[2];
                b[np * 2 + 1][1] = bb[3];
            }
            #pragma unroll
            for (int mt = 0; mt < 4; ++mt)
                #pragma unroll
                for (int nt = 0; nt < 4; ++nt)
                    mma_fp16(acc[mt][nt], a[mt], b[nt]);
        }
    }

    #pragma unroll
    for (int mt = 0; mt < 4; ++mt) {
        #pragma unroll
        for (int half = 0; half < 2; ++half) {
            int row = bm + wm + mt * 16 + g + half * 8;
            #pragma unroll
            for (int nt = 0; nt < 4; ++nt) {
                float vx = acc[mt][nt][half * 2 + 0];
                float vy = acc[mt][nt][half * 2 + 1];
                if (MODE == 0) {
                    int col = bn + wn + nt * 8 + q * 2;
                    size_t off = (size_t)row * N + col;
                    float* C = (float*)Cv;
                    float2 v2;
                    v2.x = vx; v2.y = vy;
                    if (R) {
                        const float2 rr = *(const float2*)(R + off);
                        v2.x += rr.x; v2.y += rr.y;
                    }
                    *(float2*)(C + off) = v2;
                } else if (MODE == 1) {
                    int col = bn + wn + nt * 8 + q * 2;
                    __half2* C = (__half2*)Cv;
                    C[((size_t)row * N + col) >> 1] = __floats2half2_rn(vx, vy);
                } else {
                    int oc = (bn + wn) / 2 + nt * 4 + q;
                    float r = (vx / (1.f + expf(-vx))) * vy;
                    __half* C = (__half*)Cv;
                    C[(size_t)row * (N >> 1) + oc] = __float2half_rn(r);
                }
            }
        }
    }
}

// ---------------- conv(K=4)+silu+RoPE fused (q,k path) ----------------
__global__ void conv_silu_rope_kernel(const __half* __restrict__ x, const float* __restrict__ w,
                                      __half* __restrict__ y) {
    int idx = blockIdx.x * 256 + threadIdx.x;
    int j4 = idx & 15;
    int h  = (idx >> 4) & 7;
    int t4 = (idx >> 7) & 2047;
    int b  = idx >> 18;
    const float4* w4 = (const float4*)w;
    int d1 = h * 128 + j4 * 4;
    float4 wa[4], wb[4];
    #pragma unroll
    for (int r = 0; r < 4; ++r) { wa[r] = w4[d1 + r]; wb[r] = w4[d1 + 64 + r]; }
    int t0 = t4 * 4;
    float4 xv1[7], xv2[7];
    #pragma unroll
    for (int j = 0; j < 7; ++j) {
        int tt = t0 - 3 + j;
        if (tt >= 0) {
            const __half* p = x + ((size_t)(b * TT + tt)) * 4096 + d1;
            xv1[j] = ldh4(p);
            xv2[j] = ldh4(p + 64);
        } else {
            xv1[j] = make_float4(0.f, 0.f, 0.f, 0.f);
            xv2[j] = make_float4(0.f, 0.f, 0.f, 0.f);
        }
    }
    const float4* cos4 = (const float4*)g_cos;
    const float4* sin4 = (const float4*)g_sin;
    __half2* y2 = (__half2*)y;
    #pragma unroll
    for (int i = 0; i < 4; ++i) {
        float4 a1, a2;
        a1.x = xv1[i].x * wa[0].x + xv1[i+1].x * wa[0].y + xv1[i+2].x * wa[0].z + xv1[i+3].x * wa[0].w;
        a1.y = xv1[i].y * wa[1].x + xv1[i+1].y * wa[1].y + xv1[i+2].y * wa[1].z + xv1[i+3].y * wa[1].w;
        a1.z = xv1[i].z * wa[2].x + xv1[i+1].z * wa[2].y + xv1[i+2].z * wa[2].z + xv1[i+3].z * wa[2].w;
        a1.w = xv1[i].w * wa[3].x + xv1[i+1].w * wa[3].y + xv1[i+2].w * wa[3].z + xv1[i+3].w * wa[3].w;
        a2.x = xv2[i].x * wb[0].x + xv2[i+1].x * wb[0].y + xv2[i+2].x * wb[0].z + xv2[i+3].x * wb[0].w;
        a2.y = xv2[i].y * wb[1].x + xv2[i+1].y * wb[1].y + xv2[i+2].y * wb[1].z + xv2[i+3].y * wb[1].w;
        a2.z = xv2[i].z * wb[2].x + xv2[i+1].z * wb[2].y + xv2[i+2].z * wb[2].z + xv2[i+3].z * wb[2].w;
        a2.w = xv2[i].w * wb[3].x + xv2[i+1].w * wb[3].y + xv2[i+2].w * wb[3].z + xv2[i+3].w * wb[3].w;
        a1.x /= (1.f + expf(-a1.x)); a1.y /= (1.f + expf(-a1.y));
        a1.z /= (1.f + expf(-a1.z)); a1.w /= (1.f + expf(-a1.w));
        a2.x /= (1.f + expf(-a2.x)); a2.y /= (1.f + expf(-a2.y));
        a2.z /= (1.f + expf(-a2.z)); a2.w /= (1.f + expf(-a2.w));
        int t = t0 + i;
        float4 c = cos4[t * 16 + j4];
        float4 s = sin4[t * 16 + j4];
        float4 o1, o2;
        o1.x = a1.x * c.x - a2.x * s.x;  o2.x = a1.x * s.x + a2.x * c.x;
        o1.y = a1.y * c.y - a2.y * s.y;  o2.y = a1.y * s.y + a2.y * c.y;
        o1.z = a1.z * c.z - a2.z * s.z;  o2.z = a1.z * s.z + a2.z * c.z;
        o1.w = a1.w * c.w - a2.w * s.w;  o2.w = a1.w * s.w + a2.w * c.w;
        size_t base1 = (((size_t)(b * TT + t)) * DD + d1) >> 1;
        y2[base1]      = __floats2half2_rn(o1.x, o1.y);
        y2[base1 + 1]  = __floats2half2_rn(o1.z, o1.w);
        y2[base1 + 32] = __floats2half2_rn(o2.x, o2.y);
        y2[base1 + 33] = __floats2half2_rn(o2.z, o2.w);
    }
}

// ---------------- conv(K=4)+silu (v path) ----------------
__global__ void conv_silu_h_kernel(const __half* __restrict__ x, const float* __restrict__ w,
                                   __half* __restrict__ y) {
    int idx = blockIdx.x * 256 + threadIdx.x;
    int d4 = idx & 255;
    int rest = idx >> 8;
    int t4 = rest & (TT / 4 - 1);
    int b = rest >> 11;
    const float4* w4 = (const float4*)w;
    float4 wr0 = w4[d4 * 4 + 0], wr1 = w4[d4 * 4 + 1];
    float4 wr2 = w4[d4 * 4 + 2], wr3 = w4[d4 * 4 + 3];
    int t0 = t4 * 4;
    float4 xv[7];
    #pragma unroll
    for (int j = 0; j < 7; ++j) {
        int tt = t0 - 3 + j;
        xv[j] = (tt >= 0) ? ldh4(x + ((size_t)(b * TT + tt)) * 4096 + d4 * 4)
                          : make_float4(0.f, 0.f, 0.f, 0.f);
    }
    __half2* y2 = (__half2*)y;
    #pragma unroll
    for (int i = 0; i < 4; ++i) {
        float4 a;
        a.x = xv[i].x * wr0.x + xv[i+1].x * wr0.y + xv[i+2].x * wr0.z + xv[i+3].x * wr0.w;
        a.y = xv[i].y * wr1.x + xv[i+1].y * wr1.y + xv[i+2].y * wr1.z + xv[i+3].y * wr1.w;
        a.z = xv[i].z * wr2.x + xv[i+1].z * wr2.y + xv[i+2].z * wr2.z + xv[i+3].z * wr2.w;
        a.w = xv[i].w * wr3.x + xv[i+1].w * wr3.y + xv[i+2].w * wr3.z + xv[i+3].w * wr3.w;
        a.x /= (1.f + expf(-a.x)); a.y /= (1.f + expf(-a.y));
        a.z /= (1.f + expf(-a.z)); a.w /= (1.f + expf(-a.w));
        size_t bh = ((size_t)(b * TT + t0 + i)) * 512 + d4 * 2;
        y2[bh]     = __floats2half2_rn(a.x, a.y);
        y2[bh + 1] = __floats2half2_rn(a.z, a.w);
    }
}

// ---------------- RoPE table ----------------
__global__ void rope_table_kernel() {
    int idx = blockIdx.x * 256 + threadIdx.x;
    if (idx >= TT * 64) return;
    int t = idx >> 6, j = idx & 63;
    float invf = (float)(1.0 / pow(10000.0, (double)j / 64.0));
    float f = (float)t * invf;
    g_cos[idx] = (float)cos((double)f);
    g_sin[idx] = (float)sin((double)f);
}

// ================= retention phase 1 (HMMA): S = (k*dec)^T @ v =================
#define RSTR 136
#define SMEM_P1 ((64*RSTR + 64*RSTR) * 2)
__global__ __launch_bounds__(256, 2)
void ret_phase1(const __half* __restrict__ k, const __half* __restrict__ v,
                __half* __restrict__ S) {
    extern __shared__ __half smh[];
    __half* ks = smh;
    __half* vs = smh + 64 * RSTR;
    int c = blockIdx.x, h = blockIdx.y, b = blockIdx.z;
    float gamma = 1.f - exp2f(-5.f - (float)h);
    float lg = logf(gamma);
    int tid = threadIdx.x, lane = tid & 31, w = tid >> 5;
    int g = lane >> 2, q = lane & 3;
    uint32_t sk = (uint32_t)__cvta_generic_to_shared(ks);
    uint32_t sv = (uint32_t)__cvta_generic_to_shared(vs);

    #pragma unroll
    for (int it = 0; it < 4; ++it) {
        int x = it * 256 + tid;
        int row = x >> 4, ch = x & 15;
        cpasync16(sv + (uint32_t)(row * RSTR + ch * 8) * 2,
                  v + ((size_t)(b * TT + c * 64 + row) * DD + h * 128 + ch * 8));
    }
    asm volatile("cp.async.commit_group;");
    const __half2* k2 = (const __half2*)k;
    for (int x = tid; x < 4096; x += 256) {
        int row = x >> 6, d2 = x & 63;
        float dec = expf(lg * (float)(63 - row));
        float2 kf = __half22float2(k2[((size_t)(b * TT + c * 64 + row) * DD + h * 128) / 2 + d2]);
        *(__half2*)(ks + row * RSTR + d2 * 2) = __floats2half2_rn(kf.x * dec, kf.y * dec);
    }
    asm volatile("cp.async.wait_group 0;");
    __syncthreads();

    int m0 = (w & 3) * 32;
    int e0w = (w >> 2) * 64;
    float acc[2][8][4];
    #pragma unroll
    for (int i = 0; i < 2; ++i)
        #pragma unroll
        for (int j = 0; j < 8; ++j)
            #pragma unroll
            for (int r = 0; r < 4; ++r) acc[i][j][r] = 0.f;

    int aRow = (lane & 7) + ((lane >> 4) << 3);
    int aCol = ((lane >> 3) & 1) << 3;
    int bRow = (lane & 7) + (((lane >> 3) & 1) << 3);
    int bCol = (lane >> 4) << 3;

    #pragma unroll
    for (int kt = 0; kt < 4; ++kt) {
        int j0 = kt * 16;
        uint32_t a[2][4];
        #pragma unroll
        for (int mt = 0; mt < 2; ++mt)
            ldsm_x4_t(a[mt], sk + (uint32_t)((j0 + aRow) * RSTR + m0 + mt * 16 + aCol) * 2);
        #pragma unroll
        for (int np = 0; np < 4; ++np) {
            uint32_t bb[4];
            ldsm_x4_t(bb, sv + (uint32_t)((j0 + bRow) * RSTR + e0w + np * 16 + bCol) * 2);
            #pragma unroll
            for (int mt = 0; mt < 2; ++mt) {
                mma_fp16(acc[mt][np * 2],     a[mt], bb);
                mma_fp16(acc[mt][np * 2 + 1], a[mt], bb + 2);
            }
        }
    }

    size_t sb = (((size_t)(b * HH + h)) * NC + c) * 16384;
    __half2* S2 = (__half2*)S;
    #pragma unroll
    for (int mt = 0; mt < 2; ++mt) {
        #pragma unroll
        for (int nt = 0; nt < 8; ++nt) {
            int e = e0w + nt * 8 + q * 2;
            int d1 = m0 + mt * 16 + g;
            S2[(sb + (size_t)d1 * 128 + e) >> 1]       = __floats2half2_rn(acc[mt][nt][0], acc[mt][nt][1]);
            S2[(sb + (size_t)(d1 + 8) * 128 + e) >> 1] = __floats2half2_rn(acc[mt][nt][2], acc[mt][nt][3]);
        }
    }
}

// ---------------- retention phase 2: parallel exclusive scan (half2) ----------------
__global__ void ret_scan(__half* __restrict__ S) {
    int bh = blockIdx.x >> 5;
    int pairIdx = ((blockIdx.x & 31) << 8) + threadIdx.x;
    int h = bh & 7;
    float gamma = 1.f - exp2f(-5.f - (float)h);
    float cdec = expf(logf(gamma) * 64.f);
    float2 carry = make_float2(0.f, 0.f);
    __half2* S2 = (__half2*)S;
    size_t base = (size_t)bh * NC * 8192 + pairIdx;
    for (int c = 0; c < NC; ++c) {
        size_t idx = base + (size_t)c * 8192;
        float2 loc = __half22float2(S2[idx]);
        S2[idx] = __floats2half2_rn(carry.x, carry.y);
        carry.x = carry.x * cdec + loc.x;
        carry.y = carry.y * cdec + loc.y;
    }
}

// ================= retention phase 3 (HMMA) + fused gate =================
#define ASTR3 72
#define SMEM_P3 ((3*64*RSTR + 64*ASTR3) * 2 + 512)
__global__ __launch_bounds__(256, 2)
void ret_phase3(const __half* __restrict__ q, const __half* __restrict__ k,
                const __half* __restrict__ v, const __half* __restrict__ S,
                const __half* __restrict__ gbig, const float* __restrict__ gnw,
                __half* __restrict__ oh) {
    extern __shared__ __half smh[];
    __half* qs  = smh;
    __half* ksb = smh + 64 * RSTR;
    __half* vsb = smh + 2 * 64 * RSTR;
    __half* ats = smh + 3 * 64 * RSTR;
    float*  rn  = (float*)(smh + 3 * 64 * RSTR + 64 * ASTR3);   // [2][64]
    int c = blockIdx.x, h = blockIdx.y, b = blockIdx.z;
    float gamma = 1.f - exp2f(-5.f - (float)h);
    float lg = logf(gamma);
    const float scale = 0.08838834764831845f;
    int tid = threadIdx.x, lane = tid & 31, w = tid >> 5;
    int g = lane >> 2, qq = lane & 3;
    uint32_t sq = (uint32_t)__cvta_generic_to_shared(qs);
    uint32_t sk = (uint32_t)__cvta_generic_to_shared(ksb);
    uint32_t sv = (uint32_t)__cvta_generic_to_shared(vsb);
    uint32_t sa = (uint32_t)__cvta_generic_to_shared(ats);

    #pragma unroll
    for (int it = 0; it < 4; ++it) {
        int x = it * 256 + tid;
        int row = x >> 4, ch = x & 15;
        size_t gg = (size_t)(b * TT + c * 64 + row) * DD + h * 128 + ch * 8;
        uint32_t off = (uint32_t)(row * RSTR + ch * 8) * 2;
        cpasync16(sq + off, q + gg);
        cpasync16(sk + off, k + gg);
        cpasync16(sv + off, v + gg);
    }
    asm volatile("cp.async.commit_group;");
    asm volatile("cp.async.wait_group 0;");
    __syncthreads();

    const int mt = w & 3;
    const int m0 = mt * 16;
    const int eh = w >> 2;
    size_t sbg = (((size_t)(b * HH + h)) * NC + c) * 16384;

    int aRow = m0 + (lane & 15);
    int aCol = (lane >> 4) << 3;
    int bRowN = (lane & 7) + ((lane >> 4) << 3);
    int bColN = ((lane >> 3) & 1) << 3;
    int tRow = (lane & 7) + (((lane >> 3) & 1) << 3);
    int tCol = (lane >> 4) << 3;

    // Step A: att = q @ k^T
    {
        int n0 = eh * 32;
        float accT[4][4];
        #pragma unroll
        for (int i = 0; i < 4; ++i)
            #pragma unroll
            for (int r = 0; r < 4; ++r) accT[i][r] = 0.f;
        #pragma unroll
        for (int kt = 0; kt < 8; ++kt) {
            uint32_t a[4];
            ldsm_x4(a, sq + (uint32_t)(aRow * RSTR + aCol + kt * 16) * 2);
            #pragma unroll
            for (int np = 0; np < 2; ++np) {
                uint32_t bb[4];
                ldsm_x4(bb, sk + (uint32_t)((n0 + np * 16 + bRowN) * RSTR + bColN + kt * 16) * 2);
                mma_fp16(accT[np * 2],     a, bb);
                mma_fp16(accT[np * 2 + 1], a, bb + 2);
            }
        }
        #pragma unroll
        for (int nt = 0; nt < 4; ++nt) {
            int j0 = n0 + nt * 8 + qq * 2;
            int i1 = m0 + g, i2 = i1 + 8;
            float f0 = (i1 >= j0)     ? scale * expf(lg * (float)(i1 - j0))     : 0.f;
            float f1 = (i1 >= j0 + 1) ? scale * expf(lg * (float)(i1 - j0 - 1)) : 0.f;
            float f2 = (i2 >= j0)     ? scale * expf(lg * (float)(i2 - j0))     : 0.f;
            float f3 = (i2 >= j0 + 1) ? scale * expf(lg * (float)(i2 - j0 - 1)) : 0.f;
            *(__half2*)(ats + i1 * ASTR3 + j0) = __floats2half2_rn(accT[nt][0] * f0, accT[nt][1] * f1);
            *(__half2*)(ats + i2 * ASTR3 + j0) = __floats2half2_rn(accT[nt][2] * f2, accT[nt][3] * f3);
        }
    }
    __syncthreads();

    // prefetch S[0:64] into ks buffer
    #pragma unroll
    for (int it = 0; it < 4; ++it) {
        int x = it * 256 + tid;
        int row = x >> 4, ch = x & 15;
        cpasync16(sk + (uint32_t)(row * RSTR + ch * 8) * 2, S + sbg + (size_t)row * 128 + ch * 8);
    }
    asm volatile("cp.async.commit_group;");

    // Step B: o1 = att @ v
    const int e0w = eh * 64;
    float accA[8][4];
    #pragma unroll
    for (int i = 0; i < 8; ++i)
        #pragma unroll
        for (int r = 0; r < 4; ++r) accA[i][r] = 0.f;
    #pragma unroll
    for (int kt = 0; kt < 4; ++kt) {
        int j0 = kt * 16;
        uint32_t a[4];
        ldsm_x4(a, sa + (uint32_t)(aRow * ASTR3 + aCol + kt * 16) * 2);
        #pragma unroll
        for (int np = 0; np < 4; ++np) {
            uint32_t bb[4];
            ldsm_x4_t(bb, sv + (uint32_t)((j0 + tRow) * RSTR + e0w + np * 16 + tCol) * 2);
            mma_fp16(accA[np * 2],     a, bb);
            mma_fp16(accA[np * 2 + 1], a, bb + 2);
        }
    }
    asm volatile("cp.async.wait_group 0;");
    __syncthreads();

    // prefetch S[64:128] into vs buffer
    #pragma unroll
    for (int it = 0; it < 4; ++it) {
        int x = it * 256 + tid;
        int row = x >> 4, ch = x & 15;
        cpasync16(sv + (uint32_t)(row * RSTR + ch * 8) * 2, S + sbg + (size_t)(64 + row) * 128 + ch * 8);
    }
    asm volatile("cp.async.commit_group;");

    // Step C1: accB += q @ S[0:64]
    float accB[8][4];
    #pragma unroll
    for (int i = 0; i < 8; ++i)
        #pragma unroll
        for (int r = 0; r < 4; ++r) accB[i][r] = 0.f;
    #pragma unroll
    for (int kt = 0; kt < 4; ++kt) {
        int d0 = kt * 16;
        uint32_t a[4];
        ldsm_x4(a, sq + (uint32_t)(aRow * RSTR + aCol + kt * 16) * 2);
        #pragma unroll
        for (int np = 0; np < 4; ++np) {
            uint32_t bb[4];
            ldsm_x4_t(bb, sk + (uint32_t)((d0 + tRow) * RSTR + e0w + np * 16 + tCol) * 2);
            mma_fp16(accB[np * 2],     a, bb);
            mma_fp16(accB[np * 2 + 1], a, bb + 2);
        }
    }
    asm volatile("cp.async.wait_group 0;");
    __syncthreads();

    // Step C2: accB += q @ S[64:128]
    #pragma unroll
    for (int kt = 4; kt < 8; ++kt) {
        int d0 = (kt - 4) * 16;
        uint32_t a[4];
        ldsm_x4(a, sq + (uint32_t)(aRow * RSTR + aCol + kt * 16) * 2);
        #pragma unroll
        for (int np = 0; np < 4; ++np) {
            uint32_t bb[4];
            ldsm_x4_t(bb, sv + (uint32_t)((d0 + tRow) * RSTR + e0w + np * 16 + tCol) * 2);
            mma_fp16(accB[np * 2],     a, bb);
            mma_fp16(accB[np * 2 + 1], a, bb + 2);
        }
    }

    // combine + fused rmsnorm(128) * gnw * silu(g) -> fp16 oh
    int i1 = m0 + g;
    int i2 = i1 + 8;
    float cf1 = scale * expf(lg * (float)(i1 + 1));
    float cf2 = scale * expf(lg * (float)(i1 + 9));
    float ss1 = 0.f, ss2 = 0.f;
    #pragma unroll
    for (int nt = 0; nt < 8; ++nt) {
        accA[nt][0] += cf1 * accB[nt][0];
        accA[nt][1] += cf1 * accB[nt][1];
        accA[nt][2] += cf2 * accB[nt][2];
        accA[nt][3] += cf2 * accB[nt][3];
        ss1 += accA[nt][0] * accA[nt][0] + accA[nt][1] * accA[nt][1];
        ss2 += accA[nt][2] * accA[nt][2] + accA[nt][3] * accA[nt][3];
    }
    ss1 += __shfl_xor_sync(0xffffffffu, ss1, 1);
    ss1 += __shfl_xor_sync(0xffffffffu, ss1, 2);
    ss2 += __shfl_xor_sync(0xffffffffu, ss2, 1);
    ss2 += __shfl_xor_sync(0xffffffffu, ss2, 2);
    if (qq == 0) { rn[eh * 64 + i1] = ss1; rn[eh * 64 + i2] = ss2; }
    __syncthreads();
    float inv1 = rsqrtf((rn[i1] + rn[64 + i1]) * 0.0078125f + GATE_EPS);
    float inv2 = rsqrtf((rn[i2] + rn[64 + i2]) * 0.0078125f + GATE_EPS);

    size_t r1 = (size_t)(b * TT + c * 64 + i1);
    size_t r2 = r1 + 8;
    __half2* dst = (__half2*)oh;
    #pragma unroll
    for (int nt = 0; nt < 8; ++nt) {
        int e = e0w + nt * 8 + qq * 2;
        float2 gw = *(const float2*)(gnw + e);
        float2 g1 = __half22float2(*(const __half2*)(gbig + r1 * 4096 + 3072 + h * 128 + e));
        float2 g2 = __half22float2(*(const __half2*)(gbig + r2 * 4096 + 3072 + h * 128 + e));
        float o1x = accA[nt][0] * inv1 * gw.x * (g1.x / (1.f + expf(-g1.x)));
        float o1y = accA[nt][1] * inv1 * gw.y * (g1.y / (1.f + expf(-g1.y)));
        float o2x = accA[nt][2] * inv2 * gw.x * (g2.x / (1.f + expf(-g2.x)));
        float o2y = accA[nt][3] * inv2 * gw.y * (g2.y / (1.f + expf(-g2.y)));
        dst[(r1 * 1024 + h * 128 + e) >> 1] = __floats2half2_rn(o1x, o1y);
        dst[(r2 * 1024 + h * 128 + e) >> 1] = __floats2half2_rn(o2x, o2y);
    }
}

// ---------------- launch ----------------
extern "C" void kernel_launch(void* const* d_in, const int* in_sizes, int n_in,
                              void* d_out, int out_size) {
    const float* hs    = (const float*)d_in[0];
    const float* ln1   = (const float*)d_in[1];
    const float* ln2   = (const float*)d_in[2];
    const float* wq    = (const float*)d_in[3];
    const float* wk    = (const float*)d_in[4];
    const float* wv    = (const float*)d_in[5];
    const float* wg    = (const float*)d_in[6];
    const float* wo    = (const float*)d_in[7];
    const float* cq    = (const float*)d_in[8];
    const float* ck    = (const float*)d_in[9];
    const float* cv    = (const float*)d_in[10];
    const float* gn    = (const float*)d_in[11];
    const float* wgate = (const float*)d_in[12];
    const float* wup   = (const float*)d_in[13];
    const float* wdown = (const float*)d_in[14];
    float* out = (float*)d_out;

    cudaFuncSetAttribute(hgemm_t<0>, cudaFuncAttributeMaxDynamicSharedMemorySize, SMEM_GEMM);
    cudaFuncSetAttribute(hgemm_t<1>, cudaFuncAttributeMaxDynamicSharedMemorySize, SMEM_GEMM);
    cudaFuncSetAttribute(hgemm_t<2>, cudaFuncAttributeMaxDynamicSharedMemorySize, SMEM_GEMM);
    cudaFuncSetAttribute(ret_phase1, cudaFuncAttributeMaxDynamicSharedMemorySize, SMEM_P1);
    cudaFuncSetAttribute(ret_phase3, cudaFuncAttributeMaxDynamicSharedMemorySize, SMEM_P3);

    float *hbuf;
    __half *big, *qh, *kh, *vh, *Sh, *xh, *oh, *m1h, *bt;
    cudaGetSymbolAddress((void**)&big, g_big);
    cudaGetSymbolAddress((void**)&qh,  g_qh);
    cudaGetSymbolAddress((void**)&kh,  g_kh);
    cudaGetSymbolAddress((void**)&vh,  g_vh);
    cudaGetSymbolAddress((void**)&hbuf, g_h);
    cudaGetSymbolAddress((void**)&Sh,  g_Sh);
    cudaGetSymbolAddress((void**)&xh,  g_xh);
    cudaGetSymbolAddress((void**)&oh,  g_oh);
    cudaGetSymbolAddress((void**)&m1h, g_m1h);
    cudaGetSymbolAddress((void**)&bt,  g_bt);

    __half* bt_wo   = bt + (size_t)4096 * DD;
    __half* bt_mlp  = bt + (size_t)5120 * DD;
    __half* bt_down = bt + (size_t)10752 * DD;

    // all weight converts up front (independent)
    dim3 tb(32, 8);
    convT5<<<dim3(32, 32, 5), tb>>>(wq, wk, wv, wg, wo, bt);
    convTI<<<dim3(88, 32, 2), tb>>>(wgate, wup, bt_mlp);
    convTW<<<dim3(32, 88, 1), tb>>>(wdown, bt_down);

    rope_table_kernel<<<(TT * 64 + 255) / 256, 256>>>();
    rmsnorm_kernel<<<BT, 256>>>(hs, ln1, xh, RMS_EPS);

    dim3 gQKVG(4096 / 128, BT / 128);
    hgemm_t<1><<<gQKVG, 256, SMEM_GEMM>>>(xh, bt, nullptr, big, BT, 4096, DD);

    const int crblocks = (BB * (TT / 4) * HH * 16) / 256;
    const int cvblocks = BB * TT / 4;
    conv_silu_rope_kernel<<<crblocks, 256>>>(big,        cq, qh);
    conv_silu_rope_kernel<<<crblocks, 256>>>(big + 1024, ck, kh);
    conv_silu_h_kernel<<<cvblocks, 256>>>(big + 2048, cv, vh);

    dim3 gc(NC, HH, BB);
    ret_phase1<<<gc, 256, SMEM_P1>>>(kh, vh, Sh);
    ret_scan<<<BB * HH * 32, 256>>>(Sh);
    ret_phase3<<<gc, 256, SMEM_P3>>>(qh, kh, vh, Sh, big, gn, oh);

    dim3 gD(DD / 128, BT / 128);
    hgemm_t<0><<<gD, 256, SMEM_GEMM>>>(oh, bt_wo, hs, hbuf, BT, DD, DD);

    rmsnorm_kernel<<<BT, 256>>>(hbuf, ln2, xh, RMS_EPS);
    dim3 gMLP(5632 / 128, BT / 128);
    hgemm_t<2><<<gMLP, 256, SMEM_GEMM>>>(xh, bt_mlp, nullptr, m1h, BT, 5632, DD);
    hgemm_t<0><<<gD, 256, SMEM_GEMM>>>(m1h, bt_down, hbuf, out, BT, DD, II);
}

// round 13
// speedup vs baseline: 7.7527x; 1.0346x over previous
#include <cuda_runtime.h>
#include <cuda_fp16.h>
#include <math.h>
#include <stdint.h>

#define BB 4
#define TT 8192
#define DD 1024
#define HH 8
#define II 2816
#define NC 128
#define BT (BB*TT)

#define RMS_EPS 1e-6f
#define GATE_EPS 1e-5f

// ---------------- scratch ----------------
__device__ __half g_big[(size_t)BT*4096];
__device__ __half g_qh [(size_t)BT*DD];
__device__ __half g_kh [(size_t)BT*DD];
__device__ __half g_vh [(size_t)BT*DD];
__device__ float  g_h [(size_t)BT*DD];
__device__ __half g_Sh[(size_t)BB*HH*NC*128*128];
__device__ __half g_xh [(size_t)BT*DD];
__device__ __half g_oh [(size_t)BT*DD];
__device__ __half g_m1h[(size_t)BT*II];
__device__ __half g_bt [(size_t)13568*DD];
__device__ float  g_cos[TT*64];
__device__ float  g_sin[TT*64];
__device__ float  g_invf[64];

// ---------------- helpers ----------------
__device__ __forceinline__ float4 ldh4(const __half* p) {
    uint2 u = *(const uint2*)p;
    float2 f0 = __half22float2(*(__half2*)&u.x);
    float2 f1 = __half22float2(*(__half2*)&u.y);
    return make_float4(f0.x, f0.y, f1.x, f1.y);
}
__device__ __forceinline__ void mma_fp16(float* c, const uint32_t* a, const uint32_t* b) {
    asm volatile("mma.sync.aligned.m16n8k16.row.col.f32.f16.f16.f32 "
        "{%0,%1,%2,%3}, {%4,%5,%6,%7}, {%8,%9}, {%0,%1,%2,%3};"
        : "+f"(c[0]), "+f"(c[1]), "+f"(c[2]), "+f"(c[3])
        : "r"(a[0]), "r"(a[1]), "r"(a[2]), "r"(a[3]), "r"(b[0]), "r"(b[1]));
}
__device__ __forceinline__ void cpasync16(uint32_t s, const void* g) {
    asm volatile("cp.async.cg.shared.global [%0], [%1], 16;" :: "r"(s), "l"(g));
}
__device__ __forceinline__ void ldsm_x4(uint32_t* r, uint32_t addr) {
    asm volatile("ldmatrix.sync.aligned.m8n8.x4.shared.b16 {%0,%1,%2,%3}, [%4];"
        : "=r"(r[0]), "=r"(r[1]), "=r"(r[2]), "=r"(r[3]) : "r"(addr));
}
__device__ __forceinline__ void ldsm_x4_t(uint32_t* r, uint32_t addr) {
    asm volatile("ldmatrix.sync.aligned.m8n8.x4.trans.shared.b16 {%0,%1,%2,%3}, [%4];"
        : "=r"(r[0]), "=r"(r[1]), "=r"(r[2]), "=r"(r[3]) : "r"(addr));
}

// ---------------- rmsnorm -> fp16 out ----------------
__global__ void rmsnorm_kernel(const float* __restrict__ x, const float* __restrict__ w,
                               __half* __restrict__ out, float eps) {
    int row = blockIdx.x;
    const float4* xr = (const float4*)(x + (size_t)row * DD);
    float4 v = xr[threadIdx.x];
    float s = v.x * v.x + v.y * v.y + v.z * v.z + v.w * v.w;
    __shared__ float red[8];
    #pragma unroll
    for (int o = 16; o > 0; o >>= 1) s += __shfl_down_sync(0xffffffffu, s, o);
    if ((threadIdx.x & 31) == 0) red[threadIdx.x >> 5] = s;
    __syncthreads();
    if (threadIdx.x < 8) {
        s = red[threadIdx.x];
        #pragma unroll
        for (int o = 4; o > 0; o >>= 1) s += __shfl_down_sync(0xffu, s, o);
        if (threadIdx.x == 0) red[0] = s;
    }
    __syncthreads();
    float inv = rsqrtf(red[0] / (float)DD + eps);
    float4 wv = ((const float4*)w)[threadIdx.x];
    __half2* orow = (__half2*)(out + (size_t)row * DD);
    orow[threadIdx.x * 2]     = __floats2half2_rn(v.x * inv * wv.x, v.y * inv * wv.y);
    orow[threadIdx.x * 2 + 1] = __floats2half2_rn(v.z * inv * wv.z, v.w * inv * wv.w);
}

// ---------------- batched weight convert+transpose ----------------
__global__ void convT5(const float* __restrict__ w0, const float* __restrict__ w1,
                       const float* __restrict__ w2, const float* __restrict__ w3,
                       const float* __restrict__ w4, __half* __restrict__ Wt) {
    __shared__ float tile[32][33];
    const float* W = (blockIdx.z == 0) ? w0 : (blockIdx.z == 1) ? w1 :
                     (blockIdx.z == 2) ? w2 : (blockIdx.z == 3) ? w3 : w4;
    __half* dst = Wt + (size_t)blockIdx.z * 1024 * DD;
    int n0 = blockIdx.x * 32, k0 = blockIdx.y * 32;
    #pragma unroll
    for (int j = threadIdx.y; j < 32; j += 8)
        tile[j][threadIdx.x] = W[(size_t)(k0 + j) * DD + n0 + threadIdx.x];
    __syncthreads();
    #pragma unroll
    for (int j = threadIdx.y; j < 32; j += 8)
        dst[(size_t)(n0 + j) * DD + k0 + threadIdx.x] = __float2half_rn(tile[threadIdx.x][j]);
}
__global__ void convTI(const float* __restrict__ wg, const float* __restrict__ wu,
                       __half* __restrict__ Wt) {
    __shared__ float tile[32][33];
    const float* W = blockIdx.z ? wu : wg;
    int ro = blockIdx.z;
    int n0 = blockIdx.x * 32, k0 = blockIdx.y * 32;
    #pragma unroll
    for (int j = threadIdx.y; j < 32; j += 8)
        tile[j][threadIdx.x] = W[(size_t)(k0 + j) * II + n0 + threadIdx.x];
    __syncthreads();
    #pragma unroll
    for (int j = threadIdx.y; j < 32; j += 8)
        Wt[((size_t)(n0 + j) * 2 + ro) * DD + k0 + threadIdx.x] = __float2half_rn(tile[threadIdx.x][j]);
}
__global__ void convTW(const float* __restrict__ W, __half* __restrict__ Wt) {
    __shared__ float tile[32][33];
    int n0 = blockIdx.x * 32, k0 = blockIdx.y * 32;
    #pragma unroll
    for (int j = threadIdx.y; j < 32; j += 8)
        tile[j][threadIdx.x] = W[(size_t)(k0 + j) * DD + n0 + threadIdx.x];
    __syncthreads();
    #pragma unroll
    for (int j = threadIdx.y; j < 32; j += 8)
        Wt[(size_t)(n0 + j) * II + k0 + threadIdx.x] = __float2half_rn(tile[threadIdx.x][j]);
}

// ================= fp16 tensor-core GEMM =================
#define BKH 64
#define XW 36
#define AW (128*XW)
#define BW (128*XW)
#define STG (AW+BW)
#define SMEM_GEMM (3*STG*4)

template <int MODE>
__global__ __launch_bounds__(256, 2)
void hgemm_t(const __half* __restrict__ A, const __half* __restrict__ Bt,
             const float* __restrict__ R, void* __restrict__ Cv,
             int M, int N, int K) {
    extern __shared__ uint32_t smw[];

    const int tid = threadIdx.x;
    const int lane = tid & 31;
    const int w = tid >> 5;
    const int g = lane >> 2, q = lane & 3;
    const int wm = (w & 1) * 64;
    const int wn = (w >> 1) * 32;
    const int bm = blockIdx.y * 128, bn = blockIdx.x * 128;

    uint32_t sBase = (uint32_t)__cvta_generic_to_shared(smw);

    const uint32_t aLane = (uint32_t)((wm + (lane & 15)) * XW + ((lane >> 4) << 2));
    const uint32_t bLane = (uint32_t)((wn + (lane & 7) + ((lane >> 4) << 3)) * XW + (((lane >> 3) & 1) << 2));

    float acc[4][4][4];
    #pragma unroll
    for (int i = 0; i < 4; ++i)
        #pragma unroll
        for (int j = 0; j < 4; ++j)
            #pragma unroll
            for (int r = 0; r < 4; ++r) acc[i][j][r] = 0.f;

    const int ntile = K / BKH;

    auto loadTile = [&](int t, int s) {
        #pragma unroll
        for (int i = 0; i < 4; ++i) {
            int idx = i * 256 + tid;
            int row = idx >> 3, kc = (idx & 7) * 8;
            cpasync16(sBase + (uint32_t)((s * STG + row * XW) * 4 + kc * 2),
                      A + (size_t)(bm + row) * K + t * BKH + kc);
        }
        #pragma unroll
        for (int i = 0; i < 4; ++i) {
            int idx = i * 256 + tid;
            int n = idx >> 3, kc = (idx & 7) * 8;
            cpasync16(sBase + (uint32_t)((s * STG + AW + n * XW) * 4 + kc * 2),
                      Bt + (size_t)(bn + n) * K + t * BKH + kc);
        }
        asm volatile("cp.async.commit_group;");
    };

    loadTile(0, 0);
    if (ntile > 1) loadTile(1, 1);

    for (int t = 0; t < ntile; ++t) {
        int s = t % 3;
        if (t + 2 < ntile) asm volatile("cp.async.wait_group 1;");
        else               asm volatile("cp.async.wait_group 0;");
        __syncthreads();
        if (t + 2 < ntile) loadTile(t + 2, (t + 2) % 3);

        const uint32_t aOff = sBase + (uint32_t)(s * STG) * 4;
        const uint32_t bOff = sBase + (uint32_t)(s * STG + AW) * 4;
        #pragma unroll
        for (int ks = 0; ks < 4; ++ks) {
            uint32_t a[4][4], b[4][2];
            #pragma unroll
            for (int mt = 0; mt < 4; ++mt)
                ldsm_x4(a[mt], aOff + (aLane + (uint32_t)(mt * 16 * XW + ks * 8)) * 4);
            #pragma unroll
            for (int np = 0; np < 2; ++np) {
                uint32_t bb[4];
                ldsm_x4(bb, bOff + (bLane + (uint32_t)(np * 16 * XW + ks * 8)) * 4);
                b[np * 2][0]     = bb[0];
                b[np * 2][1]     = bb[1];
                b[np * 2 + 1][0] = bb[2];
                b[np * 2 + 1][1] = bb[3];
            }
            #pragma unroll
            for (int mt = 0; mt < 4; ++mt)
                #pragma unroll
                for (int nt = 0; nt < 4; ++nt)
                    mma_fp16(acc[mt][nt], a[mt], b[nt]);
        }
    }

    #pragma unroll
    for (int mt = 0; mt < 4; ++mt) {
        #pragma unroll
        for (int half = 0; half < 2; ++half) {
            int row = bm + wm + mt * 16 + g + half * 8;
            #pragma unroll
            for (int nt = 0; nt < 4; ++nt) {
                float vx = acc[mt][nt][half * 2 + 0];
                float vy = acc[mt][nt][half * 2 + 1];
                if (MODE == 0) {
                    int col = bn + wn + nt * 8 + q * 2;
                    size_t off = (size_t)row * N + col;
                    float* C = (float*)Cv;
                    float2 v2;
                    v2.x = vx; v2.y = vy;
                    if (R) {
                        const float2 rr = *(const float2*)(R + off);
                        v2.x += rr.x; v2.y += rr.y;
                    }
                    *(float2*)(C + off) = v2;
                } else if (MODE == 1) {
                    int col = bn + wn + nt * 8 + q * 2;
                    __half2* C = (__half2*)Cv;
                    C[((size_t)row * N + col) >> 1] = __floats2half2_rn(vx, vy);
                } else {
                    int oc = (bn + wn) / 2 + nt * 4 + q;
                    float r = (vx / (1.f + expf(-vx))) * vy;
                    __half* C = (__half*)Cv;
                    C[(size_t)row * (N >> 1) + oc] = __float2half_rn(r);
                }
            }
        }
    }
}

// ---------------- conv(K=4)+silu+RoPE fused (q,k path) ----------------
__global__ void conv_silu_rope_kernel(const __half* __restrict__ x, const float* __restrict__ w,
                                      __half* __restrict__ y) {
    int idx = blockIdx.x * 256 + threadIdx.x;
    int j4 = idx & 15;
    int h  = (idx >> 4) & 7;
    int t4 = (idx >> 7) & 2047;
    int b  = idx >> 18;
    const float4* w4 = (const float4*)w;
    int d1 = h * 128 + j4 * 4;
    float4 wa[4], wb[4];
    #pragma unroll
    for (int r = 0; r < 4; ++r) { wa[r] = w4[d1 + r]; wb[r] = w4[d1 + 64 + r]; }
    int t0 = t4 * 4;
    float4 xv1[7], xv2[7];
    #pragma unroll
    for (int j = 0; j < 7; ++j) {
        int tt = t0 - 3 + j;
        if (tt >= 0) {
            const __half* p = x + ((size_t)(b * TT + tt)) * 4096 + d1;
            xv1[j] = ldh4(p);
            xv2[j] = ldh4(p + 64);
        } else {
            xv1[j] = make_float4(0.f, 0.f, 0.f, 0.f);
            xv2[j] = make_float4(0.f, 0.f, 0.f, 0.f);
        }
    }
    const float4* cos4 = (const float4*)g_cos;
    const float4* sin4 = (const float4*)g_sin;
    __half2* y2 = (__half2*)y;
    #pragma unroll
    for (int i = 0; i < 4; ++i) {
        float4 a1, a2;
        a1.x = xv1[i].x * wa[0].x + xv1[i+1].x * wa[0].y + xv1[i+2].x * wa[0].z + xv1[i+3].x * wa[0].w;
        a1.y = xv1[i].y * wa[1].x + xv1[i+1].y * wa[1].y + xv1[i+2].y * wa[1].z + xv1[i+3].y * wa[1].w;
        a1.z = xv1[i].z * wa[2].x + xv1[i+1].z * wa[2].y + xv1[i+2].z * wa[2].z + xv1[i+3].z * wa[2].w;
        a1.w = xv1[i].w * wa[3].x + xv1[i+1].w * wa[3].y + xv1[i+2].w * wa[3].z + xv1[i+3].w * wa[3].w;
        a2.x = xv2[i].x * wb[0].x + xv2[i+1].x * wb[0].y + xv2[i+2].x * wb[0].z + xv2[i+3].x * wb[0].w;
        a2.y = xv2[i].y * wb[1].x + xv2[i+1].y * wb[1].y + xv2[i+2].y * wb[1].z + xv2[i+3].y * wb[1].w;
        a2.z = xv2[i].z * wb[2].x + xv2[i+1].z * wb[2].y + xv2[i+2].z * wb[2].z + xv2[i+3].z * wb[2].w;
        a2.w = xv2[i].w * wb[3].x + xv2[i+1].w * wb[3].y + xv2[i+2].w * wb[3].z + xv2[i+3].w * wb[3].w;
        a1.x /= (1.f + expf(-a1.x)); a1.y /= (1.f + expf(-a1.y));
        a1.z /= (1.f + expf(-a1.z)); a1.w /= (1.f + expf(-a1.w));
        a2.x /= (1.f + expf(-a2.x)); a2.y /= (1.f + expf(-a2.y));
        a2.z /= (1.f + expf(-a2.z)); a2.w /= (1.f + expf(-a2.w));
        int t = t0 + i;
        float4 c = cos4[t * 16 + j4];
        float4 s = sin4[t * 16 + j4];
        float4 o1, o2;
        o1.x = a1.x * c.x - a2.x * s.x;  o2.x = a1.x * s.x + a2.x * c.x;
        o1.y = a1.y * c.y - a2.y * s.y;  o2.y = a1.y * s.y + a2.y * c.y;
        o1.z = a1.z * c.z - a2.z * s.z;  o2.z = a1.z * s.z + a2.z * c.z;
        o1.w = a1.w * c.w - a2.w * s.w;  o2.w = a1.w * s.w + a2.w * c.w;
        size_t base1 = (((size_t)(b * TT + t)) * DD + d1) >> 1;
        y2[base1]      = __floats2half2_rn(o1.x, o1.y);
        y2[base1 + 1]  = __floats2half2_rn(o1.z, o1.w);
        y2[base1 + 32] = __floats2half2_rn(o2.x, o2.y);
        y2[base1 + 33] = __floats2half2_rn(o2.z, o2.w);
    }
}

// ---------------- conv(K=4)+silu (v path) ----------------
__global__ void conv_silu_h_kernel(const __half* __restrict__ x, const float* __restrict__ w,
                                   __half* __restrict__ y) {
    int idx = blockIdx.x * 256 + threadIdx.x;
    int d4 = idx & 255;
    int rest = idx >> 8;
    int t4 = rest & (TT / 4 - 1);
    int b = rest >> 11;
    const float4* w4 = (const float4*)w;
    float4 wr0 = w4[d4 * 4 + 0], wr1 = w4[d4 * 4 + 1];
    float4 wr2 = w4[d4 * 4 + 2], wr3 = w4[d4 * 4 + 3];
    int t0 = t4 * 4;
    float4 xv[7];
    #pragma unroll
    for (int j = 0; j < 7; ++j) {
        int tt = t0 - 3 + j;
        xv[j] = (tt >= 0) ? ldh4(x + ((size_t)(b * TT + tt)) * 4096 + d4 * 4)
                          : make_float4(0.f, 0.f, 0.f, 0.f);
    }
    __half2* y2 = (__half2*)y;
    #pragma unroll
    for (int i = 0; i < 4; ++i) {
        float4 a;
        a.x = xv[i].x * wr0.x + xv[i+1].x * wr0.y + xv[i+2].x * wr0.z + xv[i+3].x * wr0.w;
        a.y = xv[i].y * wr1.x + xv[i+1].y * wr1.y + xv[i+2].y * wr1.z + xv[i+3].y * wr1.w;
        a.z = xv[i].z * wr2.x + xv[i+1].z * wr2.y + xv[i+2].z * wr2.z + xv[i+3].z * wr2.w;
        a.w = xv[i].w * wr3.x + xv[i+1].w * wr3.y + xv[i+2].w * wr3.z + xv[i+3].w * wr3.w;
        a.x /= (1.f + expf(-a.x)); a.y /= (1.f + expf(-a.y));
        a.z /= (1.f + expf(-a.z)); a.w /= (1.f + expf(-a.w));
        size_t bh = ((size_t)(b * TT + t0 + i)) * 512 + d4 * 2;
        y2[bh]     = __floats2half2_rn(a.x, a.y);
        y2[bh + 1] = __floats2half2_rn(a.z, a.w);
    }
}

// ---------------- RoPE tables (cheap FP64: only range reduction) ----------------
__global__ void rope_invf_kernel() {
    int j = threadIdx.x;
    if (j < 64) g_invf[j] = (float)(1.0 / pow(10000.0, (double)j / 64.0));
}
__global__ void rope_table_kernel() {
    int idx = blockIdx.x * 256 + threadIdx.x;
    if (idx >= TT * 64) return;
    int t = idx >> 6, j = idx & 63;
    float f = (float)t * g_invf[j];                 // fp32 phase, same rounding as reference
    double d = (double)f;
    double n = floor(d * 0.15915494309189535);      // 1/(2*pi)
    float r = (float)(d - n * 6.283185307179586);   // reduced to [0, 2*pi)
    float s, c;
    __sincosf(r, &s, &c);
    g_cos[idx] = c;
    g_sin[idx] = s;
}

// ================= retention phase 1 (HMMA): S = (k*dec)^T @ v =================
#define RSTR 136
#define SMEM_P1 ((64*RSTR + 64*RSTR) * 2)
__global__ __launch_bounds__(256, 2)
void ret_phase1(const __half* __restrict__ k, const __half* __restrict__ v,
                __half* __restrict__ S) {
    extern __shared__ __half smh[];
    __half* ks = smh;
    __half* vs = smh + 64 * RSTR;
    int c = blockIdx.x, h = blockIdx.y, b = blockIdx.z;
    float gamma = 1.f - exp2f(-5.f - (float)h);
    float lg = logf(gamma);
    int tid = threadIdx.x, lane = tid & 31, w = tid >> 5;
    int g = lane >> 2, q = lane & 3;
    uint32_t sk = (uint32_t)__cvta_generic_to_shared(ks);
    uint32_t sv = (uint32_t)__cvta_generic_to_shared(vs);

    #pragma unroll
    for (int it = 0; it < 4; ++it) {
        int x = it * 256 + tid;
        int row = x >> 4, ch = x & 15;
        cpasync16(sv + (uint32_t)(row * RSTR + ch * 8) * 2,
                  v + ((size_t)(b * TT + c * 64 + row) * DD + h * 128 + ch * 8));
    }
    asm volatile("cp.async.commit_group;");
    const __half2* k2 = (const __half2*)k;
    for (int x = tid; x < 4096; x += 256) {
        int row = x >> 6, d2 = x & 63;
        float dec = expf(lg * (float)(63 - row));
        float2 kf = __half22float2(k2[((size_t)(b * TT + c * 64 + row) * DD + h * 128) / 2 + d2]);
        *(__half2*)(ks + row * RSTR + d2 * 2) = __floats2half2_rn(kf.x * dec, kf.y * dec);
    }
    asm volatile("cp.async.wait_group 0;");
    __syncthreads();

    int m0 = (w & 3) * 32;
    int e0w = (w >> 2) * 64;
    float acc[2][8][4];
    #pragma unroll
    for (int i = 0; i < 2; ++i)
        #pragma unroll
        for (int j = 0; j < 8; ++j)
            #pragma unroll
            for (int r = 0; r < 4; ++r) acc[i][j][r] = 0.f;

    int aRow = (lane & 7) + ((lane >> 4) << 3);
    int aCol = ((lane >> 3) & 1) << 3;
    int bRow = (lane & 7) + (((lane >> 3) & 1) << 3);
    int bCol = (lane >> 4) << 3;

    #pragma unroll
    for (int kt = 0; kt < 4; ++kt) {
        int j0 = kt * 16;
        uint32_t a[2][4];
        #pragma unroll
        for (int mt = 0; mt < 2; ++mt)
            ldsm_x4_t(a[mt], sk + (uint32_t)((j0 + aRow) * RSTR + m0 + mt * 16 + aCol) * 2);
        #pragma unroll
        for (int np = 0; np < 4; ++np) {
            uint32_t bb[4];
            ldsm_x4_t(bb, sv + (uint32_t)((j0 + bRow) * RSTR + e0w + np * 16 + bCol) * 2);
            #pragma unroll
            for (int mt = 0; mt < 2; ++mt) {
                mma_fp16(acc[mt][np * 2],     a[mt], bb);
                mma_fp16(acc[mt][np * 2 + 1], a[mt], bb + 2);
            }
        }
    }

    size_t sb = (((size_t)(b * HH + h)) * NC + c) * 16384;
    __half2* S2 = (__half2*)S;
    #pragma unroll
    for (int mt = 0; mt < 2; ++mt) {
        #pragma unroll
        for (int nt = 0; nt < 8; ++nt) {
            int e = e0w + nt * 8 + q * 2;
            int d1 = m0 + mt * 16 + g;
            S2[(sb + (size_t)d1 * 128 + e) >> 1]       = __floats2half2_rn(acc[mt][nt][0], acc[mt][nt][1]);
            S2[(sb + (size_t)(d1 + 8) * 128 + e) >> 1] = __floats2half2_rn(acc[mt][nt][2], acc[mt][nt][3]);
        }
    }
}

// ---------------- retention phase 2: parallel exclusive scan (half2) ----------------
__global__ void ret_scan(__half* __restrict__ S) {
    int bh = blockIdx.x >> 5;
    int pairIdx = ((blockIdx.x & 31) << 8) + threadIdx.x;
    int h = bh & 7;
    float gamma = 1.f - exp2f(-5.f - (float)h);
    float cdec = expf(logf(gamma) * 64.f);
    float2 carry = make_float2(0.f, 0.f);
    __half2* S2 = (__half2*)S;
    size_t base = (size_t)bh * NC * 8192 + pairIdx;
    for (int c = 0; c < NC; ++c) {
        size_t idx = base + (size_t)c * 8192;
        float2 loc = __half22float2(S2[idx]);
        S2[idx] = __floats2half2_rn(carry.x, carry.y);
        carry.x = carry.x * cdec + loc.x;
        carry.y = carry.y * cdec + loc.y;
    }
}

// ================= retention phase 3 (HMMA) + fused gate =================
#define ASTR3 72
#define SMEM_P3 ((3*64*RSTR + 64*ASTR3) * 2 + 512)
__global__ __launch_bounds__(256, 2)
void ret_phase3(const __half* __restrict__ q, const __half* __restrict__ k,
                const __half* __restrict__ v, const __half* __restrict__ S,
                const __half* __restrict__ gbig, const float* __restrict__ gnw,
                __half* __restrict__ oh) {
    extern __shared__ __half smh[];
    __half* qs  = smh;
    __half* ksb = smh + 64 * RSTR;
    __half* vsb = smh + 2 * 64 * RSTR;
    __half* ats = smh + 3 * 64 * RSTR;
    float*  rn  = (float*)(smh + 3 * 64 * RSTR + 64 * ASTR3);
    int c = blockIdx.x, h = blockIdx.y, b = blockIdx.z;
    float gamma = 1.f - exp2f(-5.f - (float)h);
    float lg = logf(gamma);
    const float scale = 0.08838834764831845f;
    int tid = threadIdx.x, lane = tid & 31, w = tid >> 5;
    int g = lane >> 2, qq = lane & 3;
    uint32_t sq = (uint32_t)__cvta_generic_to_shared(qs);
    uint32_t sk = (uint32_t)__cvta_generic_to_shared(ksb);
    uint32_t sv = (uint32_t)__cvta_generic_to_shared(vsb);
    uint32_t sa = (uint32_t)__cvta_generic_to_shared(ats);

    #pragma unroll
    for (int it = 0; it < 4; ++it) {
        int x = it * 256 + tid;
        int row = x >> 4, ch = x & 15;
        size_t gg = (size_t)(b * TT + c * 64 + row) * DD + h * 128 + ch * 8;
        uint32_t off = (uint32_t)(row * RSTR + ch * 8) * 2;
        cpasync16(sq + off, q + gg);
        cpasync16(sk + off, k + gg);
        cpasync16(sv + off, v + gg);
    }
    asm volatile("cp.async.commit_group;");
    asm volatile("cp.async.wait_group 0;");
    __syncthreads();

    const int mt = w & 3;
    const int m0 = mt * 16;
    const int eh = w >> 2;
    size_t sbg = (((size_t)(b * HH + h)) * NC + c) * 16384;

    int aRow = m0 + (lane & 15);
    int aCol = (lane >> 4) << 3;
    int bRowN = (lane & 7) + ((lane >> 4) << 3);
    int bColN = ((lane >> 3) & 1) << 3;
    int tRow = (lane & 7) + (((lane >> 3) & 1) << 3);
    int tCol = (lane >> 4) << 3;

    // Step A: att = q @ k^T
    {
        int n0 = eh * 32;
        float accT[4][4];
        #pragma unroll
        for (int i = 0; i < 4; ++i)
            #pragma unroll
            for (int r = 0; r < 4; ++r) accT[i][r] = 0.f;
        #pragma unroll
        for (int kt = 0; kt < 8; ++kt) {
            uint32_t a[4];
            ldsm_x4(a, sq + (uint32_t)(aRow * RSTR + aCol + kt * 16) * 2);
            #pragma unroll
            for (int np = 0; np < 2; ++np) {
                uint32_t bb[4];
                ldsm_x4(bb, sk + (uint32_t)((n0 + np * 16 + bRowN) * RSTR + bColN + kt * 16) * 2);
                mma_fp16(accT[np * 2],     a, bb);
                mma_fp16(accT[np * 2 + 1], a, bb + 2);
            }
        }
        #pragma unroll
        for (int nt = 0; nt < 4; ++nt) {
            int j0 = n0 + nt * 8 + qq * 2;
            int i1 = m0 + g, i2 = i1 + 8;
            float f0 = (i1 >= j0)     ? scale * expf(lg * (float)(i1 - j0))     : 0.f;
            float f1 = (i1 >= j0 + 1) ? scale * expf(lg * (float)(i1 - j0 - 1)) : 0.f;
            float f2 = (i2 >= j0)     ? scale * expf(lg * (float)(i2 - j0))     : 0.f;
            float f3 = (i2 >= j0 + 1) ? scale * expf(lg * (float)(i2 - j0 - 1)) : 0.f;
            *(__half2*)(ats + i1 * ASTR3 + j0) = __floats2half2_rn(accT[nt][0] * f0, accT[nt][1] * f1);
            *(__half2*)(ats + i2 * ASTR3 + j0) = __floats2half2_rn(accT[nt][2] * f2, accT[nt][3] * f3);
        }
    }
    __syncthreads();

    #pragma unroll
    for (int it = 0; it < 4; ++it) {
        int x = it * 256 + tid;
        int row = x >> 4, ch = x & 15;
        cpasync16(sk + (uint32_t)(row * RSTR + ch * 8) * 2, S + sbg + (size_t)row * 128 + ch * 8);
    }
    asm volatile("cp.async.commit_group;");

    // Step B: o1 = att @ v
    const int e0w = eh * 64;
    float accA[8][4];
    #pragma unroll
    for (int i = 0; i < 8; ++i)
        #pragma unroll
        for (int r = 0; r < 4; ++r) accA[i][r] = 0.f;
    #pragma unroll
    for (int kt = 0; kt < 4; ++kt) {
        int j0 = kt * 16;
        uint32_t a[4];
        ldsm_x4(a, sa + (uint32_t)(aRow * ASTR3 + aCol + kt * 16) * 2);
        #pragma unroll
        for (int np = 0; np < 4; ++np) {
            uint32_t bb[4];
            ldsm_x4_t(bb, sv + (uint32_t)((j0 + tRow) * RSTR + e0w + np * 16 + tCol) * 2);
            mma_fp16(accA[np * 2],     a, bb);
            mma_fp16(accA[np * 2 + 1], a, bb + 2);
        }
    }
    asm volatile("cp.async.wait_group 0;");
    __syncthreads();

    #pragma unroll
    for (int it = 0; it < 4; ++it) {
        int x = it * 256 + tid;
        int row = x >> 4, ch = x & 15;
        cpasync16(sv + (uint32_t)(row * RSTR + ch * 8) * 2, S + sbg + (size_t)(64 + row) * 128 + ch * 8);
    }
    asm volatile("cp.async.commit_group;");

    // Step C1: accB += q @ S[0:64]
    float accB[8][4];
    #pragma unroll
    for (int i = 0; i < 8; ++i)
        #pragma unroll
        for (int r = 0; r < 4; ++r) accB[i][r] = 0.f;
    #pragma unroll
    for (int kt = 0; kt < 4; ++kt) {
        int d0 = kt * 16;
        uint32_t a[4];
        ldsm_x4(a, sq + (uint32_t)(aRow * RSTR + aCol + kt * 16) * 2);
        #pragma unroll
        for (int np = 0; np < 4; ++np) {
            uint32_t bb[4];
            ldsm_x4_t(bb, sk + (uint32_t)((d0 + tRow) * RSTR + e0w + np * 16 + tCol) * 2);
            mma_fp16(accB[np * 2],     a, bb);
            mma_fp16(accB[np * 2 + 1], a, bb + 2);
        }
    }
    asm volatile("cp.async.wait_group 0;");
    __syncthreads();

    // Step C2: accB += q @ S[64:128]
    #pragma unroll
    for (int kt = 4; kt < 8; ++kt) {
        int d0 = (kt - 4) * 16;
        uint32_t a[4];
        ldsm_x4(a, sq + (uint32_t)(aRow * RSTR + aCol + kt * 16) * 2);
        #pragma unroll
        for (int np = 0; np < 4; ++np) {
            uint32_t bb[4];
            ldsm_x4_t(bb, sv + (uint32_t)((d0 + tRow) * RSTR + e0w + np * 16 + tCol) * 2);
            mma_fp16(accB[np * 2],     a, bb);
            mma_fp16(accB[np * 2 + 1], a, bb + 2);
        }
    }

    // combine + fused rmsnorm(128) * gnw * silu(g) -> fp16 oh
    int i1 = m0 + g;
    int i2 = i1 + 8;
    float cf1 = scale * expf(lg * (float)(i1 + 1));
    float cf2 = scale * expf(lg * (float)(i1 + 9));
    float ss1 = 0.f, ss2 = 0.f;
    #pragma unroll
    for (int nt = 0; nt < 8; ++nt) {
        accA[nt][0] += cf1 * accB[nt][0];
        accA[nt][1] += cf1 * accB[nt][1];
        accA[nt][2] += cf2 * accB[nt][2];
        accA[nt][3] += cf2 * accB[nt][3];
        ss1 += accA[nt][0] * accA[nt][0] + accA[nt][1] * accA[nt][1];
        ss2 += accA[nt][2] * accA[nt][2] + accA[nt][3] * accA[nt][3];
    }
    ss1 += __shfl_xor_sync(0xffffffffu, ss1, 1);
    ss1 += __shfl_xor_sync(0xffffffffu, ss1, 2);
    ss2 += __shfl_xor_sync(0xffffffffu, ss2, 1);
    ss2 += __shfl_xor_sync(0xffffffffu, ss2, 2);
    if (qq == 0) { rn[eh * 64 + i1] = ss1; rn[eh * 64 + i2] = ss2; }
    __syncthreads();
    float inv1 = rsqrtf((rn[i1] + rn[64 + i1]) * 0.0078125f + GATE_EPS);
    float inv2 = rsqrtf((rn[i2] + rn[64 + i2]) * 0.0078125f + GATE_EPS);

    size_t r1 = (size_t)(b * TT + c * 64 + i1);
    size_t r2 = r1 + 8;
    __half2* dst = (__half2*)oh;
    #pragma unroll
    for (int nt = 0; nt < 8; ++nt) {
        int e = e0w + nt * 8 + qq * 2;
        float2 gw = *(const float2*)(gnw + e);
        float2 g1 = __half22float2(*(const __half2*)(gbig + r1 * 4096 + 3072 + h * 128 + e));
        float2 g2 = __half22float2(*(const __half2*)(gbig + r2 * 4096 + 3072 + h * 128 + e));
        float o1x = accA[nt][0] * inv1 * gw.x * (g1.x / (1.f + expf(-g1.x)));
        float o1y = accA[nt][1] * inv1 * gw.y * (g1.y / (1.f + expf(-g1.y)));
        float o2x = accA[nt][2] * inv2 * gw.x * (g2.x / (1.f + expf(-g2.x)));
        float o2y = accA[nt][3] * inv2 * gw.y * (g2.y / (1.f + expf(-g2.y)));
        dst[(r1 * 1024 + h * 128 + e) >> 1] = __floats2half2_rn(o1x, o1y);
        dst[(r2 * 1024 + h * 128 + e) >> 1] = __floats2half2_rn(o2x, o2y);
    }
}

// ---------------- launch ----------------
extern "C" void kernel_launch(void* const* d_in, const int* in_sizes, int n_in,
                              void* d_out, int out_size) {
    const float* hs    = (const float*)d_in[0];
    const float* ln1   = (const float*)d_in[1];
    const float* ln2   = (const float*)d_in[2];
    const float* wq    = (const float*)d_in[3];
    const float* wk    = (const float*)d_in[4];
    const float* wv    = (const float*)d_in[5];
    const float* wg    = (const float*)d_in[6];
    const float* wo    = (const float*)d_in[7];
    const float* cq    = (const float*)d_in[8];
    const float* ck    = (const float*)d_in[9];
    const float* cv    = (const float*)d_in[10];
    const float* gn    = (const float*)d_in[11];
    const float* wgate = (const float*)d_in[12];
    const float* wup   = (const float*)d_in[13];
    const float* wdown = (const float*)d_in[14];
    float* out = (float*)d_out;

    cudaFuncSetAttribute(hgemm_t<0>, cudaFuncAttributeMaxDynamicSharedMemorySize, SMEM_GEMM);
    cudaFuncSetAttribute(hgemm_t<1>, cudaFuncAttributeMaxDynamicSharedMemorySize, SMEM_GEMM);
    cudaFuncSetAttribute(hgemm_t<2>, cudaFuncAttributeMaxDynamicSharedMemorySize, SMEM_GEMM);
    cudaFuncSetAttribute(ret_phase1, cudaFuncAttributeMaxDynamicSharedMemorySize, SMEM_P1);
    cudaFuncSetAttribute(ret_phase3, cudaFuncAttributeMaxDynamicSharedMemorySize, SMEM_P3);

    float *hbuf;
    __half *big, *qh, *kh, *vh, *Sh, *xh, *oh, *m1h, *bt;
    cudaGetSymbolAddress((void**)&big, g_big);
    cudaGetSymbolAddress((void**)&qh,  g_qh);
    cudaGetSymbolAddress((void**)&kh,  g_kh);
    cudaGetSymbolAddress((void**)&vh,  g_vh);
    cudaGetSymbolAddress((void**)&hbuf, g_h);
    cudaGetSymbolAddress((void**)&Sh,  g_Sh);
    cudaGetSymbolAddress((void**)&xh,  g_xh);
    cudaGetSymbolAddress((void**)&oh,  g_oh);
    cudaGetSymbolAddress((void**)&m1h, g_m1h);
    cudaGetSymbolAddress((void**)&bt,  g_bt);

    __half* bt_wo   = bt + (size_t)4096 * DD;
    __half* bt_mlp  = bt + (size_t)5120 * DD;
    __half* bt_down = bt + (size_t)10752 * DD;

    dim3 tb(32, 8);
    convT5<<<dim3(32, 32, 5), tb>>>(wq, wk, wv, wg, wo, bt);
    convTI<<<dim3(88, 32, 2), tb>>>(wgate, wup, bt_mlp);
    convTW<<<dim3(32, 88, 1), tb>>>(wdown, bt_down);

    rope_invf_kernel<<<1, 64>>>();
    rope_table_kernel<<<(TT * 64 + 255) / 256, 256>>>();
    rmsnorm_kernel<<<BT, 256>>>(hs, ln1, xh, RMS_EPS);

    dim3 gQKVG(4096 / 128, BT / 128);
    hgemm_t<1><<<gQKVG, 256, SMEM_GEMM>>>(xh, bt, nullptr, big, BT, 4096, DD);

    const int crblocks = (BB * (TT / 4) * HH * 16) / 256;
    const int cvblocks = BB * TT / 4;
    conv_silu_rope_kernel<<<crblocks, 256>>>(big,        cq, qh);
    conv_silu_rope_kernel<<<crblocks, 256>>>(big + 1024, ck, kh);
    conv_silu_h_kernel<<<cvblocks, 256>>>(big + 2048, cv, vh);

    dim3 gc(NC, HH, BB);
    ret_phase1<<<gc, 256, SMEM_P1>>>(kh, vh, Sh);
    ret_scan<<<BB * HH * 32, 256>>>(Sh);
    ret_phase3<<<gc, 256, SMEM_P3>>>(qh, kh, vh, Sh, big, gn, oh);

    dim3 gD(DD / 128, BT / 128);
    hgemm_t<0><<<gD, 256, SMEM_GEMM>>>(oh, bt_wo, hs, hbuf, BT, DD, DD);

    rmsnorm_kernel<<<BT, 256>>>(hbuf, ln2, xh, RMS_EPS);
    dim3 gMLP(5632 / 128, BT / 128);
    hgemm_t<2><<<gMLP, 256, SMEM_GEMM>>>(xh, bt_mlp, nullptr, m1h, BT, 5632, DD);
    hgemm_t<0><<<gD, 256, SMEM_GEMM>>>(m1h, bt_down, hbuf, out, BT, DD, II);
}